// round 4
// baseline (speedup 1.0000x reference)
#include <cuda_runtime.h>
#include <cuda_fp16.h>
#include <math.h>
#include <stdint.h>

// Shapes (fixed by the problem)
#define BATCH 8
#define SEQ   1024
#define DMODEL 1024
#define NHEAD 16
#define HD    64
#define FFDIM 4096
#define MROWS (BATCH*SEQ)   // 8192

// ---------------- scratch (device globals; no allocation allowed) ----------
__device__ float g_xn [MROWS*DMODEL];
__device__ float g_q  [MROWS*DMODEL];
__device__ float g_k  [MROWS*DMODEL];
__device__ float g_v  [MROWS*DMODEL];
__device__ float g_ctx[MROWS*DMODEL];
__device__ float g_y1 [MROWS*DMODEL];
__device__ float g_ff [MROWS*FFDIM];

// ---------------- common helpers ----------------
__device__ __forceinline__ unsigned f2tf(float x) {
    unsigned u;
    asm("cvt.rna.tf32.f32 %0, %1;" : "=r"(u) : "f"(x));
    return u;
}
__device__ __forceinline__ float f2tf_f(float x) { return __uint_as_float(f2tf(x)); }

__device__ __forceinline__ void mma8(float acc[4], const unsigned a[4],
                                     unsigned b0, unsigned b1) {
    asm volatile(
        "mma.sync.aligned.m16n8k8.row.col.f32.tf32.tf32.f32 "
        "{%0,%1,%2,%3}, {%4,%5,%6,%7}, {%8,%9}, {%0,%1,%2,%3};\n"
        : "+f"(acc[0]), "+f"(acc[1]), "+f"(acc[2]), "+f"(acc[3])
        : "r"(a[0]), "r"(a[1]), "r"(a[2]), "r"(a[3]), "r"(b0), "r"(b1));
}

__device__ __forceinline__ void mma16(float acc[4], const unsigned a[4],
                                      unsigned b0, unsigned b1) {
    asm volatile(
        "mma.sync.aligned.m16n8k16.row.col.f32.f16.f16.f32 "
        "{%0,%1,%2,%3}, {%4,%5,%6,%7}, {%8,%9}, {%0,%1,%2,%3};\n"
        : "+f"(acc[0]), "+f"(acc[1]), "+f"(acc[2]), "+f"(acc[3])
        : "r"(a[0]), "r"(a[1]), "r"(a[2]), "r"(a[3]), "r"(b0), "r"(b1));
}

__device__ __forceinline__ uint32_t smem_u32(const void* p) {
    uint32_t a;
    asm("{ .reg .u64 t; cvta.to.shared.u64 t, %1; cvt.u32.u64 %0, t; }"
        : "=r"(a) : "l"(p));
    return a;
}

__device__ __forceinline__ float block_sum(float v) {
    __shared__ float sh[32];
    int tid = threadIdx.x;
    #pragma unroll
    for (int o = 16; o; o >>= 1) v += __shfl_xor_sync(0xffffffffu, v, o);
    __syncthreads();
    if ((tid & 31) == 0) sh[tid >> 5] = v;
    __syncthreads();
    if (tid < 32) {
        float t = (tid < (int)(blockDim.x >> 5)) ? sh[tid] : 0.f;
        #pragma unroll
        for (int o = 4; o; o >>= 1) t += __shfl_xor_sync(0xffffffffu, t, o);
        if (tid == 0) sh[0] = t;
    }
    __syncthreads();
    return sh[0];
}

__device__ __forceinline__ unsigned pack2(float a, float b) {
    __half2 h = __floats2half2_rn(a, b);
    return *(unsigned*)&h;
}

// ---------------- LayerNorm kernels (D = 1024, 256 threads) -----------------
__global__ void ln_double_kernel(const float* __restrict__ X,
                                 const float* __restrict__ g1, const float* __restrict__ b1,
                                 const float* __restrict__ g2, const float* __restrict__ b2,
                                 float* __restrict__ Y) {
    int row = blockIdx.x, tid = threadIdx.x;
    float4 v = ((const float4*)X)[(size_t)row * 256 + tid];
    float mu = block_sum(v.x + v.y + v.z + v.w) * (1.0f / 1024.0f);
    float d0 = v.x - mu, d1 = v.y - mu, d2 = v.z - mu, d3 = v.w - mu;
    float var = block_sum(d0*d0 + d1*d1 + d2*d2 + d3*d3) * (1.0f / 1024.0f);
    float inv = rsqrtf(var + 1e-6f);
    float4 G = ((const float4*)g1)[tid], Bv = ((const float4*)b1)[tid];
    float y0 = d0*inv*G.x + Bv.x, y1 = d1*inv*G.y + Bv.y;
    float y2 = d2*inv*G.z + Bv.z, y3 = d3*inv*G.w + Bv.w;
    float mu2 = block_sum(y0 + y1 + y2 + y3) * (1.0f / 1024.0f);
    float e0 = y0 - mu2, e1 = y1 - mu2, e2 = y2 - mu2, e3 = y3 - mu2;
    float var2 = block_sum(e0*e0 + e1*e1 + e2*e2 + e3*e3) * (1.0f / 1024.0f);
    float inv2 = rsqrtf(var2 + 1e-6f);
    float4 G2 = ((const float4*)g2)[tid], B2 = ((const float4*)b2)[tid];
    float4 o;
    o.x = e0*inv2*G2.x + B2.x; o.y = e1*inv2*G2.y + B2.y;
    o.z = e2*inv2*G2.z + B2.z; o.w = e3*inv2*G2.w + B2.w;
    ((float4*)Y)[(size_t)row * 256 + tid] = o;
}

__global__ void ln_single_kernel(const float* __restrict__ X,
                                 const float* __restrict__ g, const float* __restrict__ b,
                                 float* __restrict__ Y) {
    int row = blockIdx.x, tid = threadIdx.x;
    float4 v = ((const float4*)X)[(size_t)row * 256 + tid];
    float mu = block_sum(v.x + v.y + v.z + v.w) * (1.0f / 1024.0f);
    float d0 = v.x - mu, d1 = v.y - mu, d2 = v.z - mu, d3 = v.w - mu;
    float var = block_sum(d0*d0 + d1*d1 + d2*d2 + d3*d3) * (1.0f / 1024.0f);
    float inv = rsqrtf(var + 1e-6f);
    float4 G = ((const float4*)g)[tid], Bv = ((const float4*)b)[tid];
    float4 o;
    o.x = d0*inv*G.x + Bv.x; o.y = d1*inv*G.y + Bv.y;
    o.z = d2*inv*G.z + Bv.z; o.w = d3*inv*G.w + Bv.w;
    ((float4*)Y)[(size_t)row * 256 + tid] = o;
}

// ---------------- FP16 ldmatrix GEMM ----------------------------------------
// C[M,N] = A[M,K] @ W[K,N] + bias (+gelu) (+res). fp32 in/out, fp16 mma, fp32 acc.
// BM=64, BN=128, BK=32. 256 threads = 8 warps (2 m x 4 n), warp tile 32x32.
// smem: A[2][64][32] half (4KB/stage), B[2][128][32] half (8KB/stage) = 24KB.
// Row = 64B (32 halfs); 16B-chunk swizzle: chunk ^= (row>>1)&3  -> conflict-free
// for both the STS.128 stores and ldmatrix reads.
#define AS_OFF(s)  ((s) * 4096)
#define BS_OFF(s)  (8192 + (s) * 8192)

__global__ __launch_bounds__(256, 2) void gemm_f16_kernel(
    const float* __restrict__ A, const float* __restrict__ W,
    const float* __restrict__ bias, const float* __restrict__ res,
    float* __restrict__ C, int M, int N, int K, int act)
{
    __shared__ __align__(1024) char gsm[24576];
    const uint32_t sb = smem_u32(gsm);
    const int tid = threadIdx.x, lane = tid & 31, warp = tid >> 5;
    const int m0 = blockIdx.y * 64, n0 = blockIdx.x * 128;
    const int wm = (warp >> 2) * 32, wn = (warp & 3) * 32;

    // A staging: row = tid&63, kq = tid>>6 -> 8 consecutive k floats
    const int arow = tid & 63, akq = tid >> 6;
    const int achunk = akq ^ ((arow >> 1) & 3);
    // B staging: n = tid&127, kh = tid>>7 -> 16 k floats (stride N)
    const int bn = tid & 127, bkh = tid >> 7;
    const int bsw = (bn >> 1) & 3;

    const float* Ag = A + (size_t)(m0 + arow) * K + akq * 8;
    const float* Bg = W + (size_t)(bkh * 16) * N + n0 + bn;

    float a_pf[8];
    float b_pf[16];

    // ldmatrix source addresses (row part precomputed; chunk varies with ks)
    const int mt = lane >> 3, r8 = lane & 7;
    uint32_t a_rowaddr[2];    // per mi
    int      a_sw[2];
    #pragma unroll
    for (int mi = 0; mi < 2; mi++) {
        int r = wm + mi * 16 + (mt & 1) * 8 + r8;
        a_rowaddr[mi] = r * 64;
        a_sw[mi] = (r >> 1) & 3;
    }
    const int a_hi = mt >> 1;
    uint32_t b_rowaddr[4];
    int      b_sw[4];
    #pragma unroll
    for (int ni = 0; ni < 4; ni++) {
        int r = wn + ni * 8 + r8;
        b_rowaddr[ni] = r * 64;
        b_sw[ni] = (r >> 1) & 3;
    }
    const int b_hi = (lane >> 3) & 1;

    float acc[2][4][4] = {};

    auto loadG = [&](int kc) {
        const float* ap = Ag + kc * 32;
        *(float4*)&a_pf[0] = *(const float4*)(ap);
        *(float4*)&a_pf[4] = *(const float4*)(ap + 4);
        const float* bp = Bg + (size_t)(kc * 32) * N;
        #pragma unroll
        for (int j = 0; j < 16; j++) b_pf[j] = bp[(size_t)j * N];
    };
    auto storeS = [&](int s) {
        uint4 av;
        av.x = pack2(a_pf[0], a_pf[1]); av.y = pack2(a_pf[2], a_pf[3]);
        av.z = pack2(a_pf[4], a_pf[5]); av.w = pack2(a_pf[6], a_pf[7]);
        *(uint4*)(gsm + AS_OFF(s) + arow * 64 + achunk * 16) = av;
        uint4 bv0, bv1;
        bv0.x = pack2(b_pf[0], b_pf[1]);  bv0.y = pack2(b_pf[2], b_pf[3]);
        bv0.z = pack2(b_pf[4], b_pf[5]);  bv0.w = pack2(b_pf[6], b_pf[7]);
        bv1.x = pack2(b_pf[8], b_pf[9]);  bv1.y = pack2(b_pf[10], b_pf[11]);
        bv1.z = pack2(b_pf[12], b_pf[13]); bv1.w = pack2(b_pf[14], b_pf[15]);
        *(uint4*)(gsm + BS_OFF(s) + bn * 64 + ((bkh*2)     ^ bsw) * 16) = bv0;
        *(uint4*)(gsm + BS_OFF(s) + bn * 64 + ((bkh*2 + 1) ^ bsw) * 16) = bv1;
    };

    const int NC = K >> 5;

    loadG(0);
    storeS(0);
    __syncthreads();

    for (int kc = 0; kc < NC; kc++) {
        const int cur = kc & 1, nxt = cur ^ 1;
        const bool more = (kc + 1) < NC;
        if (more) loadG(kc + 1);

        const uint32_t asb = sb + AS_OFF(cur);
        const uint32_t bsb = sb + BS_OFF(cur);
        #pragma unroll
        for (int ks = 0; ks < 2; ks++) {
            unsigned af[2][4], bf[4][2];
            #pragma unroll
            for (int mi = 0; mi < 2; mi++) {
                uint32_t addr = asb + a_rowaddr[mi]
                              + (uint32_t)(((ks*2 + a_hi) ^ a_sw[mi]) * 16);
                asm volatile(
                    "ldmatrix.sync.aligned.m8n8.x4.shared.b16 {%0,%1,%2,%3}, [%4];"
                    : "=r"(af[mi][0]), "=r"(af[mi][1]), "=r"(af[mi][2]), "=r"(af[mi][3])
                    : "r"(addr));
            }
            #pragma unroll
            for (int ni = 0; ni < 4; ni++) {
                uint32_t addr = bsb + b_rowaddr[ni]
                              + (uint32_t)(((ks*2 + b_hi) ^ b_sw[ni]) * 16);
                asm volatile(
                    "ldmatrix.sync.aligned.m8n8.x2.shared.b16 {%0,%1}, [%2];"
                    : "=r"(bf[ni][0]), "=r"(bf[ni][1])
                    : "r"(addr));
            }
            #pragma unroll
            for (int mi = 0; mi < 2; mi++)
                #pragma unroll
                for (int ni = 0; ni < 4; ni++)
                    mma16(acc[mi][ni], af[mi], bf[ni][0], bf[ni][1]);
        }

        if (more) storeS(nxt);
        __syncthreads();
    }

    // epilogue
    const int g = lane >> 2, c4 = lane & 3;
    #pragma unroll
    for (int mi = 0; mi < 2; mi++) {
        #pragma unroll
        for (int ni = 0; ni < 4; ni++) {
            int gn = n0 + wn + ni * 8 + c4 * 2;
            float bv0 = bias[gn], bv1 = bias[gn + 1];
            #pragma unroll
            for (int half = 0; half < 2; half++) {
                int gr = m0 + wm + mi * 16 + g + half * 8;
                float v0 = acc[mi][ni][half * 2 + 0] + bv0;
                float v1 = acc[mi][ni][half * 2 + 1] + bv1;
                if (act) {
                    v0 = 0.5f * v0 * (1.0f + erff(v0 * 0.70710678118654752f));
                    v1 = 0.5f * v1 * (1.0f + erff(v1 * 0.70710678118654752f));
                }
                size_t o = (size_t)gr * N + gn;
                if (res) { v0 += res[o]; v1 += res[o + 1]; }
                C[o] = v0; C[o + 1] = v1;
            }
        }
    }
}

// ---------------- Flash attention (TF32 legacy MMA), HD=64 -------------------
#define APAD 68
#define ATTN_SMEM (3 * 64 * APAD * 4)

__global__ __launch_bounds__(128) void attn_kernel(
    const float* __restrict__ Q, const float* __restrict__ Kb,
    const float* __restrict__ Vb, float* __restrict__ O) {
    extern __shared__ float sm[];
    float* Ks = sm;
    float* Vs = sm + 64 * APAD;
    float* Ps = sm + 2 * 64 * APAD;

    int tid = threadIdx.x, lane = tid & 31, warp = tid >> 5;
    int g = lane >> 2, c4 = lane & 3;
    int bh = blockIdx.x, qt = blockIdx.y;
    int b = bh >> 4, h = bh & 15;

    unsigned aQ[8][4];
    {
        int qr = qt * 64 + warp * 16 + g;
        const float* q0 = Q + ((size_t)(b * SEQ + qr)) * DMODEL + h * HD;
        const float* q8 = q0 + (size_t)8 * DMODEL;
        #pragma unroll
        for (int ks = 0; ks < 8; ks++) {
            int col = ks * 8 + c4;
            aQ[ks][0] = f2tf(q0[col] * 0.125f);
            aQ[ks][1] = f2tf(q8[col] * 0.125f);
            aQ[ks][2] = f2tf(q0[col + 4] * 0.125f);
            aQ[ks][3] = f2tf(q8[col + 4] * 0.125f);
        }
    }

    float m0 = -INFINITY, m1 = -INFINITY, l0 = 0.f, l1 = 0.f;
    float acc[8][4] = {};

    for (int kt = 0; kt < SEQ / 64; kt++) {
        __syncthreads();
        #pragma unroll
        for (int i = 0; i < 8; i++) {
            int cidx = tid + i * 128;
            int kr = cidx >> 4, h4 = cidx & 15;
            size_t goff = ((size_t)(b * SEQ + kt * 64 + kr)) * DMODEL + h * HD + h4 * 4;
            float4 kv = *(const float4*)(Kb + goff);
            float4 vv = *(const float4*)(Vb + goff);
            float* kd = &Ks[kr * APAD + h4 * 4];
            kd[0] = f2tf_f(kv.x); kd[1] = f2tf_f(kv.y);
            kd[2] = f2tf_f(kv.z); kd[3] = f2tf_f(kv.w);
            float* vd = &Vs[kr * APAD + h4 * 4];
            vd[0] = f2tf_f(vv.x); vd[1] = f2tf_f(vv.y);
            vd[2] = f2tf_f(vv.z); vd[3] = f2tf_f(vv.w);
        }
        __syncthreads();

        float s[8][4] = {};
        #pragma unroll
        for (int ks = 0; ks < 8; ks++) {
            #pragma unroll
            for (int nt = 0; nt < 8; nt++) {
                unsigned b0 = __float_as_uint(Ks[(nt * 8 + g) * APAD + ks * 8 + c4]);
                unsigned b1 = __float_as_uint(Ks[(nt * 8 + g) * APAD + ks * 8 + c4 + 4]);
                mma8(s[nt], aQ[ks], b0, b1);
            }
        }

        float tm0 = -INFINITY, tm1 = -INFINITY;
        #pragma unroll
        for (int nt = 0; nt < 8; nt++) {
            tm0 = fmaxf(tm0, fmaxf(s[nt][0], s[nt][1]));
            tm1 = fmaxf(tm1, fmaxf(s[nt][2], s[nt][3]));
        }
        tm0 = fmaxf(tm0, __shfl_xor_sync(0xffffffffu, tm0, 1));
        tm0 = fmaxf(tm0, __shfl_xor_sync(0xffffffffu, tm0, 2));
        tm1 = fmaxf(tm1, __shfl_xor_sync(0xffffffffu, tm1, 1));
        tm1 = fmaxf(tm1, __shfl_xor_sync(0xffffffffu, tm1, 2));
        float mn0 = fmaxf(m0, tm0), mn1 = fmaxf(m1, tm1);
        float cf0 = __expf(m0 - mn0), cf1 = __expf(m1 - mn1);
        m0 = mn0; m1 = mn1;

        float rs0 = 0.f, rs1 = 0.f;
        int pr = warp * 16 + g;
        #pragma unroll
        for (int nt = 0; nt < 8; nt++) {
            float p0 = __expf(s[nt][0] - m0), p1 = __expf(s[nt][1] - m0);
            float p2 = __expf(s[nt][2] - m1), p3 = __expf(s[nt][3] - m1);
            rs0 += p0 + p1; rs1 += p2 + p3;
            int pc = nt * 8 + c4 * 2;
            Ps[pr * APAD + pc]       = f2tf_f(p0);
            Ps[pr * APAD + pc + 1]   = f2tf_f(p1);
            Ps[(pr + 8) * APAD + pc]     = f2tf_f(p2);
            Ps[(pr + 8) * APAD + pc + 1] = f2tf_f(p3);
        }
        rs0 += __shfl_xor_sync(0xffffffffu, rs0, 1);
        rs0 += __shfl_xor_sync(0xffffffffu, rs0, 2);
        rs1 += __shfl_xor_sync(0xffffffffu, rs1, 1);
        rs1 += __shfl_xor_sync(0xffffffffu, rs1, 2);
        l0 = l0 * cf0 + rs0; l1 = l1 * cf1 + rs1;
        #pragma unroll
        for (int nt = 0; nt < 8; nt++) {
            acc[nt][0] *= cf0; acc[nt][1] *= cf0;
            acc[nt][2] *= cf1; acc[nt][3] *= cf1;
        }
        __syncwarp();

        #pragma unroll
        for (int ks = 0; ks < 8; ks++) {
            unsigned a[4];
            a[0] = __float_as_uint(Ps[(warp * 16 + g) * APAD + ks * 8 + c4]);
            a[1] = __float_as_uint(Ps[(warp * 16 + g + 8) * APAD + ks * 8 + c4]);
            a[2] = __float_as_uint(Ps[(warp * 16 + g) * APAD + ks * 8 + c4 + 4]);
            a[3] = __float_as_uint(Ps[(warp * 16 + g + 8) * APAD + ks * 8 + c4 + 4]);
            #pragma unroll
            for (int nt = 0; nt < 8; nt++) {
                unsigned b0 = __float_as_uint(Vs[(ks * 8 + c4) * APAD + nt * 8 + g]);
                unsigned b1 = __float_as_uint(Vs[(ks * 8 + c4 + 4) * APAD + nt * 8 + g]);
                mma8(acc[nt], a, b0, b1);
            }
        }
    }

    float inv0 = 1.0f / l0, inv1 = 1.0f / l1;
    int qr = qt * 64 + warp * 16 + g;
    #pragma unroll
    for (int nt = 0; nt < 8; nt++) {
        size_t o = ((size_t)(b * SEQ + qr)) * DMODEL + h * HD + nt * 8 + c4 * 2;
        O[o]     = acc[nt][0] * inv0;
        O[o + 1] = acc[nt][1] * inv0;
        O[o + (size_t)8 * DMODEL]     = acc[nt][2] * inv1;
        O[o + (size_t)8 * DMODEL + 1] = acc[nt][3] * inv1;
    }
}

// ---------------- launch ----------------
extern "C" void kernel_launch(void* const* d_in, const int* in_sizes, int n_in,
                              void* d_out, int out_size) {
    const float* x     = (const float*)d_in[0];
    const float* ln1_g = (const float*)d_in[1];
    const float* ln1_b = (const float*)d_in[2];
    const float* ln2_g = (const float*)d_in[3];
    const float* ln2_b = (const float*)d_in[4];
    const float* wq    = (const float*)d_in[5];
    const float* bq    = (const float*)d_in[6];
    const float* wk    = (const float*)d_in[7];
    const float* bk    = (const float*)d_in[8];
    const float* wv    = (const float*)d_in[9];
    const float* bv    = (const float*)d_in[10];
    const float* wp    = (const float*)d_in[11];
    const float* bp    = (const float*)d_in[12];
    const float* ln3_g = (const float*)d_in[13];
    const float* ln3_b = (const float*)d_in[14];
    const float* w1    = (const float*)d_in[15];
    const float* b1    = (const float*)d_in[16];
    const float* w2    = (const float*)d_in[17];
    const float* b2    = (const float*)d_in[18];
    float* out = (float*)d_out;

    float *xn, *q, *k, *v, *ctx, *y1, *ff;
    cudaGetSymbolAddress((void**)&xn,  g_xn);
    cudaGetSymbolAddress((void**)&q,   g_q);
    cudaGetSymbolAddress((void**)&k,   g_k);
    cudaGetSymbolAddress((void**)&v,   g_v);
    cudaGetSymbolAddress((void**)&ctx, g_ctx);
    cudaGetSymbolAddress((void**)&y1,  g_y1);
    cudaGetSymbolAddress((void**)&ff,  g_ff);

    cudaFuncSetAttribute(attn_kernel,
                         cudaFuncAttributeMaxDynamicSharedMemorySize, ATTN_SMEM);

    // 1. double pre-norm
    ln_double_kernel<<<MROWS, 256>>>(x, ln1_g, ln1_b, ln2_g, ln2_b, xn);

    // 2-4. Q, K, V projections (fp16 ldmatrix GEMM)
    dim3 gqkv(DMODEL / 128, MROWS / 64);
    gemm_f16_kernel<<<gqkv, 256>>>(xn, wq, bq, nullptr, q, MROWS, DMODEL, DMODEL, 0);
    gemm_f16_kernel<<<gqkv, 256>>>(xn, wk, bk, nullptr, k, MROWS, DMODEL, DMODEL, 0);
    gemm_f16_kernel<<<gqkv, 256>>>(xn, wv, bv, nullptr, v, MROWS, DMODEL, DMODEL, 0);

    // 5. attention
    attn_kernel<<<dim3(BATCH * NHEAD, SEQ / 64), 128, ATTN_SMEM>>>(q, k, v, ctx);

    // 6. output projection + residual
    gemm_f16_kernel<<<gqkv, 256>>>(ctx, wp, bp, x, y1, MROWS, DMODEL, DMODEL, 0);

    // 7. ffn pre-norm
    ln_single_kernel<<<MROWS, 256>>>(y1, ln3_g, ln3_b, xn);

    // 8. FFN
    gemm_f16_kernel<<<dim3(FFDIM / 128, MROWS / 64), 256>>>(
        xn, w1, b1, nullptr, ff, MROWS, FFDIM, DMODEL, 1);
    gemm_f16_kernel<<<gqkv, 256>>>(ff, w2, b2, y1, out, MROWS, DMODEL, FFDIM, 0);
}

// round 6
// speedup vs baseline: 1.8777x; 1.8777x over previous
#include <cuda_runtime.h>
#include <cuda_fp16.h>
#include <math.h>
#include <stdint.h>

// Shapes (fixed by the problem)
#define BATCH 8
#define SEQ   1024
#define DMODEL 1024
#define NHEAD 16
#define HD    64
#define FFDIM 4096
#define MROWS (BATCH*SEQ)   // 8192

// ---------------- scratch (device globals; no allocation allowed) ----------
__device__ float g_q  [MROWS*DMODEL];
__device__ float g_k  [MROWS*DMODEL];
__device__ float g_v  [MROWS*DMODEL];
__device__ float g_y1 [MROWS*DMODEL];

__device__ __half g_xnh [MROWS*DMODEL];
__device__ __half g_ctxh[MROWS*DMODEL];
__device__ __half g_ffh [MROWS*FFDIM];

__device__ __half g_wqT[DMODEL*DMODEL];
__device__ __half g_wkT[DMODEL*DMODEL];
__device__ __half g_wvT[DMODEL*DMODEL];
__device__ __half g_wpT[DMODEL*DMODEL];
__device__ __half g_w1T[DMODEL*FFDIM];
__device__ __half g_w2T[FFDIM*DMODEL];

// ---------------- common helpers ----------------
__device__ __forceinline__ unsigned f2tf(float x) {
    unsigned u;
    asm("cvt.rna.tf32.f32 %0, %1;" : "=r"(u) : "f"(x));
    return u;
}
__device__ __forceinline__ float f2tf_f(float x) { return __uint_as_float(f2tf(x)); }

__device__ __forceinline__ void mma8(float acc[4], const unsigned a[4],
                                     unsigned b0, unsigned b1) {
    asm volatile(
        "mma.sync.aligned.m16n8k8.row.col.f32.tf32.tf32.f32 "
        "{%0,%1,%2,%3}, {%4,%5,%6,%7}, {%8,%9}, {%0,%1,%2,%3};\n"
        : "+f"(acc[0]), "+f"(acc[1]), "+f"(acc[2]), "+f"(acc[3])
        : "r"(a[0]), "r"(a[1]), "r"(a[2]), "r"(a[3]), "r"(b0), "r"(b1));
}

__device__ __forceinline__ void mma16(float acc[4], const unsigned a[4],
                                      unsigned b0, unsigned b1) {
    asm volatile(
        "mma.sync.aligned.m16n8k16.row.col.f32.f16.f16.f32 "
        "{%0,%1,%2,%3}, {%4,%5,%6,%7}, {%8,%9}, {%0,%1,%2,%3};\n"
        : "+f"(acc[0]), "+f"(acc[1]), "+f"(acc[2]), "+f"(acc[3])
        : "r"(a[0]), "r"(a[1]), "r"(a[2]), "r"(a[3]), "r"(b0), "r"(b1));
}

__device__ __forceinline__ uint32_t smem_u32(const void* p) {
    uint32_t a;
    asm("{ .reg .u64 t; cvta.to.shared.u64 t, %1; cvt.u32.u64 %0, t; }"
        : "=r"(a) : "l"(p));
    return a;
}

#define CP_ASYNC16(dst, src) \
    asm volatile("cp.async.cg.shared.global [%0], [%1], 16;" :: "r"(dst), "l"(src))
#define CP_COMMIT()   asm volatile("cp.async.commit_group;" ::: "memory")
#define CP_WAIT(n)    asm volatile("cp.async.wait_group %0;" :: "n"(n) : "memory")

__device__ __forceinline__ float block_sum(float v) {
    __shared__ float sh[32];
    int tid = threadIdx.x;
    #pragma unroll
    for (int o = 16; o; o >>= 1) v += __shfl_xor_sync(0xffffffffu, v, o);
    __syncthreads();
    if ((tid & 31) == 0) sh[tid >> 5] = v;
    __syncthreads();
    if (tid < 32) {
        float t = (tid < (int)(blockDim.x >> 5)) ? sh[tid] : 0.f;
        #pragma unroll
        for (int o = 4; o; o >>= 1) t += __shfl_xor_sync(0xffffffffu, t, o);
        if (tid == 0) sh[0] = t;
    }
    __syncthreads();
    return sh[0];
}

// ---------------- weight convert + transpose: W[K,N] f32 -> Wt[N,K] f16 -----
__global__ void cvt_transpose_kernel(const float* __restrict__ W,
                                     __half* __restrict__ Wt, int K, int N) {
    __shared__ float t[32][33];
    int bk = blockIdx.x * 32, bn = blockIdx.y * 32;
    int tx = threadIdx.x, ty = threadIdx.y;   // (32, 8)
    #pragma unroll
    for (int i = 0; i < 4; i++)
        t[ty + i * 8][tx] = W[(size_t)(bk + ty + i * 8) * N + bn + tx];
    __syncthreads();
    #pragma unroll
    for (int i = 0; i < 4; i++)
        Wt[(size_t)(bn + ty + i * 8) * K + bk + tx] = __float2half(t[tx][ty + i * 8]);
}

// ---------------- LayerNorm kernels (write fp16) -----------------------------
__global__ void ln_double_kernel(const float* __restrict__ X,
                                 const float* __restrict__ g1, const float* __restrict__ b1,
                                 const float* __restrict__ g2, const float* __restrict__ b2,
                                 __half* __restrict__ Y) {
    int row = blockIdx.x, tid = threadIdx.x;
    float4 v = ((const float4*)X)[(size_t)row * 256 + tid];
    float mu = block_sum(v.x + v.y + v.z + v.w) * (1.0f / 1024.0f);
    float d0 = v.x - mu, d1 = v.y - mu, d2 = v.z - mu, d3 = v.w - mu;
    float var = block_sum(d0*d0 + d1*d1 + d2*d2 + d3*d3) * (1.0f / 1024.0f);
    float inv = rsqrtf(var + 1e-6f);
    float4 G = ((const float4*)g1)[tid], Bv = ((const float4*)b1)[tid];
    float y0 = d0*inv*G.x + Bv.x, y1 = d1*inv*G.y + Bv.y;
    float y2 = d2*inv*G.z + Bv.z, y3 = d3*inv*G.w + Bv.w;
    float mu2 = block_sum(y0 + y1 + y2 + y3) * (1.0f / 1024.0f);
    float e0 = y0 - mu2, e1 = y1 - mu2, e2 = y2 - mu2, e3 = y3 - mu2;
    float var2 = block_sum(e0*e0 + e1*e1 + e2*e2 + e3*e3) * (1.0f / 1024.0f);
    float inv2 = rsqrtf(var2 + 1e-6f);
    float4 G2 = ((const float4*)g2)[tid], B2 = ((const float4*)b2)[tid];
    __half2 h0 = __floats2half2_rn(e0*inv2*G2.x + B2.x, e1*inv2*G2.y + B2.y);
    __half2 h1 = __floats2half2_rn(e2*inv2*G2.z + B2.z, e3*inv2*G2.w + B2.w);
    ((__half2*)Y)[(size_t)row * 512 + tid * 2]     = h0;
    ((__half2*)Y)[(size_t)row * 512 + tid * 2 + 1] = h1;
}

__global__ void ln_single_kernel(const float* __restrict__ X,
                                 const float* __restrict__ g, const float* __restrict__ b,
                                 __half* __restrict__ Y) {
    int row = blockIdx.x, tid = threadIdx.x;
    float4 v = ((const float4*)X)[(size_t)row * 256 + tid];
    float mu = block_sum(v.x + v.y + v.z + v.w) * (1.0f / 1024.0f);
    float d0 = v.x - mu, d1 = v.y - mu, d2 = v.z - mu, d3 = v.w - mu;
    float var = block_sum(d0*d0 + d1*d1 + d2*d2 + d3*d3) * (1.0f / 1024.0f);
    float inv = rsqrtf(var + 1e-6f);
    float4 G = ((const float4*)g)[tid], Bv = ((const float4*)b)[tid];
    __half2 h0 = __floats2half2_rn(d0*inv*G.x + Bv.x, d1*inv*G.y + Bv.y);
    __half2 h1 = __floats2half2_rn(d2*inv*G.z + Bv.z, d3*inv*G.w + Bv.w);
    ((__half2*)Y)[(size_t)row * 512 + tid * 2]     = h0;
    ((__half2*)Y)[(size_t)row * 512 + tid * 2 + 1] = h1;
}

// ---------------- FP16 cp.async GEMM -----------------------------------------
// C[M,N] = A[M,K] @ Wt[N,K]^T + bias (+gelu) (+res). A, Wt fp16; acc fp32;
// out fp32 (C) or fp16 (Ch). BM=128, BN=128, BK=32, 3-stage cp.async pipeline,
// 256 threads, 8 warps of 64x32 warp tiles. smem row = 64B, 16B-chunk swizzle
// chunk ^= (row>>1)&3 (conflict-free; verified round 4).
// Pipeline tail fixed (round-5 bug): wait count shrinks as commits stop.
#define STAGES 3
#define STG_BYTES 16384          // A 8KB + B 8KB

__global__ __launch_bounds__(256, 2) void gemm_f16_kernel(
    const __half* __restrict__ A, const __half* __restrict__ Wt,
    const float* __restrict__ bias, const float* __restrict__ res,
    float* __restrict__ C, __half* __restrict__ Ch,
    int M, int N, int K, int act)
{
    __shared__ __align__(128) char gsm[STAGES * STG_BYTES];
    const uint32_t sb = smem_u32(gsm);
    const int tid = threadIdx.x, lane = tid & 31, warp = tid >> 5;
    const int m0 = blockIdx.y * 128, n0 = blockIdx.x * 128;
    const int wm = (warp >> 2) * 64, wn = (warp & 3) * 32;

    // staging: 512 16B-chunks per tensor; thread t handles chunks t and t+256
    const int r0a = tid >> 2, c0a = tid & 3;
    const int r1a = (tid + 256) >> 2;
    const uint32_t dstA0 = (uint32_t)(r0a * 64 + ((c0a ^ ((r0a >> 1) & 3)) * 16));
    const uint32_t dstA1 = (uint32_t)(r1a * 64 + ((c0a ^ ((r1a >> 1) & 3)) * 16));
    const __half* Abase  = A  + (size_t)(m0 + r0a) * K + c0a * 8;
    const __half* Abase1 = A  + (size_t)(m0 + r1a) * K + c0a * 8;
    const __half* Bbase  = Wt + (size_t)(n0 + r0a) * K + c0a * 8;
    const __half* Bbase1 = Wt + (size_t)(n0 + r1a) * K + c0a * 8;

    // ldmatrix addressing
    const int r8 = lane & 7, sel = lane >> 3;
    uint32_t a_addr[4]; int a_sw[4];
    #pragma unroll
    for (int mi = 0; mi < 4; mi++) {
        int r = wm + mi * 16 + (sel & 1) * 8 + r8;
        a_addr[mi] = r * 64;
        a_sw[mi] = (r >> 1) & 3;
    }
    const int a_hi = sel >> 1;
    uint32_t b_addr[2]; int b_sw[2];
    #pragma unroll
    for (int nj = 0; nj < 2; nj++) {
        int r = wn + (nj * 2 + (sel >> 1)) * 8 + r8;
        b_addr[nj] = (uint32_t)(8192 + r * 64);
        b_sw[nj] = (r >> 1) & 3;
    }
    const int b_hi = sel & 1;

    float acc[4][4][4] = {};

    auto issue = [&](int s, int kc) {
        const uint32_t st = sb + s * STG_BYTES;
        const int ko = kc * 32;
        CP_ASYNC16(st + dstA0, Abase + ko);
        CP_ASYNC16(st + dstA1, Abase1 + ko);
        CP_ASYNC16(st + 8192 + dstA0, Bbase + ko);
        CP_ASYNC16(st + 8192 + dstA1, Bbase1 + ko);
        CP_COMMIT();
    };

    const int NC = K >> 5;
    issue(0, 0);
    issue(1, 1);

    for (int kc = 0; kc < NC; kc++) {
        const int cur = kc % STAGES;
        // prefetch first (stage (kc+2)%3 was last read at kc-1, behind barrier),
        // then wait with tail-aware count so stage `cur` is ALWAYS complete.
        if (kc + 2 < NC) {
            issue((kc + 2) % STAGES, kc + 2);
            CP_WAIT(2);
        } else if (kc + 1 < NC) {
            CP_WAIT(1);
        } else {
            CP_WAIT(0);
        }
        __syncthreads();

        const uint32_t stb = sb + cur * STG_BYTES;
        #pragma unroll
        for (int ks = 0; ks < 2; ks++) {
            unsigned af[4][4], bf[4][2];
            #pragma unroll
            for (int mi = 0; mi < 4; mi++) {
                uint32_t addr = stb + a_addr[mi]
                              + (uint32_t)(((ks * 2 + a_hi) ^ a_sw[mi]) * 16);
                asm volatile(
                    "ldmatrix.sync.aligned.m8n8.x4.shared.b16 {%0,%1,%2,%3}, [%4];"
                    : "=r"(af[mi][0]), "=r"(af[mi][1]), "=r"(af[mi][2]), "=r"(af[mi][3])
                    : "r"(addr));
            }
            #pragma unroll
            for (int nj = 0; nj < 2; nj++) {
                uint32_t addr = stb + b_addr[nj]
                              + (uint32_t)(((ks * 2 + b_hi) ^ b_sw[nj]) * 16);
                asm volatile(
                    "ldmatrix.sync.aligned.m8n8.x4.shared.b16 {%0,%1,%2,%3}, [%4];"
                    : "=r"(bf[nj*2][0]), "=r"(bf[nj*2][1]),
                      "=r"(bf[nj*2+1][0]), "=r"(bf[nj*2+1][1])
                    : "r"(addr));
            }
            #pragma unroll
            for (int mi = 0; mi < 4; mi++)
                #pragma unroll
                for (int ni = 0; ni < 4; ni++)
                    mma16(acc[mi][ni], af[mi], bf[ni][0], bf[ni][1]);
        }
        __syncthreads();
    }

    // epilogue
    const int g = lane >> 2, c4 = lane & 3;
    #pragma unroll
    for (int mi = 0; mi < 4; mi++) {
        #pragma unroll
        for (int ni = 0; ni < 4; ni++) {
            int gn = n0 + wn + ni * 8 + c4 * 2;
            float bv0 = bias[gn], bv1 = bias[gn + 1];
            #pragma unroll
            for (int half_ = 0; half_ < 2; half_++) {
                int gr = m0 + wm + mi * 16 + g + half_ * 8;
                float v0 = acc[mi][ni][half_ * 2 + 0] + bv0;
                float v1 = acc[mi][ni][half_ * 2 + 1] + bv1;
                if (act) {
                    v0 = 0.5f * v0 * (1.0f + erff(v0 * 0.70710678118654752f));
                    v1 = 0.5f * v1 * (1.0f + erff(v1 * 0.70710678118654752f));
                }
                size_t o = (size_t)gr * N + gn;
                if (res) { v0 += res[o]; v1 += res[o + 1]; }
                if (Ch) {
                    *(__half2*)(Ch + o) = __floats2half2_rn(v0, v1);
                } else {
                    C[o] = v0; C[o + 1] = v1;
                }
            }
        }
    }
}

// ---------------- Flash attention (TF32 legacy MMA), HD=64, fp16 ctx out ----
#define APAD 68
#define ATTN_SMEM (3 * 64 * APAD * 4)

__global__ __launch_bounds__(128) void attn_kernel(
    const float* __restrict__ Q, const float* __restrict__ Kb,
    const float* __restrict__ Vb, __half* __restrict__ O) {
    extern __shared__ float sm[];
    float* Ks = sm;
    float* Vs = sm + 64 * APAD;
    float* Ps = sm + 2 * 64 * APAD;

    int tid = threadIdx.x, lane = tid & 31, warp = tid >> 5;
    int g = lane >> 2, c4 = lane & 3;
    int bh = blockIdx.x, qt = blockIdx.y;
    int b = bh >> 4, h = bh & 15;

    unsigned aQ[8][4];
    {
        int qr = qt * 64 + warp * 16 + g;
        const float* q0 = Q + ((size_t)(b * SEQ + qr)) * DMODEL + h * HD;
        const float* q8 = q0 + (size_t)8 * DMODEL;
        #pragma unroll
        for (int ks = 0; ks < 8; ks++) {
            int col = ks * 8 + c4;
            aQ[ks][0] = f2tf(q0[col] * 0.125f);
            aQ[ks][1] = f2tf(q8[col] * 0.125f);
            aQ[ks][2] = f2tf(q0[col + 4] * 0.125f);
            aQ[ks][3] = f2tf(q8[col + 4] * 0.125f);
        }
    }

    float m0 = -INFINITY, m1 = -INFINITY, l0 = 0.f, l1 = 0.f;
    float acc[8][4] = {};

    for (int kt = 0; kt < SEQ / 64; kt++) {
        __syncthreads();
        #pragma unroll
        for (int i = 0; i < 8; i++) {
            int cidx = tid + i * 128;
            int kr = cidx >> 4, h4 = cidx & 15;
            size_t goff = ((size_t)(b * SEQ + kt * 64 + kr)) * DMODEL + h * HD + h4 * 4;
            float4 kv = *(const float4*)(Kb + goff);
            float4 vv = *(const float4*)(Vb + goff);
            float* kd = &Ks[kr * APAD + h4 * 4];
            kd[0] = f2tf_f(kv.x); kd[1] = f2tf_f(kv.y);
            kd[2] = f2tf_f(kv.z); kd[3] = f2tf_f(kv.w);
            float* vd = &Vs[kr * APAD + h4 * 4];
            vd[0] = f2tf_f(vv.x); vd[1] = f2tf_f(vv.y);
            vd[2] = f2tf_f(vv.z); vd[3] = f2tf_f(vv.w);
        }
        __syncthreads();

        float s[8][4] = {};
        #pragma unroll
        for (int ks = 0; ks < 8; ks++) {
            #pragma unroll
            for (int nt = 0; nt < 8; nt++) {
                unsigned b0 = __float_as_uint(Ks[(nt * 8 + g) * APAD + ks * 8 + c4]);
                unsigned b1 = __float_as_uint(Ks[(nt * 8 + g) * APAD + ks * 8 + c4 + 4]);
                mma8(s[nt], aQ[ks], b0, b1);
            }
        }

        float tm0 = -INFINITY, tm1 = -INFINITY;
        #pragma unroll
        for (int nt = 0; nt < 8; nt++) {
            tm0 = fmaxf(tm0, fmaxf(s[nt][0], s[nt][1]));
            tm1 = fmaxf(tm1, fmaxf(s[nt][2], s[nt][3]));
        }
        tm0 = fmaxf(tm0, __shfl_xor_sync(0xffffffffu, tm0, 1));
        tm0 = fmaxf(tm0, __shfl_xor_sync(0xffffffffu, tm0, 2));
        tm1 = fmaxf(tm1, __shfl_xor_sync(0xffffffffu, tm1, 1));
        tm1 = fmaxf(tm1, __shfl_xor_sync(0xffffffffu, tm1, 2));
        float mn0 = fmaxf(m0, tm0), mn1 = fmaxf(m1, tm1);
        float cf0 = __expf(m0 - mn0), cf1 = __expf(m1 - mn1);
        m0 = mn0; m1 = mn1;

        float rs0 = 0.f, rs1 = 0.f;
        int pr = warp * 16 + g;
        #pragma unroll
        for (int nt = 0; nt < 8; nt++) {
            float p0 = __expf(s[nt][0] - m0), p1 = __expf(s[nt][1] - m0);
            float p2 = __expf(s[nt][2] - m1), p3 = __expf(s[nt][3] - m1);
            rs0 += p0 + p1; rs1 += p2 + p3;
            int pc = nt * 8 + c4 * 2;
            Ps[pr * APAD + pc]       = f2tf_f(p0);
            Ps[pr * APAD + pc + 1]   = f2tf_f(p1);
            Ps[(pr + 8) * APAD + pc]     = f2tf_f(p2);
            Ps[(pr + 8) * APAD + pc + 1] = f2tf_f(p3);
        }
        rs0 += __shfl_xor_sync(0xffffffffu, rs0, 1);
        rs0 += __shfl_xor_sync(0xffffffffu, rs0, 2);
        rs1 += __shfl_xor_sync(0xffffffffu, rs1, 1);
        rs1 += __shfl_xor_sync(0xffffffffu, rs1, 2);
        l0 = l0 * cf0 + rs0; l1 = l1 * cf1 + rs1;
        #pragma unroll
        for (int nt = 0; nt < 8; nt++) {
            acc[nt][0] *= cf0; acc[nt][1] *= cf0;
            acc[nt][2] *= cf1; acc[nt][3] *= cf1;
        }
        __syncwarp();

        #pragma unroll
        for (int ks = 0; ks < 8; ks++) {
            unsigned a[4];
            a[0] = __float_as_uint(Ps[(warp * 16 + g) * APAD + ks * 8 + c4]);
            a[1] = __float_as_uint(Ps[(warp * 16 + g + 8) * APAD + ks * 8 + c4]);
            a[2] = __float_as_uint(Ps[(warp * 16 + g) * APAD + ks * 8 + c4 + 4]);
            a[3] = __float_as_uint(Ps[(warp * 16 + g + 8) * APAD + ks * 8 + c4 + 4]);
            #pragma unroll
            for (int nt = 0; nt < 8; nt++) {
                unsigned b0 = __float_as_uint(Vs[(ks * 8 + c4) * APAD + nt * 8 + g]);
                unsigned b1 = __float_as_uint(Vs[(ks * 8 + c4 + 4) * APAD + nt * 8 + g]);
                mma8(acc[nt], a, b0, b1);
            }
        }
    }

    float inv0 = 1.0f / l0, inv1 = 1.0f / l1;
    int qr = qt * 64 + warp * 16 + g;
    #pragma unroll
    for (int nt = 0; nt < 8; nt++) {
        size_t o = ((size_t)(b * SEQ + qr)) * DMODEL + h * HD + nt * 8 + c4 * 2;
        *(__half2*)(O + o) = __floats2half2_rn(acc[nt][0] * inv0, acc[nt][1] * inv0);
        *(__half2*)(O + o + (size_t)8 * DMODEL) =
            __floats2half2_rn(acc[nt][2] * inv1, acc[nt][3] * inv1);
    }
}

// ---------------- launch ----------------
extern "C" void kernel_launch(void* const* d_in, const int* in_sizes, int n_in,
                              void* d_out, int out_size) {
    const float* x     = (const float*)d_in[0];
    const float* ln1_g = (const float*)d_in[1];
    const float* ln1_b = (const float*)d_in[2];
    const float* ln2_g = (const float*)d_in[3];
    const float* ln2_b = (const float*)d_in[4];
    const float* wq    = (const float*)d_in[5];
    const float* bq    = (const float*)d_in[6];
    const float* wk    = (const float*)d_in[7];
    const float* bk    = (const float*)d_in[8];
    const float* wv    = (const float*)d_in[9];
    const float* bv    = (const float*)d_in[10];
    const float* wp    = (const float*)d_in[11];
    const float* bp    = (const float*)d_in[12];
    const float* ln3_g = (const float*)d_in[13];
    const float* ln3_b = (const float*)d_in[14];
    const float* w1    = (const float*)d_in[15];
    const float* b1    = (const float*)d_in[16];
    const float* w2    = (const float*)d_in[17];
    const float* b2    = (const float*)d_in[18];
    float* out = (float*)d_out;

    float *q, *k, *v, *y1;
    __half *xnh, *ctxh, *ffh, *wqT, *wkT, *wvT, *wpT, *w1T, *w2T;
    cudaGetSymbolAddress((void**)&q,    g_q);
    cudaGetSymbolAddress((void**)&k,    g_k);
    cudaGetSymbolAddress((void**)&v,    g_v);
    cudaGetSymbolAddress((void**)&y1,   g_y1);
    cudaGetSymbolAddress((void**)&xnh,  g_xnh);
    cudaGetSymbolAddress((void**)&ctxh, g_ctxh);
    cudaGetSymbolAddress((void**)&ffh,  g_ffh);
    cudaGetSymbolAddress((void**)&wqT,  g_wqT);
    cudaGetSymbolAddress((void**)&wkT,  g_wkT);
    cudaGetSymbolAddress((void**)&wvT,  g_wvT);
    cudaGetSymbolAddress((void**)&wpT,  g_wpT);
    cudaGetSymbolAddress((void**)&w1T,  g_w1T);
    cudaGetSymbolAddress((void**)&w2T,  g_w2T);

    cudaFuncSetAttribute(attn_kernel,
                         cudaFuncAttributeMaxDynamicSharedMemorySize, ATTN_SMEM);

    // 0. convert + transpose weights to fp16 (once per launch; ~25us)
    dim3 tblk(32, 8);
    cvt_transpose_kernel<<<dim3(DMODEL/32, DMODEL/32), tblk>>>(wq, wqT, DMODEL, DMODEL);
    cvt_transpose_kernel<<<dim3(DMODEL/32, DMODEL/32), tblk>>>(wk, wkT, DMODEL, DMODEL);
    cvt_transpose_kernel<<<dim3(DMODEL/32, DMODEL/32), tblk>>>(wv, wvT, DMODEL, DMODEL);
    cvt_transpose_kernel<<<dim3(DMODEL/32, DMODEL/32), tblk>>>(wp, wpT, DMODEL, DMODEL);
    cvt_transpose_kernel<<<dim3(DMODEL/32, FFDIM/32),  tblk>>>(w1, w1T, DMODEL, FFDIM);
    cvt_transpose_kernel<<<dim3(FFDIM/32,  DMODEL/32), tblk>>>(w2, w2T, FFDIM, DMODEL);

    // 1. double pre-norm -> fp16
    ln_double_kernel<<<MROWS, 256>>>(x, ln1_g, ln1_b, ln2_g, ln2_b, xnh);

    // 2-4. Q, K, V projections (fp16 cp.async GEMM, fp32 out)
    dim3 gqkv(DMODEL / 128, MROWS / 128);
    gemm_f16_kernel<<<gqkv, 256>>>(xnh, wqT, bq, nullptr, q, nullptr, MROWS, DMODEL, DMODEL, 0);
    gemm_f16_kernel<<<gqkv, 256>>>(xnh, wkT, bk, nullptr, k, nullptr, MROWS, DMODEL, DMODEL, 0);
    gemm_f16_kernel<<<gqkv, 256>>>(xnh, wvT, bv, nullptr, v, nullptr, MROWS, DMODEL, DMODEL, 0);

    // 5. attention -> fp16 ctx
    attn_kernel<<<dim3(BATCH * NHEAD, SEQ / 64), 128, ATTN_SMEM>>>(q, k, v, ctxh);

    // 6. output projection + residual (fp32 out)
    gemm_f16_kernel<<<gqkv, 256>>>(ctxh, wpT, bp, x, y1, nullptr, MROWS, DMODEL, DMODEL, 0);

    // 7. ffn pre-norm -> fp16
    ln_single_kernel<<<MROWS, 256>>>(y1, ln3_g, ln3_b, xnh);

    // 8. FFN: w1 (+gelu, fp16 out), w2 (+residual, fp32 out -> d_out)
    gemm_f16_kernel<<<dim3(FFDIM / 128, MROWS / 128), 256>>>(
        xnh, w1T, b1, nullptr, nullptr, ffh, MROWS, FFDIM, DMODEL, 1);
    gemm_f16_kernel<<<gqkv, 256>>>(ffh, w2T, b2, y1, out, nullptr, MROWS, DMODEL, FFDIM, 0);
}

// round 7
// speedup vs baseline: 2.4314x; 1.2948x over previous
#include <cuda_runtime.h>
#include <cuda_fp16.h>
#include <math.h>
#include <stdint.h>

// Shapes (fixed by the problem)
#define BATCH 8
#define SEQ   1024
#define DMODEL 1024
#define NHEAD 16
#define HD    64
#define FFDIM 4096
#define MROWS (BATCH*SEQ)   // 8192

// ---------------- scratch (device globals; no allocation allowed) ----------
__device__ float g_y1 [MROWS*DMODEL];

__device__ __half g_xnh [MROWS*DMODEL];
__device__ __half g_qkvh[MROWS*3*DMODEL];     // [token][3072]: q|k|v
__device__ __half g_ctxh[MROWS*DMODEL];
__device__ __half g_ffh [MROWS*FFDIM];

__device__ __half g_wqkvT[3*DMODEL*DMODEL];   // [3072][1024]
__device__ __half g_wpT[DMODEL*DMODEL];
__device__ __half g_w1T[DMODEL*FFDIM];
__device__ __half g_w2T[FFDIM*DMODEL];
__device__ float  g_bqkv[3*DMODEL];

// ---------------- common helpers ----------------
__device__ __forceinline__ void mma16(float acc[4], const unsigned a[4],
                                      unsigned b0, unsigned b1) {
    asm volatile(
        "mma.sync.aligned.m16n8k16.row.col.f32.f16.f16.f32 "
        "{%0,%1,%2,%3}, {%4,%5,%6,%7}, {%8,%9}, {%0,%1,%2,%3};\n"
        : "+f"(acc[0]), "+f"(acc[1]), "+f"(acc[2]), "+f"(acc[3])
        : "r"(a[0]), "r"(a[1]), "r"(a[2]), "r"(a[3]), "r"(b0), "r"(b1));
}

__device__ __forceinline__ uint32_t smem_u32(const void* p) {
    uint32_t a;
    asm("{ .reg .u64 t; cvta.to.shared.u64 t, %1; cvt.u32.u64 %0, t; }"
        : "=r"(a) : "l"(p));
    return a;
}

#define CP_ASYNC16(dst, src) \
    asm volatile("cp.async.cg.shared.global [%0], [%1], 16;" :: "r"(dst), "l"(src))
#define CP_COMMIT()   asm volatile("cp.async.commit_group;" ::: "memory")
#define CP_WAIT(n)    asm volatile("cp.async.wait_group %0;" :: "n"(n) : "memory")

__device__ __forceinline__ unsigned pack2(float a, float b) {
    __half2 h = __floats2half2_rn(a, b);
    return *(unsigned*)&h;
}

__device__ __forceinline__ float block_sum(float v) {
    __shared__ float sh[32];
    int tid = threadIdx.x;
    #pragma unroll
    for (int o = 16; o; o >>= 1) v += __shfl_xor_sync(0xffffffffu, v, o);
    __syncthreads();
    if ((tid & 31) == 0) sh[tid >> 5] = v;
    __syncthreads();
    if (tid < 32) {
        float t = (tid < (int)(blockDim.x >> 5)) ? sh[tid] : 0.f;
        #pragma unroll
        for (int o = 4; o; o >>= 1) t += __shfl_xor_sync(0xffffffffu, t, o);
        if (tid == 0) sh[0] = t;
    }
    __syncthreads();
    return sh[0];
}

// ---------------- weight convert + transpose: W[K,N] f32 -> Wt[N,K] f16 -----
__global__ void cvt_transpose_kernel(const float* __restrict__ W,
                                     __half* __restrict__ Wt, int K, int N) {
    __shared__ float t[32][33];
    int bk = blockIdx.x * 32, bn = blockIdx.y * 32;
    int tx = threadIdx.x, ty = threadIdx.y;   // (32, 8)
    #pragma unroll
    for (int i = 0; i < 4; i++)
        t[ty + i * 8][tx] = W[(size_t)(bk + ty + i * 8) * N + bn + tx];
    __syncthreads();
    #pragma unroll
    for (int i = 0; i < 4; i++)
        Wt[(size_t)(bn + ty + i * 8) * K + bk + tx] = __float2half(t[tx][ty + i * 8]);
}

__global__ void cat_bias_kernel(const float* __restrict__ bq,
                                const float* __restrict__ bk,
                                const float* __restrict__ bv,
                                float* __restrict__ out) {
    int i = blockIdx.x * 256 + threadIdx.x;
    if (i < DMODEL) {
        out[i] = bq[i];
        out[DMODEL + i] = bk[i];
        out[2 * DMODEL + i] = bv[i];
    }
}

// ---------------- LayerNorm kernels (write fp16) -----------------------------
__global__ void ln_double_kernel(const float* __restrict__ X,
                                 const float* __restrict__ g1, const float* __restrict__ b1,
                                 const float* __restrict__ g2, const float* __restrict__ b2,
                                 __half* __restrict__ Y) {
    int row = blockIdx.x, tid = threadIdx.x;
    float4 v = ((const float4*)X)[(size_t)row * 256 + tid];
    float mu = block_sum(v.x + v.y + v.z + v.w) * (1.0f / 1024.0f);
    float d0 = v.x - mu, d1 = v.y - mu, d2 = v.z - mu, d3 = v.w - mu;
    float var = block_sum(d0*d0 + d1*d1 + d2*d2 + d3*d3) * (1.0f / 1024.0f);
    float inv = rsqrtf(var + 1e-6f);
    float4 G = ((const float4*)g1)[tid], Bv = ((const float4*)b1)[tid];
    float y0 = d0*inv*G.x + Bv.x, y1 = d1*inv*G.y + Bv.y;
    float y2 = d2*inv*G.z + Bv.z, y3 = d3*inv*G.w + Bv.w;
    float mu2 = block_sum(y0 + y1 + y2 + y3) * (1.0f / 1024.0f);
    float e0 = y0 - mu2, e1 = y1 - mu2, e2 = y2 - mu2, e3 = y3 - mu2;
    float var2 = block_sum(e0*e0 + e1*e1 + e2*e2 + e3*e3) * (1.0f / 1024.0f);
    float inv2 = rsqrtf(var2 + 1e-6f);
    float4 G2 = ((const float4*)g2)[tid], B2 = ((const float4*)b2)[tid];
    __half2 h0 = __floats2half2_rn(e0*inv2*G2.x + B2.x, e1*inv2*G2.y + B2.y);
    __half2 h1 = __floats2half2_rn(e2*inv2*G2.z + B2.z, e3*inv2*G2.w + B2.w);
    ((__half2*)Y)[(size_t)row * 512 + tid * 2]     = h0;
    ((__half2*)Y)[(size_t)row * 512 + tid * 2 + 1] = h1;
}

__global__ void ln_single_kernel(const float* __restrict__ X,
                                 const float* __restrict__ g, const float* __restrict__ b,
                                 __half* __restrict__ Y) {
    int row = blockIdx.x, tid = threadIdx.x;
    float4 v = ((const float4*)X)[(size_t)row * 256 + tid];
    float mu = block_sum(v.x + v.y + v.z + v.w) * (1.0f / 1024.0f);
    float d0 = v.x - mu, d1 = v.y - mu, d2 = v.z - mu, d3 = v.w - mu;
    float var = block_sum(d0*d0 + d1*d1 + d2*d2 + d3*d3) * (1.0f / 1024.0f);
    float inv = rsqrtf(var + 1e-6f);
    float4 G = ((const float4*)g)[tid], Bv = ((const float4*)b)[tid];
    __half2 h0 = __floats2half2_rn(d0*inv*G.x + Bv.x, d1*inv*G.y + Bv.y);
    __half2 h1 = __floats2half2_rn(d2*inv*G.z + Bv.z, d3*inv*G.w + Bv.w);
    ((__half2*)Y)[(size_t)row * 512 + tid * 2]     = h0;
    ((__half2*)Y)[(size_t)row * 512 + tid * 2 + 1] = h1;
}

// ---------------- FP16 cp.async GEMM (proven round 6) ------------------------
#define STAGES 3
#define STG_BYTES 16384          // A 8KB + B 8KB

__global__ __launch_bounds__(256, 2) void gemm_f16_kernel(
    const __half* __restrict__ A, const __half* __restrict__ Wt,
    const float* __restrict__ bias, const float* __restrict__ res,
    float* __restrict__ C, __half* __restrict__ Ch,
    int M, int N, int K, int act)
{
    __shared__ __align__(128) char gsm[STAGES * STG_BYTES];
    const uint32_t sb = smem_u32(gsm);
    const int tid = threadIdx.x, lane = tid & 31, warp = tid >> 5;
    const int m0 = blockIdx.y * 128, n0 = blockIdx.x * 128;
    const int wm = (warp >> 2) * 64, wn = (warp & 3) * 32;

    const int r0a = tid >> 2, c0a = tid & 3;
    const int r1a = (tid + 256) >> 2;
    const uint32_t dstA0 = (uint32_t)(r0a * 64 + ((c0a ^ ((r0a >> 1) & 3)) * 16));
    const uint32_t dstA1 = (uint32_t)(r1a * 64 + ((c0a ^ ((r1a >> 1) & 3)) * 16));
    const __half* Abase  = A  + (size_t)(m0 + r0a) * K + c0a * 8;
    const __half* Abase1 = A  + (size_t)(m0 + r1a) * K + c0a * 8;
    const __half* Bbase  = Wt + (size_t)(n0 + r0a) * K + c0a * 8;
    const __half* Bbase1 = Wt + (size_t)(n0 + r1a) * K + c0a * 8;

    const int r8 = lane & 7, sel = lane >> 3;
    uint32_t a_addr[4]; int a_sw[4];
    #pragma unroll
    for (int mi = 0; mi < 4; mi++) {
        int r = wm + mi * 16 + (sel & 1) * 8 + r8;
        a_addr[mi] = r * 64;
        a_sw[mi] = (r >> 1) & 3;
    }
    const int a_hi = sel >> 1;
    uint32_t b_addr[2]; int b_sw[2];
    #pragma unroll
    for (int nj = 0; nj < 2; nj++) {
        int r = wn + (nj * 2 + (sel >> 1)) * 8 + r8;
        b_addr[nj] = (uint32_t)(8192 + r * 64);
        b_sw[nj] = (r >> 1) & 3;
    }
    const int b_hi = sel & 1;

    float acc[4][4][4] = {};

    auto issue = [&](int s, int kc) {
        const uint32_t st = sb + s * STG_BYTES;
        const int ko = kc * 32;
        CP_ASYNC16(st + dstA0, Abase + ko);
        CP_ASYNC16(st + dstA1, Abase1 + ko);
        CP_ASYNC16(st + 8192 + dstA0, Bbase + ko);
        CP_ASYNC16(st + 8192 + dstA1, Bbase1 + ko);
        CP_COMMIT();
    };

    const int NC = K >> 5;
    issue(0, 0);
    issue(1, 1);

    for (int kc = 0; kc < NC; kc++) {
        const int cur = kc % STAGES;
        if (kc + 2 < NC) {
            issue((kc + 2) % STAGES, kc + 2);
            CP_WAIT(2);
        } else if (kc + 1 < NC) {
            CP_WAIT(1);
        } else {
            CP_WAIT(0);
        }
        __syncthreads();

        const uint32_t stb = sb + cur * STG_BYTES;
        #pragma unroll
        for (int ks = 0; ks < 2; ks++) {
            unsigned af[4][4], bf[4][2];
            #pragma unroll
            for (int mi = 0; mi < 4; mi++) {
                uint32_t addr = stb + a_addr[mi]
                              + (uint32_t)(((ks * 2 + a_hi) ^ a_sw[mi]) * 16);
                asm volatile(
                    "ldmatrix.sync.aligned.m8n8.x4.shared.b16 {%0,%1,%2,%3}, [%4];"
                    : "=r"(af[mi][0]), "=r"(af[mi][1]), "=r"(af[mi][2]), "=r"(af[mi][3])
                    : "r"(addr));
            }
            #pragma unroll
            for (int nj = 0; nj < 2; nj++) {
                uint32_t addr = stb + b_addr[nj]
                              + (uint32_t)(((ks * 2 + b_hi) ^ b_sw[nj]) * 16);
                asm volatile(
                    "ldmatrix.sync.aligned.m8n8.x4.shared.b16 {%0,%1,%2,%3}, [%4];"
                    : "=r"(bf[nj*2][0]), "=r"(bf[nj*2][1]),
                      "=r"(bf[nj*2+1][0]), "=r"(bf[nj*2+1][1])
                    : "r"(addr));
            }
            #pragma unroll
            for (int mi = 0; mi < 4; mi++)
                #pragma unroll
                for (int ni = 0; ni < 4; ni++)
                    mma16(acc[mi][ni], af[mi], bf[ni][0], bf[ni][1]);
        }
        __syncthreads();
    }

    const int g = lane >> 2, c4 = lane & 3;
    #pragma unroll
    for (int mi = 0; mi < 4; mi++) {
        #pragma unroll
        for (int ni = 0; ni < 4; ni++) {
            int gn = n0 + wn + ni * 8 + c4 * 2;
            float bv0 = bias[gn], bv1 = bias[gn + 1];
            #pragma unroll
            for (int half_ = 0; half_ < 2; half_++) {
                int gr = m0 + wm + mi * 16 + g + half_ * 8;
                float v0 = acc[mi][ni][half_ * 2 + 0] + bv0;
                float v1 = acc[mi][ni][half_ * 2 + 1] + bv1;
                if (act) {
                    v0 = 0.5f * v0 * (1.0f + erff(v0 * 0.70710678118654752f));
                    v1 = 0.5f * v1 * (1.0f + erff(v1 * 0.70710678118654752f));
                }
                size_t o = (size_t)gr * N + gn;
                if (res) { v0 += res[o]; v1 += res[o + 1]; }
                if (Ch) {
                    *(__half2*)(Ch + o) = __floats2half2_rn(v0, v1);
                } else {
                    C[o] = v0; C[o + 1] = v1;
                }
            }
        }
    }
}

// ---------------- FP16 flash attention --------------------------------------
// CTA: 64 q rows (4 warps x 16), K-block 64 keys, double-buffered cp.async.
// QKV: [token][3072] fp16 (q|k|v, head h at col h*64 within each third).
// smem tile rows = 64 halfs = 128B = 8 chunks of 16B; swizzle chunk ^= row&7.
#define ATT_STG 16384            // K 8KB + V 8KB per stage
#define QKV_LD  (3 * DMODEL)

__global__ __launch_bounds__(128) void attn_f16_kernel(
    const __half* __restrict__ QKV, __half* __restrict__ O) {
    __shared__ __align__(128) char smb[2 * ATT_STG];
    const uint32_t sb = smem_u32(smb);
    const int tid = threadIdx.x, lane = tid & 31, warp = tid >> 5;
    const int g = lane >> 2, c4 = lane & 3;
    const int bh = blockIdx.x, qt = blockIdx.y;
    const int b = bh >> 4, h = bh & 15;

    // ---- Q fragments: 4 hd k-tiles x 4 half2 regs, scaled by 0.125 ----
    unsigned aQ[4][4];
    const int qr = qt * 64 + warp * 16 + g;
    {
        const __half2 sc = __floats2half2_rn(0.125f, 0.125f);
        const __half* q0 = QKV + (size_t)(b * SEQ + qr) * QKV_LD + h * HD;
        const __half* q8 = q0 + (size_t)8 * QKV_LD;
        #pragma unroll
        for (int j = 0; j < 4; j++) {
            __half2 t;
            t = __hmul2(*(const __half2*)(q0 + j * 16 + 2 * c4), sc);     aQ[j][0] = *(unsigned*)&t;
            t = __hmul2(*(const __half2*)(q8 + j * 16 + 2 * c4), sc);     aQ[j][1] = *(unsigned*)&t;
            t = __hmul2(*(const __half2*)(q0 + j * 16 + 8 + 2 * c4), sc); aQ[j][2] = *(unsigned*)&t;
            t = __hmul2(*(const __half2*)(q8 + j * 16 + 8 + 2 * c4), sc); aQ[j][3] = *(unsigned*)&t;
        }
    }

    // staging mapping: thread t -> row t>>1, chunks (t&1)*4 .. +3
    const int sr = tid >> 1, sc4 = (tid & 1) * 4;
    const __half* ksrc0 = QKV + (size_t)(b * SEQ + sr) * QKV_LD + DMODEL + h * HD;
    const __half* vsrc0 = ksrc0 + DMODEL;

    auto issue = [&](int s, int kt) {
        const uint32_t st = sb + s * ATT_STG;
        const size_t roff = (size_t)(kt * 64) * QKV_LD;
        #pragma unroll
        for (int j = 0; j < 4; j++) {
            int c = sc4 + j;
            uint32_t d = (uint32_t)(sr * 128 + ((c ^ (sr & 7)) * 16));
            CP_ASYNC16(st + d, ksrc0 + roff + c * 8);
            CP_ASYNC16(st + 8192 + d, vsrc0 + roff + c * 8);
        }
        CP_COMMIT();
    };

    float m0 = -INFINITY, m1 = -INFINITY, l0 = 0.f, l1 = 0.f;
    float acc[8][4] = {};

    const int sel = lane >> 3, r8 = lane & 7;

    issue(0, 0);
    const int NT = SEQ / 64;
    for (int kt = 0; kt < NT; kt++) {
        const int cur = kt & 1;
        CP_WAIT(0);
        __syncthreads();
        if (kt + 1 < NT) issue(cur ^ 1, kt + 1);

        const uint32_t Kb = sb + cur * ATT_STG;
        const uint32_t Vb = Kb + 8192;

        // ---- S = Q K^T (rows g/g+8, cols nt*8 + 2c4) ----
        float s[8][4] = {};
        #pragma unroll
        for (int ks = 0; ks < 4; ks++) {
            #pragma unroll
            for (int njp = 0; njp < 4; njp++) {
                // x4 non-trans: m0/m1 = key rows group 2njp (chunk ks*2, +1),
                //               m2/m3 = key rows group 2njp+1
                int row = (njp * 2 + (sel >> 1)) * 8 + r8;
                int c = ks * 2 + (sel & 1);
                uint32_t addr = Kb + (uint32_t)(row * 128 + ((c ^ (row & 7)) * 16));
                unsigned bf0, bf1, bf2, bf3;
                asm volatile(
                    "ldmatrix.sync.aligned.m8n8.x4.shared.b16 {%0,%1,%2,%3}, [%4];"
                    : "=r"(bf0), "=r"(bf1), "=r"(bf2), "=r"(bf3) : "r"(addr));
                mma16(s[njp * 2],     aQ[ks], bf0, bf1);
                mma16(s[njp * 2 + 1], aQ[ks], bf2, bf3);
            }
        }

        // ---- online softmax ----
        float tm0 = -INFINITY, tm1 = -INFINITY;
        #pragma unroll
        for (int nt = 0; nt < 8; nt++) {
            tm0 = fmaxf(tm0, fmaxf(s[nt][0], s[nt][1]));
            tm1 = fmaxf(tm1, fmaxf(s[nt][2], s[nt][3]));
        }
        tm0 = fmaxf(tm0, __shfl_xor_sync(0xffffffffu, tm0, 1));
        tm0 = fmaxf(tm0, __shfl_xor_sync(0xffffffffu, tm0, 2));
        tm1 = fmaxf(tm1, __shfl_xor_sync(0xffffffffu, tm1, 1));
        tm1 = fmaxf(tm1, __shfl_xor_sync(0xffffffffu, tm1, 2));
        float mn0 = fmaxf(m0, tm0), mn1 = fmaxf(m1, tm1);
        float cf0 = __expf(m0 - mn0), cf1 = __expf(m1 - mn1);
        m0 = mn0; m1 = mn1;

        float rs0 = 0.f, rs1 = 0.f;
        #pragma unroll
        for (int nt = 0; nt < 8; nt++) {
            s[nt][0] = __expf(s[nt][0] - m0);
            s[nt][1] = __expf(s[nt][1] - m0);
            s[nt][2] = __expf(s[nt][2] - m1);
            s[nt][3] = __expf(s[nt][3] - m1);
            rs0 += s[nt][0] + s[nt][1];
            rs1 += s[nt][2] + s[nt][3];
        }
        rs0 += __shfl_xor_sync(0xffffffffu, rs0, 1);
        rs0 += __shfl_xor_sync(0xffffffffu, rs0, 2);
        rs1 += __shfl_xor_sync(0xffffffffu, rs1, 1);
        rs1 += __shfl_xor_sync(0xffffffffu, rs1, 2);
        l0 = l0 * cf0 + rs0; l1 = l1 * cf1 + rs1;
        #pragma unroll
        for (int nt = 0; nt < 8; nt++) {
            acc[nt][0] *= cf0; acc[nt][1] *= cf0;
            acc[nt][2] *= cf1; acc[nt][3] *= cf1;
        }

        // ---- P fragments in registers (A of m16n8k16, k = keys) ----
        unsigned aP[4][4];
        #pragma unroll
        for (int j = 0; j < 4; j++) {
            aP[j][0] = pack2(s[2*j][0],   s[2*j][1]);
            aP[j][1] = pack2(s[2*j][2],   s[2*j][3]);
            aP[j][2] = pack2(s[2*j+1][0], s[2*j+1][1]);
            aP[j][3] = pack2(s[2*j+1][2], s[2*j+1][3]);
        }

        // ---- acc += P V  (V via ldmatrix.x4.trans) ----
        #pragma unroll
        for (int j = 0; j < 4; j++) {
            #pragma unroll
            for (int njp = 0; njp < 4; njp++) {
                // m0 = V rows 16j..+7 chunk 2njp, m1 = rows +8 same chunk,
                // m2/m3 = chunk 2njp+1
                int row = 16 * j + (sel & 1) * 8 + r8;
                int c = njp * 2 + (sel >> 1);
                uint32_t addr = Vb + (uint32_t)(row * 128 + ((c ^ (row & 7)) * 16));
                unsigned bf0, bf1, bf2, bf3;
                asm volatile(
                    "ldmatrix.sync.aligned.m8n8.x4.trans.shared.b16 {%0,%1,%2,%3}, [%4];"
                    : "=r"(bf0), "=r"(bf1), "=r"(bf2), "=r"(bf3) : "r"(addr));
                mma16(acc[njp * 2],     aP[j], bf0, bf1);
                mma16(acc[njp * 2 + 1], aP[j], bf2, bf3);
            }
        }
        __syncthreads();
    }

    const float inv0 = 1.0f / l0, inv1 = 1.0f / l1;
    __half* orow0 = O + (size_t)(b * SEQ + qr) * DMODEL + h * HD;
    __half* orow8 = orow0 + (size_t)8 * DMODEL;
    #pragma unroll
    for (int nt = 0; nt < 8; nt++) {
        int col = nt * 8 + 2 * c4;
        *(__half2*)(orow0 + col) = __floats2half2_rn(acc[nt][0] * inv0, acc[nt][1] * inv0);
        *(__half2*)(orow8 + col) = __floats2half2_rn(acc[nt][2] * inv1, acc[nt][3] * inv1);
    }
}

// ---------------- launch ----------------
extern "C" void kernel_launch(void* const* d_in, const int* in_sizes, int n_in,
                              void* d_out, int out_size) {
    const float* x     = (const float*)d_in[0];
    const float* ln1_g = (const float*)d_in[1];
    const float* ln1_b = (const float*)d_in[2];
    const float* ln2_g = (const float*)d_in[3];
    const float* ln2_b = (const float*)d_in[4];
    const float* wq    = (const float*)d_in[5];
    const float* bq    = (const float*)d_in[6];
    const float* wk    = (const float*)d_in[7];
    const float* bk    = (const float*)d_in[8];
    const float* wv    = (const float*)d_in[9];
    const float* bv    = (const float*)d_in[10];
    const float* wp    = (const float*)d_in[11];
    const float* bp    = (const float*)d_in[12];
    const float* ln3_g = (const float*)d_in[13];
    const float* ln3_b = (const float*)d_in[14];
    const float* w1    = (const float*)d_in[15];
    const float* b1    = (const float*)d_in[16];
    const float* w2    = (const float*)d_in[17];
    const float* b2    = (const float*)d_in[18];
    float* out = (float*)d_out;

    float *y1, *bqkv;
    __half *xnh, *qkvh, *ctxh, *ffh, *wqkvT, *wpT, *w1T, *w2T;
    cudaGetSymbolAddress((void**)&y1,    g_y1);
    cudaGetSymbolAddress((void**)&bqkv,  g_bqkv);
    cudaGetSymbolAddress((void**)&xnh,   g_xnh);
    cudaGetSymbolAddress((void**)&qkvh,  g_qkvh);
    cudaGetSymbolAddress((void**)&ctxh,  g_ctxh);
    cudaGetSymbolAddress((void**)&ffh,   g_ffh);
    cudaGetSymbolAddress((void**)&wqkvT, g_wqkvT);
    cudaGetSymbolAddress((void**)&wpT,   g_wpT);
    cudaGetSymbolAddress((void**)&w1T,   g_w1T);
    cudaGetSymbolAddress((void**)&w2T,   g_w2T);

    // 0. weight prep (fp16 transposed); qkv weights concatenated
    dim3 tblk(32, 8);
    cvt_transpose_kernel<<<dim3(DMODEL/32, DMODEL/32), tblk>>>(wq, wqkvT, DMODEL, DMODEL);
    cvt_transpose_kernel<<<dim3(DMODEL/32, DMODEL/32), tblk>>>(wk, wqkvT + DMODEL*DMODEL, DMODEL, DMODEL);
    cvt_transpose_kernel<<<dim3(DMODEL/32, DMODEL/32), tblk>>>(wv, wqkvT + 2*DMODEL*DMODEL, DMODEL, DMODEL);
    cvt_transpose_kernel<<<dim3(DMODEL/32, DMODEL/32), tblk>>>(wp, wpT, DMODEL, DMODEL);
    cvt_transpose_kernel<<<dim3(DMODEL/32, FFDIM/32),  tblk>>>(w1, w1T, DMODEL, FFDIM);
    cvt_transpose_kernel<<<dim3(FFDIM/32,  DMODEL/32), tblk>>>(w2, w2T, FFDIM, DMODEL);
    cat_bias_kernel<<<4, 256>>>(bq, bk, bv, bqkv);

    // 1. double pre-norm -> fp16
    ln_double_kernel<<<MROWS, 256>>>(x, ln1_g, ln1_b, ln2_g, ln2_b, xnh);

    // 2. fused QKV projection (fp16 out, N=3072)
    gemm_f16_kernel<<<dim3(3*DMODEL/128, MROWS/128), 256>>>(
        xnh, wqkvT, bqkv, nullptr, nullptr, qkvh, MROWS, 3*DMODEL, DMODEL, 0);

    // 3. fp16 flash attention -> fp16 ctx
    attn_f16_kernel<<<dim3(BATCH * NHEAD, SEQ / 64), 128>>>(qkvh, ctxh);

    // 4. output projection + residual (fp32 out)
    dim3 gdd(DMODEL / 128, MROWS / 128);
    gemm_f16_kernel<<<gdd, 256>>>(ctxh, wpT, bp, x, y1, nullptr, MROWS, DMODEL, DMODEL, 0);

    // 5. ffn pre-norm -> fp16
    ln_single_kernel<<<MROWS, 256>>>(y1, ln3_g, ln3_b, xnh);

    // 6. FFN: w1 (+gelu, fp16 out), w2 (+residual, fp32 out -> d_out)
    gemm_f16_kernel<<<dim3(FFDIM / 128, MROWS / 128), 256>>>(
        xnh, w1T, b1, nullptr, nullptr, ffh, MROWS, FFDIM, DMODEL, 1);
    gemm_f16_kernel<<<gdd, 256>>>(ffh, w2T, b2, y1, out, nullptr, MROWS, DMODEL, FFDIM, 0);
}

// round 8
// speedup vs baseline: 2.5220x; 1.0372x over previous
#include <cuda_runtime.h>
#include <cuda_fp16.h>
#include <math.h>
#include <stdint.h>

// Shapes (fixed by the problem)
#define BATCH 8
#define SEQ   1024
#define DMODEL 1024
#define NHEAD 16
#define HD    64
#define FFDIM 4096
#define MROWS (BATCH*SEQ)   // 8192

// ---------------- scratch (device globals; no allocation allowed) ----------
__device__ float g_y1 [MROWS*DMODEL];

__device__ __half g_xnh [MROWS*DMODEL];
__device__ __half g_qkvh[MROWS*3*DMODEL];     // [token][3072]: q|k|v
__device__ __half g_ctxh[MROWS*DMODEL];
__device__ __half g_ffh [MROWS*FFDIM];

__device__ __half g_wqkvT[3*DMODEL*DMODEL];   // [3072][1024]
__device__ __half g_wpT[DMODEL*DMODEL];
__device__ __half g_w1T[DMODEL*FFDIM];
__device__ __half g_w2T[FFDIM*DMODEL];
__device__ float  g_bqkv[3*DMODEL];

// ---------------- common helpers ----------------
__device__ __forceinline__ void mma16(float acc[4], const unsigned a[4],
                                      unsigned b0, unsigned b1) {
    asm volatile(
        "mma.sync.aligned.m16n8k16.row.col.f32.f16.f16.f32 "
        "{%0,%1,%2,%3}, {%4,%5,%6,%7}, {%8,%9}, {%0,%1,%2,%3};\n"
        : "+f"(acc[0]), "+f"(acc[1]), "+f"(acc[2]), "+f"(acc[3])
        : "r"(a[0]), "r"(a[1]), "r"(a[2]), "r"(a[3]), "r"(b0), "r"(b1));
}

__device__ __forceinline__ uint32_t smem_u32(const void* p) {
    uint32_t a;
    asm("{ .reg .u64 t; cvta.to.shared.u64 t, %1; cvt.u32.u64 %0, t; }"
        : "=r"(a) : "l"(p));
    return a;
}

#define CP_ASYNC16(dst, src) \
    asm volatile("cp.async.cg.shared.global [%0], [%1], 16;" :: "r"(dst), "l"(src))
#define CP_COMMIT()   asm volatile("cp.async.commit_group;" ::: "memory")
#define CP_WAIT(n)    asm volatile("cp.async.wait_group %0;" :: "n"(n) : "memory")

__device__ __forceinline__ unsigned pack2(float a, float b) {
    __half2 h = __floats2half2_rn(a, b);
    return *(unsigned*)&h;
}

__device__ __forceinline__ float block_sum(float v) {
    __shared__ float sh[32];
    int tid = threadIdx.x;
    #pragma unroll
    for (int o = 16; o; o >>= 1) v += __shfl_xor_sync(0xffffffffu, v, o);
    __syncthreads();
    if ((tid & 31) == 0) sh[tid >> 5] = v;
    __syncthreads();
    if (tid < 32) {
        float t = (tid < (int)(blockDim.x >> 5)) ? sh[tid] : 0.f;
        #pragma unroll
        for (int o = 4; o; o >>= 1) t += __shfl_xor_sync(0xffffffffu, t, o);
        if (tid == 0) sh[0] = t;
    }
    __syncthreads();
    return sh[0];
}

// ---------------- weight convert + transpose: W[K,N] f32 -> Wt[N,K] f16 -----
__global__ void cvt_transpose_kernel(const float* __restrict__ W,
                                     __half* __restrict__ Wt, int K, int N) {
    __shared__ float t[32][33];
    int bk = blockIdx.x * 32, bn = blockIdx.y * 32;
    int tx = threadIdx.x, ty = threadIdx.y;   // (32, 8)
    #pragma unroll
    for (int i = 0; i < 4; i++)
        t[ty + i * 8][tx] = W[(size_t)(bk + ty + i * 8) * N + bn + tx];
    __syncthreads();
    #pragma unroll
    for (int i = 0; i < 4; i++)
        Wt[(size_t)(bn + ty + i * 8) * K + bk + tx] = __float2half(t[tx][ty + i * 8]);
}

__global__ void cat_bias_kernel(const float* __restrict__ bq,
                                const float* __restrict__ bk,
                                const float* __restrict__ bv,
                                float* __restrict__ out) {
    int i = blockIdx.x * 256 + threadIdx.x;
    if (i < DMODEL) {
        out[i] = bq[i];
        out[DMODEL + i] = bk[i];
        out[2 * DMODEL + i] = bv[i];
    }
}

// ---------------- LayerNorm kernels (write fp16) -----------------------------
__global__ void ln_double_kernel(const float* __restrict__ X,
                                 const float* __restrict__ g1, const float* __restrict__ b1,
                                 const float* __restrict__ g2, const float* __restrict__ b2,
                                 __half* __restrict__ Y) {
    int row = blockIdx.x, tid = threadIdx.x;
    float4 v = ((const float4*)X)[(size_t)row * 256 + tid];
    float mu = block_sum(v.x + v.y + v.z + v.w) * (1.0f / 1024.0f);
    float d0 = v.x - mu, d1 = v.y - mu, d2 = v.z - mu, d3 = v.w - mu;
    float var = block_sum(d0*d0 + d1*d1 + d2*d2 + d3*d3) * (1.0f / 1024.0f);
    float inv = rsqrtf(var + 1e-6f);
    float4 G = ((const float4*)g1)[tid], Bv = ((const float4*)b1)[tid];
    float y0 = d0*inv*G.x + Bv.x, y1 = d1*inv*G.y + Bv.y;
    float y2 = d2*inv*G.z + Bv.z, y3 = d3*inv*G.w + Bv.w;
    float mu2 = block_sum(y0 + y1 + y2 + y3) * (1.0f / 1024.0f);
    float e0 = y0 - mu2, e1 = y1 - mu2, e2 = y2 - mu2, e3 = y3 - mu2;
    float var2 = block_sum(e0*e0 + e1*e1 + e2*e2 + e3*e3) * (1.0f / 1024.0f);
    float inv2 = rsqrtf(var2 + 1e-6f);
    float4 G2 = ((const float4*)g2)[tid], B2 = ((const float4*)b2)[tid];
    __half2 h0 = __floats2half2_rn(e0*inv2*G2.x + B2.x, e1*inv2*G2.y + B2.y);
    __half2 h1 = __floats2half2_rn(e2*inv2*G2.z + B2.z, e3*inv2*G2.w + B2.w);
    ((__half2*)Y)[(size_t)row * 512 + tid * 2]     = h0;
    ((__half2*)Y)[(size_t)row * 512 + tid * 2 + 1] = h1;
}

__global__ void ln_single_kernel(const float* __restrict__ X,
                                 const float* __restrict__ g, const float* __restrict__ b,
                                 __half* __restrict__ Y) {
    int row = blockIdx.x, tid = threadIdx.x;
    float4 v = ((const float4*)X)[(size_t)row * 256 + tid];
    float mu = block_sum(v.x + v.y + v.z + v.w) * (1.0f / 1024.0f);
    float d0 = v.x - mu, d1 = v.y - mu, d2 = v.z - mu, d3 = v.w - mu;
    float var = block_sum(d0*d0 + d1*d1 + d2*d2 + d3*d3) * (1.0f / 1024.0f);
    float inv = rsqrtf(var + 1e-6f);
    float4 G = ((const float4*)g)[tid], Bv = ((const float4*)b)[tid];
    __half2 h0 = __floats2half2_rn(d0*inv*G.x + Bv.x, d1*inv*G.y + Bv.y);
    __half2 h1 = __floats2half2_rn(d2*inv*G.z + Bv.z, d3*inv*G.w + Bv.w);
    ((__half2*)Y)[(size_t)row * 512 + tid * 2]     = h0;
    ((__half2*)Y)[(size_t)row * 512 + tid * 2 + 1] = h1;
}

// ---------------- FP16 cp.async GEMM (single barrier per K-chunk) ------------
#define STAGES 3
#define STG_BYTES 16384          // A 8KB + B 8KB

__global__ __launch_bounds__(256, 2) void gemm_f16_kernel(
    const __half* __restrict__ A, const __half* __restrict__ Wt,
    const float* __restrict__ bias, const float* __restrict__ res,
    float* __restrict__ C, __half* __restrict__ Ch,
    int M, int N, int K, int act)
{
    __shared__ __align__(128) char gsm[STAGES * STG_BYTES];
    const uint32_t sb = smem_u32(gsm);
    const int tid = threadIdx.x, lane = tid & 31, warp = tid >> 5;
    const int m0 = blockIdx.y * 128, n0 = blockIdx.x * 128;
    const int wm = (warp >> 2) * 64, wn = (warp & 3) * 32;

    const int r0a = tid >> 2, c0a = tid & 3;
    const int r1a = (tid + 256) >> 2;
    const uint32_t dstA0 = (uint32_t)(r0a * 64 + ((c0a ^ ((r0a >> 1) & 3)) * 16));
    const uint32_t dstA1 = (uint32_t)(r1a * 64 + ((c0a ^ ((r1a >> 1) & 3)) * 16));
    const __half* Abase  = A  + (size_t)(m0 + r0a) * K + c0a * 8;
    const __half* Abase1 = A  + (size_t)(m0 + r1a) * K + c0a * 8;
    const __half* Bbase  = Wt + (size_t)(n0 + r0a) * K + c0a * 8;
    const __half* Bbase1 = Wt + (size_t)(n0 + r1a) * K + c0a * 8;

    const int r8 = lane & 7, sel = lane >> 3;
    uint32_t a_addr[4]; int a_sw[4];
    #pragma unroll
    for (int mi = 0; mi < 4; mi++) {
        int r = wm + mi * 16 + (sel & 1) * 8 + r8;
        a_addr[mi] = r * 64;
        a_sw[mi] = (r >> 1) & 3;
    }
    const int a_hi = sel >> 1;
    uint32_t b_addr[2]; int b_sw[2];
    #pragma unroll
    for (int nj = 0; nj < 2; nj++) {
        int r = wn + (nj * 2 + (sel >> 1)) * 8 + r8;
        b_addr[nj] = (uint32_t)(8192 + r * 64);
        b_sw[nj] = (r >> 1) & 3;
    }
    const int b_hi = sel & 1;

    float acc[4][4][4] = {};

    auto issue = [&](int s, int kc) {
        const uint32_t st = sb + s * STG_BYTES;
        const int ko = kc * 32;
        CP_ASYNC16(st + dstA0, Abase + ko);
        CP_ASYNC16(st + dstA1, Abase1 + ko);
        CP_ASYNC16(st + 8192 + dstA0, Bbase + ko);
        CP_ASYNC16(st + 8192 + dstA1, Bbase1 + ko);
        CP_COMMIT();
    };

    const int NC = K >> 5;
    issue(0, 0);
    issue(1, 1);

    for (int kc = 0; kc < NC; kc++) {
        const int cur = kc % STAGES;
        // wait for stage cur: groups committed so far are g_0..g_{min(kc+1,NC-1)};
        // allow the (kc+1) prefetch to remain in flight.
        if (kc + 1 < NC) CP_WAIT(1); else CP_WAIT(0);
        __syncthreads();   // also orders: all reads of stage (kc+2)%3 (at kc-1) done
        if (kc + 2 < NC) issue((kc + 2) % STAGES, kc + 2);

        const uint32_t stb = sb + cur * STG_BYTES;
        #pragma unroll
        for (int ks = 0; ks < 2; ks++) {
            unsigned af[4][4], bf[4][2];
            #pragma unroll
            for (int mi = 0; mi < 4; mi++) {
                uint32_t addr = stb + a_addr[mi]
                              + (uint32_t)(((ks * 2 + a_hi) ^ a_sw[mi]) * 16);
                asm volatile(
                    "ldmatrix.sync.aligned.m8n8.x4.shared.b16 {%0,%1,%2,%3}, [%4];"
                    : "=r"(af[mi][0]), "=r"(af[mi][1]), "=r"(af[mi][2]), "=r"(af[mi][3])
                    : "r"(addr));
            }
            #pragma unroll
            for (int nj = 0; nj < 2; nj++) {
                uint32_t addr = stb + b_addr[nj]
                              + (uint32_t)(((ks * 2 + b_hi) ^ b_sw[nj]) * 16);
                asm volatile(
                    "ldmatrix.sync.aligned.m8n8.x4.shared.b16 {%0,%1,%2,%3}, [%4];"
                    : "=r"(bf[nj*2][0]), "=r"(bf[nj*2][1]),
                      "=r"(bf[nj*2+1][0]), "=r"(bf[nj*2+1][1])
                    : "r"(addr));
            }
            #pragma unroll
            for (int mi = 0; mi < 4; mi++)
                #pragma unroll
                for (int ni = 0; ni < 4; ni++)
                    mma16(acc[mi][ni], af[mi], bf[ni][0], bf[ni][1]);
        }
    }

    const int g = lane >> 2, c4 = lane & 3;
    #pragma unroll
    for (int mi = 0; mi < 4; mi++) {
        #pragma unroll
        for (int ni = 0; ni < 4; ni++) {
            int gn = n0 + wn + ni * 8 + c4 * 2;
            float bv0 = bias[gn], bv1 = bias[gn + 1];
            #pragma unroll
            for (int half_ = 0; half_ < 2; half_++) {
                int gr = m0 + wm + mi * 16 + g + half_ * 8;
                float v0 = acc[mi][ni][half_ * 2 + 0] + bv0;
                float v1 = acc[mi][ni][half_ * 2 + 1] + bv1;
                if (act) {
                    v0 = 0.5f * v0 * (1.0f + erff(v0 * 0.70710678118654752f));
                    v1 = 0.5f * v1 * (1.0f + erff(v1 * 0.70710678118654752f));
                }
                size_t o = (size_t)gr * N + gn;
                if (res) { v0 += res[o]; v1 += res[o + 1]; }
                if (Ch) {
                    *(__half2*)(Ch + o) = __floats2half2_rn(v0, v1);
                } else {
                    C[o] = v0; C[o + 1] = v1;
                }
            }
        }
    }
}

// ---------------- FP16 flash attention (128 q rows per CTA) ------------------
// CTA: 128 q rows (8 warps x 16), K-block 64 keys, double-buffered cp.async.
// QKV: [token][3072] fp16. smem tile rows = 64 halfs = 128B = 8 x 16B chunks;
// swizzle chunk ^= row&7. Fragment/mma code identical to proven round 7.
#define ATT_STG 16384            // K 8KB + V 8KB per stage
#define QKV_LD  (3 * DMODEL)

__global__ __launch_bounds__(256) void attn_f16_kernel(
    const __half* __restrict__ QKV, __half* __restrict__ O) {
    __shared__ __align__(128) char smb[2 * ATT_STG];
    const uint32_t sb = smem_u32(smb);
    const int tid = threadIdx.x, lane = tid & 31, warp = tid >> 5;
    const int g = lane >> 2, c4 = lane & 3;
    const int bh = blockIdx.x, qt = blockIdx.y;
    const int b = bh >> 4, h = bh & 15;

    // ---- Q fragments: 4 hd k-tiles x 4 half2 regs, scaled by 0.125 ----
    unsigned aQ[4][4];
    const int qr = qt * 128 + warp * 16 + g;
    {
        const __half2 sc = __floats2half2_rn(0.125f, 0.125f);
        const __half* q0 = QKV + (size_t)(b * SEQ + qr) * QKV_LD + h * HD;
        const __half* q8 = q0 + (size_t)8 * QKV_LD;
        #pragma unroll
        for (int j = 0; j < 4; j++) {
            __half2 t;
            t = __hmul2(*(const __half2*)(q0 + j * 16 + 2 * c4), sc);     aQ[j][0] = *(unsigned*)&t;
            t = __hmul2(*(const __half2*)(q8 + j * 16 + 2 * c4), sc);     aQ[j][1] = *(unsigned*)&t;
            t = __hmul2(*(const __half2*)(q0 + j * 16 + 8 + 2 * c4), sc); aQ[j][2] = *(unsigned*)&t;
            t = __hmul2(*(const __half2*)(q8 + j * 16 + 8 + 2 * c4), sc); aQ[j][3] = *(unsigned*)&t;
        }
    }

    // staging: 256 threads, 64 rows x 8 chunks x {K,V}; thread t -> row t>>2,
    // chunks (t&3)*2 and (t&3)*2+1 of each tensor.
    const int sr = tid >> 2, scg = (tid & 3) * 2;
    const __half* ksrc0 = QKV + (size_t)(b * SEQ + sr) * QKV_LD + DMODEL + h * HD;
    const __half* vsrc0 = ksrc0 + DMODEL;

    auto issue = [&](int s, int kt) {
        const uint32_t st = sb + s * ATT_STG;
        const size_t roff = (size_t)(kt * 64) * QKV_LD;
        #pragma unroll
        for (int j = 0; j < 2; j++) {
            int c = scg + j;
            uint32_t d = (uint32_t)(sr * 128 + ((c ^ (sr & 7)) * 16));
            CP_ASYNC16(st + d, ksrc0 + roff + c * 8);
            CP_ASYNC16(st + 8192 + d, vsrc0 + roff + c * 8);
        }
        CP_COMMIT();
    };

    float m0 = -INFINITY, m1 = -INFINITY, l0 = 0.f, l1 = 0.f;
    float acc[8][4] = {};

    const int sel = lane >> 3, r8 = lane & 7;

    issue(0, 0);
    const int NT = SEQ / 64;
    for (int kt = 0; kt < NT; kt++) {
        const int cur = kt & 1;
        CP_WAIT(0);
        __syncthreads();              // readers of stage cur^1 (kt-1) all done
        if (kt + 1 < NT) issue(cur ^ 1, kt + 1);

        const uint32_t Kb = sb + cur * ATT_STG;
        const uint32_t Vb = Kb + 8192;

        // ---- S = Q K^T ----
        float s[8][4] = {};
        #pragma unroll
        for (int ks = 0; ks < 4; ks++) {
            #pragma unroll
            for (int njp = 0; njp < 4; njp++) {
                int row = (njp * 2 + (sel >> 1)) * 8 + r8;
                int c = ks * 2 + (sel & 1);
                uint32_t addr = Kb + (uint32_t)(row * 128 + ((c ^ (row & 7)) * 16));
                unsigned bf0, bf1, bf2, bf3;
                asm volatile(
                    "ldmatrix.sync.aligned.m8n8.x4.shared.b16 {%0,%1,%2,%3}, [%4];"
                    : "=r"(bf0), "=r"(bf1), "=r"(bf2), "=r"(bf3) : "r"(addr));
                mma16(s[njp * 2],     aQ[ks], bf0, bf1);
                mma16(s[njp * 2 + 1], aQ[ks], bf2, bf3);
            }
        }

        // ---- online softmax ----
        float tm0 = -INFINITY, tm1 = -INFINITY;
        #pragma unroll
        for (int nt = 0; nt < 8; nt++) {
            tm0 = fmaxf(tm0, fmaxf(s[nt][0], s[nt][1]));
            tm1 = fmaxf(tm1, fmaxf(s[nt][2], s[nt][3]));
        }
        tm0 = fmaxf(tm0, __shfl_xor_sync(0xffffffffu, tm0, 1));
        tm0 = fmaxf(tm0, __shfl_xor_sync(0xffffffffu, tm0, 2));
        tm1 = fmaxf(tm1, __shfl_xor_sync(0xffffffffu, tm1, 1));
        tm1 = fmaxf(tm1, __shfl_xor_sync(0xffffffffu, tm1, 2));
        float mn0 = fmaxf(m0, tm0), mn1 = fmaxf(m1, tm1);
        float cf0 = __expf(m0 - mn0), cf1 = __expf(m1 - mn1);
        m0 = mn0; m1 = mn1;

        float rs0 = 0.f, rs1 = 0.f;
        #pragma unroll
        for (int nt = 0; nt < 8; nt++) {
            s[nt][0] = __expf(s[nt][0] - m0);
            s[nt][1] = __expf(s[nt][1] - m0);
            s[nt][2] = __expf(s[nt][2] - m1);
            s[nt][3] = __expf(s[nt][3] - m1);
            rs0 += s[nt][0] + s[nt][1];
            rs1 += s[nt][2] + s[nt][3];
        }
        rs0 += __shfl_xor_sync(0xffffffffu, rs0, 1);
        rs0 += __shfl_xor_sync(0xffffffffu, rs0, 2);
        rs1 += __shfl_xor_sync(0xffffffffu, rs1, 1);
        rs1 += __shfl_xor_sync(0xffffffffu, rs1, 2);
        l0 = l0 * cf0 + rs0; l1 = l1 * cf1 + rs1;
        #pragma unroll
        for (int nt = 0; nt < 8; nt++) {
            acc[nt][0] *= cf0; acc[nt][1] *= cf0;
            acc[nt][2] *= cf1; acc[nt][3] *= cf1;
        }

        // ---- P fragments in registers ----
        unsigned aP[4][4];
        #pragma unroll
        for (int j = 0; j < 4; j++) {
            aP[j][0] = pack2(s[2*j][0],   s[2*j][1]);
            aP[j][1] = pack2(s[2*j][2],   s[2*j][3]);
            aP[j][2] = pack2(s[2*j+1][0], s[2*j+1][1]);
            aP[j][3] = pack2(s[2*j+1][2], s[2*j+1][3]);
        }

        // ---- acc += P V ----
        #pragma unroll
        for (int j = 0; j < 4; j++) {
            #pragma unroll
            for (int njp = 0; njp < 4; njp++) {
                int row = 16 * j + (sel & 1) * 8 + r8;
                int c = njp * 2 + (sel >> 1);
                uint32_t addr = Vb + (uint32_t)(row * 128 + ((c ^ (row & 7)) * 16));
                unsigned bf0, bf1, bf2, bf3;
                asm volatile(
                    "ldmatrix.sync.aligned.m8n8.x4.trans.shared.b16 {%0,%1,%2,%3}, [%4];"
                    : "=r"(bf0), "=r"(bf1), "=r"(bf2), "=r"(bf3) : "r"(addr));
                mma16(acc[njp * 2],     aP[j], bf0, bf1);
                mma16(acc[njp * 2 + 1], aP[j], bf2, bf3);
            }
        }
    }

    const float inv0 = 1.0f / l0, inv1 = 1.0f / l1;
    __half* orow0 = O + (size_t)(b * SEQ + qr) * DMODEL + h * HD;
    __half* orow8 = orow0 + (size_t)8 * DMODEL;
    #pragma unroll
    for (int nt = 0; nt < 8; nt++) {
        int col = nt * 8 + 2 * c4;
        *(__half2*)(orow0 + col) = __floats2half2_rn(acc[nt][0] * inv0, acc[nt][1] * inv0);
        *(__half2*)(orow8 + col) = __floats2half2_rn(acc[nt][2] * inv1, acc[nt][3] * inv1);
    }
}

// ---------------- launch ----------------
extern "C" void kernel_launch(void* const* d_in, const int* in_sizes, int n_in,
                              void* d_out, int out_size) {
    const float* x     = (const float*)d_in[0];
    const float* ln1_g = (const float*)d_in[1];
    const float* ln1_b = (const float*)d_in[2];
    const float* ln2_g = (const float*)d_in[3];
    const float* ln2_b = (const float*)d_in[4];
    const float* wq    = (const float*)d_in[5];
    const float* bq    = (const float*)d_in[6];
    const float* wk    = (const float*)d_in[7];
    const float* bk    = (const float*)d_in[8];
    const float* wv    = (const float*)d_in[9];
    const float* bv    = (const float*)d_in[10];
    const float* wp    = (const float*)d_in[11];
    const float* bp    = (const float*)d_in[12];
    const float* ln3_g = (const float*)d_in[13];
    const float* ln3_b = (const float*)d_in[14];
    const float* w1    = (const float*)d_in[15];
    const float* b1    = (const float*)d_in[16];
    const float* w2    = (const float*)d_in[17];
    const float* b2    = (const float*)d_in[18];
    float* out = (float*)d_out;

    float *y1, *bqkv;
    __half *xnh, *qkvh, *ctxh, *ffh, *wqkvT, *wpT, *w1T, *w2T;
    cudaGetSymbolAddress((void**)&y1,    g_y1);
    cudaGetSymbolAddress((void**)&bqkv,  g_bqkv);
    cudaGetSymbolAddress((void**)&xnh,   g_xnh);
    cudaGetSymbolAddress((void**)&qkvh,  g_qkvh);
    cudaGetSymbolAddress((void**)&ctxh,  g_ctxh);
    cudaGetSymbolAddress((void**)&ffh,   g_ffh);
    cudaGetSymbolAddress((void**)&wqkvT, g_wqkvT);
    cudaGetSymbolAddress((void**)&wpT,   g_wpT);
    cudaGetSymbolAddress((void**)&w1T,   g_w1T);
    cudaGetSymbolAddress((void**)&w2T,   g_w2T);

    // 0. weight prep (fp16 transposed); qkv weights concatenated
    dim3 tblk(32, 8);
    cvt_transpose_kernel<<<dim3(DMODEL/32, DMODEL/32), tblk>>>(wq, wqkvT, DMODEL, DMODEL);
    cvt_transpose_kernel<<<dim3(DMODEL/32, DMODEL/32), tblk>>>(wk, wqkvT + DMODEL*DMODEL, DMODEL, DMODEL);
    cvt_transpose_kernel<<<dim3(DMODEL/32, DMODEL/32), tblk>>>(wv, wqkvT + 2*DMODEL*DMODEL, DMODEL, DMODEL);
    cvt_transpose_kernel<<<dim3(DMODEL/32, DMODEL/32), tblk>>>(wp, wpT, DMODEL, DMODEL);
    cvt_transpose_kernel<<<dim3(DMODEL/32, FFDIM/32),  tblk>>>(w1, w1T, DMODEL, FFDIM);
    cvt_transpose_kernel<<<dim3(FFDIM/32,  DMODEL/32), tblk>>>(w2, w2T, FFDIM, DMODEL);
    cat_bias_kernel<<<4, 256>>>(bq, bk, bv, bqkv);

    // 1. double pre-norm -> fp16
    ln_double_kernel<<<MROWS, 256>>>(x, ln1_g, ln1_b, ln2_g, ln2_b, xnh);

    // 2. fused QKV projection (fp16 out, N=3072)
    gemm_f16_kernel<<<dim3(3*DMODEL/128, MROWS/128), 256>>>(
        xnh, wqkvT, bqkv, nullptr, nullptr, qkvh, MROWS, 3*DMODEL, DMODEL, 0);

    // 3. fp16 flash attention -> fp16 ctx (128 q rows / CTA)
    attn_f16_kernel<<<dim3(BATCH * NHEAD, SEQ / 128), 256>>>(qkvh, ctxh);

    // 4. output projection + residual (fp32 out)
    dim3 gdd(DMODEL / 128, MROWS / 128);
    gemm_f16_kernel<<<gdd, 256>>>(ctxh, wpT, bp, x, y1, nullptr, MROWS, DMODEL, DMODEL, 0);

    // 5. ffn pre-norm -> fp16
    ln_single_kernel<<<MROWS, 256>>>(y1, ln3_g, ln3_b, xnh);

    // 6. FFN: w1 (+gelu, fp16 out), w2 (+residual, fp32 out -> d_out)
    gemm_f16_kernel<<<dim3(FFDIM / 128, MROWS / 128), 256>>>(
        xnh, w1T, b1, nullptr, nullptr, ffh, MROWS, FFDIM, DMODEL, 1);
    gemm_f16_kernel<<<gdd, 256>>>(ffh, w2T, b2, y1, out, nullptr, MROWS, DMODEL, FFDIM, 0);
}

// round 9
// speedup vs baseline: 2.8129x; 1.1153x over previous
#include <cuda_runtime.h>
#include <cuda_fp16.h>
#include <math.h>
#include <stdint.h>

// Shapes (fixed by the problem)
#define BATCH 8
#define SEQ   1024
#define DMODEL 1024
#define NHEAD 16
#define HD    64
#define FFDIM 4096
#define MROWS (BATCH*SEQ)   // 8192

// ---------------- scratch (device globals; no allocation allowed) ----------
__device__ float g_y1 [MROWS*DMODEL];

__device__ __half g_xnh [MROWS*DMODEL];
__device__ __half g_qkvh[MROWS*3*DMODEL];     // [token][3072]: q|k|v
__device__ __half g_ctxh[MROWS*DMODEL];
__device__ __half g_ffh [MROWS*FFDIM];

__device__ __half g_wqkvT[3*DMODEL*DMODEL];   // [3072][1024]
__device__ __half g_wpT[DMODEL*DMODEL];
__device__ __half g_w1T[DMODEL*FFDIM];
__device__ __half g_w2T[FFDIM*DMODEL];
__device__ float  g_bqkv[3*DMODEL];

// ---------------- common helpers ----------------
__device__ __forceinline__ void mma16(float acc[4], const unsigned a[4],
                                      unsigned b0, unsigned b1) {
    asm volatile(
        "mma.sync.aligned.m16n8k16.row.col.f32.f16.f16.f32 "
        "{%0,%1,%2,%3}, {%4,%5,%6,%7}, {%8,%9}, {%0,%1,%2,%3};\n"
        : "+f"(acc[0]), "+f"(acc[1]), "+f"(acc[2]), "+f"(acc[3])
        : "r"(a[0]), "r"(a[1]), "r"(a[2]), "r"(a[3]), "r"(b0), "r"(b1));
}

__device__ __forceinline__ uint32_t smem_u32(const void* p) {
    uint32_t a;
    asm("{ .reg .u64 t; cvta.to.shared.u64 t, %1; cvt.u32.u64 %0, t; }"
        : "=r"(a) : "l"(p));
    return a;
}

#define CP_ASYNC16(dst, src) \
    asm volatile("cp.async.cg.shared.global [%0], [%1], 16;" :: "r"(dst), "l"(src))
#define CP_COMMIT()   asm volatile("cp.async.commit_group;" ::: "memory")
#define CP_WAIT(n)    asm volatile("cp.async.wait_group %0;" :: "n"(n) : "memory")

__device__ __forceinline__ unsigned pack2(float a, float b) {
    __half2 h = __floats2half2_rn(a, b);
    return *(unsigned*)&h;
}

__device__ __forceinline__ float block_sum(float v) {
    __shared__ float sh[32];
    int tid = threadIdx.x;
    #pragma unroll
    for (int o = 16; o; o >>= 1) v += __shfl_xor_sync(0xffffffffu, v, o);
    __syncthreads();
    if ((tid & 31) == 0) sh[tid >> 5] = v;
    __syncthreads();
    if (tid < 32) {
        float t = (tid < (int)(blockDim.x >> 5)) ? sh[tid] : 0.f;
        #pragma unroll
        for (int o = 4; o; o >>= 1) t += __shfl_xor_sync(0xffffffffu, t, o);
        if (tid == 0) sh[0] = t;
    }
    __syncthreads();
    return sh[0];
}

// ---------------- merged weight convert+transpose (one launch) ---------------
// tile id ranges: [0,1024) wq, [1024,2048) wk, [2048,3072) wv, [3072,4096) wp,
// [4096,8192) w1 (K=1024,N=4096, 32x128 tiles), [8192,12288) w2 (K=4096,N=1024).
__global__ void cvt_all_kernel(const float* __restrict__ wq, const float* __restrict__ wk,
                               const float* __restrict__ wv, const float* __restrict__ wp,
                               const float* __restrict__ w1, const float* __restrict__ w2,
                               __half* __restrict__ wqkvT, __half* __restrict__ wpT,
                               __half* __restrict__ w1T,   __half* __restrict__ w2T) {
    __shared__ float t[32][33];
    int id = blockIdx.x;
    const float* W; __half* Wt; int K, N, local;
    if (id < 4096) {
        K = DMODEL; N = DMODEL; local = id & 1023;
        int sel = id >> 10;
        if (sel == 0)      { W = wq; Wt = wqkvT; }
        else if (sel == 1) { W = wk; Wt = wqkvT + DMODEL*DMODEL; }
        else if (sel == 2) { W = wv; Wt = wqkvT + 2*DMODEL*DMODEL; }
        else               { W = wp; Wt = wpT; }
    } else if (id < 8192) {
        K = DMODEL; N = FFDIM; local = id - 4096; W = w1; Wt = w1T;
    } else {
        K = FFDIM; N = DMODEL; local = id - 8192; W = w2; Wt = w2T;
    }
    int gx = K >> 5;                       // tiles along K
    int bk = (local % gx) * 32, bn = (local / gx) * 32;
    int tx = threadIdx.x, ty = threadIdx.y;   // (32, 8)
    #pragma unroll
    for (int i = 0; i < 4; i++)
        t[ty + i * 8][tx] = W[(size_t)(bk + ty + i * 8) * N + bn + tx];
    __syncthreads();
    #pragma unroll
    for (int i = 0; i < 4; i++)
        Wt[(size_t)(bn + ty + i * 8) * K + bk + tx] = __float2half(t[tx][ty + i * 8]);
}

__global__ void cat_bias_kernel(const float* __restrict__ bq,
                                const float* __restrict__ bk,
                                const float* __restrict__ bv,
                                float* __restrict__ out) {
    int i = blockIdx.x * 256 + threadIdx.x;
    if (i < DMODEL) {
        out[i] = bq[i];
        out[DMODEL + i] = bk[i];
        out[2 * DMODEL + i] = bv[i];
    }
}

// ---------------- LayerNorm kernels (write fp16) -----------------------------
__global__ void ln_double_kernel(const float* __restrict__ X,
                                 const float* __restrict__ g1, const float* __restrict__ b1,
                                 const float* __restrict__ g2, const float* __restrict__ b2,
                                 __half* __restrict__ Y) {
    int row = blockIdx.x, tid = threadIdx.x;
    float4 v = ((const float4*)X)[(size_t)row * 256 + tid];
    float mu = block_sum(v.x + v.y + v.z + v.w) * (1.0f / 1024.0f);
    float d0 = v.x - mu, d1 = v.y - mu, d2 = v.z - mu, d3 = v.w - mu;
    float var = block_sum(d0*d0 + d1*d1 + d2*d2 + d3*d3) * (1.0f / 1024.0f);
    float inv = rsqrtf(var + 1e-6f);
    float4 G = ((const float4*)g1)[tid], Bv = ((const float4*)b1)[tid];
    float y0 = d0*inv*G.x + Bv.x, y1 = d1*inv*G.y + Bv.y;
    float y2 = d2*inv*G.z + Bv.z, y3 = d3*inv*G.w + Bv.w;
    float mu2 = block_sum(y0 + y1 + y2 + y3) * (1.0f / 1024.0f);
    float e0 = y0 - mu2, e1 = y1 - mu2, e2 = y2 - mu2, e3 = y3 - mu2;
    float var2 = block_sum(e0*e0 + e1*e1 + e2*e2 + e3*e3) * (1.0f / 1024.0f);
    float inv2 = rsqrtf(var2 + 1e-6f);
    float4 G2 = ((const float4*)g2)[tid], B2 = ((const float4*)b2)[tid];
    __half2 h0 = __floats2half2_rn(e0*inv2*G2.x + B2.x, e1*inv2*G2.y + B2.y);
    __half2 h1 = __floats2half2_rn(e2*inv2*G2.z + B2.z, e3*inv2*G2.w + B2.w);
    ((__half2*)Y)[(size_t)row * 512 + tid * 2]     = h0;
    ((__half2*)Y)[(size_t)row * 512 + tid * 2 + 1] = h1;
}

__global__ void ln_single_kernel(const float* __restrict__ X,
                                 const float* __restrict__ g, const float* __restrict__ b,
                                 __half* __restrict__ Y) {
    int row = blockIdx.x, tid = threadIdx.x;
    float4 v = ((const float4*)X)[(size_t)row * 256 + tid];
    float mu = block_sum(v.x + v.y + v.z + v.w) * (1.0f / 1024.0f);
    float d0 = v.x - mu, d1 = v.y - mu, d2 = v.z - mu, d3 = v.w - mu;
    float var = block_sum(d0*d0 + d1*d1 + d2*d2 + d3*d3) * (1.0f / 1024.0f);
    float inv = rsqrtf(var + 1e-6f);
    float4 G = ((const float4*)g)[tid], Bv = ((const float4*)b)[tid];
    __half2 h0 = __floats2half2_rn(d0*inv*G.x + Bv.x, d1*inv*G.y + Bv.y);
    __half2 h1 = __floats2half2_rn(d2*inv*G.z + Bv.z, d3*inv*G.w + Bv.w);
    ((__half2*)Y)[(size_t)row * 512 + tid * 2]     = h0;
    ((__half2*)Y)[(size_t)row * 512 + tid * 2 + 1] = h1;
}

// ---------------- FP16 cp.async GEMM: BK=64, 3 stages, dynamic smem ----------
// C[M,N] = A[M,K] @ Wt[N,K]^T + bias (+gelu) (+res). BM=128, BN=128, BK=64.
// smem per stage: A 16KB + B 16KB = 32KB; 3 stages = 96KB (dynamic).
// Tile rows = 64 halfs = 128B = 8 x 16B chunks; swizzle chunk ^= row&7
// (same layout proven in attention since round 7). One barrier per 64-K chunk.
#define GSTG 32768

__global__ __launch_bounds__(256, 2) void gemm_f16_kernel(
    const __half* __restrict__ A, const __half* __restrict__ Wt,
    const float* __restrict__ bias, const float* __restrict__ res,
    float* __restrict__ C, __half* __restrict__ Ch,
    int M, int N, int K, int act)
{
    extern __shared__ __align__(128) char gsm[];
    const uint32_t sb = smem_u32(gsm);
    const int tid = threadIdx.x, lane = tid & 31, warp = tid >> 5;
    const int m0 = blockIdx.y * 128, n0 = blockIdx.x * 128;
    const int wm = (warp >> 2) * 64, wn = (warp & 3) * 32;

    // staging: each tensor tile = 128 rows x 8 chunks (16B). thread t -> rows
    // sr+32i (i=0..3), chunk col = t&7. swizzled dst differs by 4096 per i.
    const int sr = tid >> 3, scol = tid & 7;
    const uint32_t dstA0 = (uint32_t)(sr * 128 + ((scol ^ (sr & 7)) * 16));
    const __half* Abase = A  + (size_t)(m0 + sr) * K + scol * 8;
    const __half* Bbase = Wt + (size_t)(n0 + sr) * K + scol * 8;

    // ldmatrix addressing (row*128 bytes, swizzle key row&7)
    const int r8 = lane & 7, sel = lane >> 3;
    uint32_t a_row[4]; int a_key[4];
    #pragma unroll
    for (int mi = 0; mi < 4; mi++) {
        int r = wm + mi * 16 + (sel & 1) * 8 + r8;
        a_row[mi] = r * 128;
        a_key[mi] = r & 7;
    }
    const int a_hi = sel >> 1;
    uint32_t b_row[2]; int b_key[2];
    #pragma unroll
    for (int nj = 0; nj < 2; nj++) {
        int r = wn + (nj * 2 + (sel >> 1)) * 8 + r8;
        b_row[nj] = (uint32_t)(16384 + r * 128);
        b_key[nj] = r & 7;
    }
    const int b_hi = sel & 1;

    float acc[4][4][4] = {};

    auto issue = [&](int s, int kc) {
        const uint32_t st = sb + s * GSTG;
        const int ko = kc * 64;
        #pragma unroll
        for (int i = 0; i < 4; i++) {
            CP_ASYNC16(st + dstA0 + i * 4096, Abase + (size_t)i * 32 * K + ko);
            CP_ASYNC16(st + 16384 + dstA0 + i * 4096, Bbase + (size_t)i * 32 * K + ko);
        }
        CP_COMMIT();
    };

    const int NC = K >> 6;
    issue(0, 0);
    if (NC > 1) issue(1, 1);

    for (int kc = 0; kc < NC; kc++) {
        const int cur = kc % 3;
        if (kc + 1 < NC) CP_WAIT(1); else CP_WAIT(0);
        __syncthreads();                         // readers of stage (kc+2)%3 done
        if (kc + 2 < NC) issue((kc + 2) % 3, kc + 2);

        const uint32_t stb = sb + cur * GSTG;
        #pragma unroll
        for (int ks = 0; ks < 4; ks++) {
            unsigned af[4][4], bf[4][2];
            #pragma unroll
            for (int mi = 0; mi < 4; mi++) {
                uint32_t addr = stb + a_row[mi]
                              + (uint32_t)(((ks * 2 + a_hi) ^ a_key[mi]) * 16);
                asm volatile(
                    "ldmatrix.sync.aligned.m8n8.x4.shared.b16 {%0,%1,%2,%3}, [%4];"
                    : "=r"(af[mi][0]), "=r"(af[mi][1]), "=r"(af[mi][2]), "=r"(af[mi][3])
                    : "r"(addr));
            }
            #pragma unroll
            for (int nj = 0; nj < 2; nj++) {
                uint32_t addr = stb + b_row[nj]
                              + (uint32_t)(((ks * 2 + b_hi) ^ b_key[nj]) * 16);
                asm volatile(
                    "ldmatrix.sync.aligned.m8n8.x4.shared.b16 {%0,%1,%2,%3}, [%4];"
                    : "=r"(bf[nj*2][0]), "=r"(bf[nj*2][1]),
                      "=r"(bf[nj*2+1][0]), "=r"(bf[nj*2+1][1])
                    : "r"(addr));
            }
            #pragma unroll
            for (int mi = 0; mi < 4; mi++)
                #pragma unroll
                for (int ni = 0; ni < 4; ni++)
                    mma16(acc[mi][ni], af[mi], bf[ni][0], bf[ni][1]);
        }
    }

    const int g = lane >> 2, c4 = lane & 3;
    #pragma unroll
    for (int mi = 0; mi < 4; mi++) {
        #pragma unroll
        for (int ni = 0; ni < 4; ni++) {
            int gn = n0 + wn + ni * 8 + c4 * 2;
            float bv0 = bias[gn], bv1 = bias[gn + 1];
            #pragma unroll
            for (int half_ = 0; half_ < 2; half_++) {
                int gr = m0 + wm + mi * 16 + g + half_ * 8;
                float v0 = acc[mi][ni][half_ * 2 + 0] + bv0;
                float v1 = acc[mi][ni][half_ * 2 + 1] + bv1;
                if (act) {
                    v0 = 0.5f * v0 * (1.0f + erff(v0 * 0.70710678118654752f));
                    v1 = 0.5f * v1 * (1.0f + erff(v1 * 0.70710678118654752f));
                }
                size_t o = (size_t)gr * N + gn;
                if (res) { v0 += res[o]; v1 += res[o + 1]; }
                if (Ch) {
                    *(__half2*)(Ch + o) = __floats2half2_rn(v0, v1);
                } else {
                    C[o] = v0; C[o + 1] = v1;
                }
            }
        }
    }
}

// ---------------- FP16 flash attention (128 q rows per CTA; proven R8) -------
#define ATT_STG 16384            // K 8KB + V 8KB per stage
#define QKV_LD  (3 * DMODEL)

__global__ __launch_bounds__(256) void attn_f16_kernel(
    const __half* __restrict__ QKV, __half* __restrict__ O) {
    __shared__ __align__(128) char smb[2 * ATT_STG];
    const uint32_t sb = smem_u32(smb);
    const int tid = threadIdx.x, lane = tid & 31, warp = tid >> 5;
    const int g = lane >> 2, c4 = lane & 3;
    const int bh = blockIdx.x, qt = blockIdx.y;
    const int b = bh >> 4, h = bh & 15;

    unsigned aQ[4][4];
    const int qr = qt * 128 + warp * 16 + g;
    {
        const __half2 sc = __floats2half2_rn(0.125f, 0.125f);
        const __half* q0 = QKV + (size_t)(b * SEQ + qr) * QKV_LD + h * HD;
        const __half* q8 = q0 + (size_t)8 * QKV_LD;
        #pragma unroll
        for (int j = 0; j < 4; j++) {
            __half2 t;
            t = __hmul2(*(const __half2*)(q0 + j * 16 + 2 * c4), sc);     aQ[j][0] = *(unsigned*)&t;
            t = __hmul2(*(const __half2*)(q8 + j * 16 + 2 * c4), sc);     aQ[j][1] = *(unsigned*)&t;
            t = __hmul2(*(const __half2*)(q0 + j * 16 + 8 + 2 * c4), sc); aQ[j][2] = *(unsigned*)&t;
            t = __hmul2(*(const __half2*)(q8 + j * 16 + 8 + 2 * c4), sc); aQ[j][3] = *(unsigned*)&t;
        }
    }

    const int sr = tid >> 2, scg = (tid & 3) * 2;
    const __half* ksrc0 = QKV + (size_t)(b * SEQ + sr) * QKV_LD + DMODEL + h * HD;
    const __half* vsrc0 = ksrc0 + DMODEL;

    auto issue = [&](int s, int kt) {
        const uint32_t st = sb + s * ATT_STG;
        const size_t roff = (size_t)(kt * 64) * QKV_LD;
        #pragma unroll
        for (int j = 0; j < 2; j++) {
            int c = scg + j;
            uint32_t d = (uint32_t)(sr * 128 + ((c ^ (sr & 7)) * 16));
            CP_ASYNC16(st + d, ksrc0 + roff + c * 8);
            CP_ASYNC16(st + 8192 + d, vsrc0 + roff + c * 8);
        }
        CP_COMMIT();
    };

    float m0 = -INFINITY, m1 = -INFINITY, l0 = 0.f, l1 = 0.f;
    float acc[8][4] = {};

    const int sel = lane >> 3, r8 = lane & 7;

    issue(0, 0);
    const int NT = SEQ / 64;
    for (int kt = 0; kt < NT; kt++) {
        const int cur = kt & 1;
        CP_WAIT(0);
        __syncthreads();
        if (kt + 1 < NT) issue(cur ^ 1, kt + 1);

        const uint32_t Kb = sb + cur * ATT_STG;
        const uint32_t Vb = Kb + 8192;

        float s[8][4] = {};
        #pragma unroll
        for (int ks = 0; ks < 4; ks++) {
            #pragma unroll
            for (int njp = 0; njp < 4; njp++) {
                int row = (njp * 2 + (sel >> 1)) * 8 + r8;
                int c = ks * 2 + (sel & 1);
                uint32_t addr = Kb + (uint32_t)(row * 128 + ((c ^ (row & 7)) * 16));
                unsigned bf0, bf1, bf2, bf3;
                asm volatile(
                    "ldmatrix.sync.aligned.m8n8.x4.shared.b16 {%0,%1,%2,%3}, [%4];"
                    : "=r"(bf0), "=r"(bf1), "=r"(bf2), "=r"(bf3) : "r"(addr));
                mma16(s[njp * 2],     aQ[ks], bf0, bf1);
                mma16(s[njp * 2 + 1], aQ[ks], bf2, bf3);
            }
        }

        float tm0 = -INFINITY, tm1 = -INFINITY;
        #pragma unroll
        for (int nt = 0; nt < 8; nt++) {
            tm0 = fmaxf(tm0, fmaxf(s[nt][0], s[nt][1]));
            tm1 = fmaxf(tm1, fmaxf(s[nt][2], s[nt][3]));
        }
        tm0 = fmaxf(tm0, __shfl_xor_sync(0xffffffffu, tm0, 1));
        tm0 = fmaxf(tm0, __shfl_xor_sync(0xffffffffu, tm0, 2));
        tm1 = fmaxf(tm1, __shfl_xor_sync(0xffffffffu, tm1, 1));
        tm1 = fmaxf(tm1, __shfl_xor_sync(0xffffffffu, tm1, 2));
        float mn0 = fmaxf(m0, tm0), mn1 = fmaxf(m1, tm1);
        float cf0 = __expf(m0 - mn0), cf1 = __expf(m1 - mn1);
        m0 = mn0; m1 = mn1;

        float rs0 = 0.f, rs1 = 0.f;
        #pragma unroll
        for (int nt = 0; nt < 8; nt++) {
            s[nt][0] = __expf(s[nt][0] - m0);
            s[nt][1] = __expf(s[nt][1] - m0);
            s[nt][2] = __expf(s[nt][2] - m1);
            s[nt][3] = __expf(s[nt][3] - m1);
            rs0 += s[nt][0] + s[nt][1];
            rs1 += s[nt][2] + s[nt][3];
        }
        rs0 += __shfl_xor_sync(0xffffffffu, rs0, 1);
        rs0 += __shfl_xor_sync(0xffffffffu, rs0, 2);
        rs1 += __shfl_xor_sync(0xffffffffu, rs1, 1);
        rs1 += __shfl_xor_sync(0xffffffffu, rs1, 2);
        l0 = l0 * cf0 + rs0; l1 = l1 * cf1 + rs1;
        #pragma unroll
        for (int nt = 0; nt < 8; nt++) {
            acc[nt][0] *= cf0; acc[nt][1] *= cf0;
            acc[nt][2] *= cf1; acc[nt][3] *= cf1;
        }

        unsigned aP[4][4];
        #pragma unroll
        for (int j = 0; j < 4; j++) {
            aP[j][0] = pack2(s[2*j][0],   s[2*j][1]);
            aP[j][1] = pack2(s[2*j][2],   s[2*j][3]);
            aP[j][2] = pack2(s[2*j+1][0], s[2*j+1][1]);
            aP[j][3] = pack2(s[2*j+1][2], s[2*j+1][3]);
        }

        #pragma unroll
        for (int j = 0; j < 4; j++) {
            #pragma unroll
            for (int njp = 0; njp < 4; njp++) {
                int row = 16 * j + (sel & 1) * 8 + r8;
                int c = njp * 2 + (sel >> 1);
                uint32_t addr = Vb + (uint32_t)(row * 128 + ((c ^ (row & 7)) * 16));
                unsigned bf0, bf1, bf2, bf3;
                asm volatile(
                    "ldmatrix.sync.aligned.m8n8.x4.trans.shared.b16 {%0,%1,%2,%3}, [%4];"
                    : "=r"(bf0), "=r"(bf1), "=r"(bf2), "=r"(bf3) : "r"(addr));
                mma16(acc[njp * 2],     aP[j], bf0, bf1);
                mma16(acc[njp * 2 + 1], aP[j], bf2, bf3);
            }
        }
    }

    const float inv0 = 1.0f / l0, inv1 = 1.0f / l1;
    __half* orow0 = O + (size_t)(b * SEQ + qr) * DMODEL + h * HD;
    __half* orow8 = orow0 + (size_t)8 * DMODEL;
    #pragma unroll
    for (int nt = 0; nt < 8; nt++) {
        int col = nt * 8 + 2 * c4;
        *(__half2*)(orow0 + col) = __floats2half2_rn(acc[nt][0] * inv0, acc[nt][1] * inv0);
        *(__half2*)(orow8 + col) = __floats2half2_rn(acc[nt][2] * inv1, acc[nt][3] * inv1);
    }
}

// ---------------- launch ----------------
extern "C" void kernel_launch(void* const* d_in, const int* in_sizes, int n_in,
                              void* d_out, int out_size) {
    const float* x     = (const float*)d_in[0];
    const float* ln1_g = (const float*)d_in[1];
    const float* ln1_b = (const float*)d_in[2];
    const float* ln2_g = (const float*)d_in[3];
    const float* ln2_b = (const float*)d_in[4];
    const float* wq    = (const float*)d_in[5];
    const float* bq    = (const float*)d_in[6];
    const float* wk    = (const float*)d_in[7];
    const float* bk    = (const float*)d_in[8];
    const float* wv    = (const float*)d_in[9];
    const float* bv    = (const float*)d_in[10];
    const float* wp    = (const float*)d_in[11];
    const float* bp    = (const float*)d_in[12];
    const float* ln3_g = (const float*)d_in[13];
    const float* ln3_b = (const float*)d_in[14];
    const float* w1    = (const float*)d_in[15];
    const float* b1    = (const float*)d_in[16];
    const float* w2    = (const float*)d_in[17];
    const float* b2    = (const float*)d_in[18];
    float* out = (float*)d_out;

    float *y1, *bqkv;
    __half *xnh, *qkvh, *ctxh, *ffh, *wqkvT, *wpT, *w1T, *w2T;
    cudaGetSymbolAddress((void**)&y1,    g_y1);
    cudaGetSymbolAddress((void**)&bqkv,  g_bqkv);
    cudaGetSymbolAddress((void**)&xnh,   g_xnh);
    cudaGetSymbolAddress((void**)&qkvh,  g_qkvh);
    cudaGetSymbolAddress((void**)&ctxh,  g_ctxh);
    cudaGetSymbolAddress((void**)&ffh,   g_ffh);
    cudaGetSymbolAddress((void**)&wqkvT, g_wqkvT);
    cudaGetSymbolAddress((void**)&wpT,   g_wpT);
    cudaGetSymbolAddress((void**)&w1T,   g_w1T);
    cudaGetSymbolAddress((void**)&w2T,   g_w2T);

    cudaFuncSetAttribute(gemm_f16_kernel,
                         cudaFuncAttributeMaxDynamicSharedMemorySize, 3 * GSTG);

    // 0. weight prep: one merged transpose launch + bias concat
    cvt_all_kernel<<<12288, dim3(32, 8)>>>(wq, wk, wv, wp, w1, w2,
                                           wqkvT, wpT, w1T, w2T);
    cat_bias_kernel<<<4, 256>>>(bq, bk, bv, bqkv);

    // 1. double pre-norm -> fp16
    ln_double_kernel<<<MROWS, 256>>>(x, ln1_g, ln1_b, ln2_g, ln2_b, xnh);

    // 2. fused QKV projection (fp16 out, N=3072)
    gemm_f16_kernel<<<dim3(3*DMODEL/128, MROWS/128), 256, 3*GSTG>>>(
        xnh, wqkvT, bqkv, nullptr, nullptr, qkvh, MROWS, 3*DMODEL, DMODEL, 0);

    // 3. fp16 flash attention -> fp16 ctx (128 q rows / CTA)
    attn_f16_kernel<<<dim3(BATCH * NHEAD, SEQ / 128), 256>>>(qkvh, ctxh);

    // 4. output projection + residual (fp32 out)
    dim3 gdd(DMODEL / 128, MROWS / 128);
    gemm_f16_kernel<<<gdd, 256, 3*GSTG>>>(ctxh, wpT, bp, x, y1, nullptr,
                                          MROWS, DMODEL, DMODEL, 0);

    // 5. ffn pre-norm -> fp16
    ln_single_kernel<<<MROWS, 256>>>(y1, ln3_g, ln3_b, xnh);

    // 6. FFN: w1 (+gelu, fp16 out), w2 (+residual, fp32 out -> d_out)
    gemm_f16_kernel<<<dim3(FFDIM / 128, MROWS / 128), 256, 3*GSTG>>>(
        xnh, w1T, b1, nullptr, nullptr, ffh, MROWS, FFDIM, DMODEL, 1);
    gemm_f16_kernel<<<gdd, 256, 3*GSTG>>>(ffh, w2T, b2, y1, out, nullptr,
                                          MROWS, DMODEL, FFDIM, 0);
}

// round 10
// speedup vs baseline: 2.8425x; 1.0105x over previous
#include <cuda_runtime.h>
#include <cuda_fp16.h>
#include <math.h>
#include <stdint.h>

// Shapes (fixed by the problem)
#define BATCH 8
#define SEQ   1024
#define DMODEL 1024
#define NHEAD 16
#define HD    64
#define FFDIM 4096
#define MROWS (BATCH*SEQ)   // 8192

// ---------------- scratch (device globals; no allocation allowed) ----------
__device__ float g_y1 [MROWS*DMODEL];

__device__ __half g_xnh [MROWS*DMODEL];
__device__ __half g_qkvh[MROWS*3*DMODEL];     // [token][3072]: q|k|v
__device__ __half g_ctxh[MROWS*DMODEL];
__device__ __half g_ffh [MROWS*FFDIM];

__device__ __half g_wqkvT[3*DMODEL*DMODEL];   // [3072][1024]
__device__ __half g_wpT[DMODEL*DMODEL];
__device__ __half g_w1T[DMODEL*FFDIM];
__device__ __half g_w2T[FFDIM*DMODEL];
__device__ float  g_bqkv[3*DMODEL];

// ---------------- common helpers ----------------
__device__ __forceinline__ void mma16(float acc[4], const unsigned a[4],
                                      unsigned b0, unsigned b1) {
    asm volatile(
        "mma.sync.aligned.m16n8k16.row.col.f32.f16.f16.f32 "
        "{%0,%1,%2,%3}, {%4,%5,%6,%7}, {%8,%9}, {%0,%1,%2,%3};\n"
        : "+f"(acc[0]), "+f"(acc[1]), "+f"(acc[2]), "+f"(acc[3])
        : "r"(a[0]), "r"(a[1]), "r"(a[2]), "r"(a[3]), "r"(b0), "r"(b1));
}

__device__ __forceinline__ uint32_t smem_u32(const void* p) {
    uint32_t a;
    asm("{ .reg .u64 t; cvta.to.shared.u64 t, %1; cvt.u32.u64 %0, t; }"
        : "=r"(a) : "l"(p));
    return a;
}

#define CP_ASYNC16(dst, src) \
    asm volatile("cp.async.cg.shared.global [%0], [%1], 16;" :: "r"(dst), "l"(src))
#define CP_COMMIT()   asm volatile("cp.async.commit_group;" ::: "memory")
#define CP_WAIT(n)    asm volatile("cp.async.wait_group %0;" :: "n"(n) : "memory")

__device__ __forceinline__ unsigned pack2(float a, float b) {
    __half2 h = __floats2half2_rn(a, b);
    return *(unsigned*)&h;
}

__device__ __forceinline__ float warp_sum(float v) {
    #pragma unroll
    for (int o = 16; o; o >>= 1) v += __shfl_xor_sync(0xffffffffu, v, o);
    return v;
}

// ---------------- merged weight convert+transpose + bias concat --------------
// tile id ranges: [0,1024) wq, [1024,2048) wk, [2048,3072) wv, [3072,4096) wp,
// [4096,8192) w1, [8192,12288) w2, [12288,12292) bias concat.
__global__ void cvt_all_kernel(const float* __restrict__ wq, const float* __restrict__ wk,
                               const float* __restrict__ wv, const float* __restrict__ wp,
                               const float* __restrict__ w1, const float* __restrict__ w2,
                               const float* __restrict__ bq, const float* __restrict__ bk,
                               const float* __restrict__ bv,
                               __half* __restrict__ wqkvT, __half* __restrict__ wpT,
                               __half* __restrict__ w1T,   __half* __restrict__ w2T,
                               float* __restrict__ bqkv) {
    int id = blockIdx.x;
    if (id >= 12288) {
        int i = (id - 12288) * 256 + threadIdx.y * 32 + threadIdx.x;
        if (i < DMODEL) {
            bqkv[i] = bq[i];
            bqkv[DMODEL + i] = bk[i];
            bqkv[2 * DMODEL + i] = bv[i];
        }
        return;
    }
    __shared__ float t[32][33];
    const float* W; __half* Wt; int K, N, local;
    if (id < 4096) {
        K = DMODEL; N = DMODEL; local = id & 1023;
        int sel = id >> 10;
        if (sel == 0)      { W = wq; Wt = wqkvT; }
        else if (sel == 1) { W = wk; Wt = wqkvT + DMODEL*DMODEL; }
        else if (sel == 2) { W = wv; Wt = wqkvT + 2*DMODEL*DMODEL; }
        else               { W = wp; Wt = wpT; }
    } else if (id < 8192) {
        K = DMODEL; N = FFDIM; local = id - 4096; W = w1; Wt = w1T;
    } else {
        K = FFDIM; N = DMODEL; local = id - 8192; W = w2; Wt = w2T;
    }
    int gx = K >> 5;
    int bk_ = (local % gx) * 32, bn = (local / gx) * 32;
    int tx = threadIdx.x, ty = threadIdx.y;   // (32, 8)
    #pragma unroll
    for (int i = 0; i < 4; i++)
        t[ty + i * 8][tx] = W[(size_t)(bk_ + ty + i * 8) * N + bn + tx];
    __syncthreads();
    #pragma unroll
    for (int i = 0; i < 4; i++)
        Wt[(size_t)(bn + ty + i * 8) * K + bk_ + tx] = __float2half(t[tx][ty + i * 8]);
}

// ---------------- LayerNorm kernels: warp-per-row, shuffle-only --------------
__global__ __launch_bounds__(256) void ln_double_kernel(
    const float* __restrict__ X,
    const float* __restrict__ g1, const float* __restrict__ b1,
    const float* __restrict__ g2, const float* __restrict__ b2,
    __half* __restrict__ Y) {
    const int lane = threadIdx.x & 31, w = threadIdx.x >> 5;
    const int row = blockIdx.x * 8 + w;
    const float4* xr = (const float4*)X + (size_t)row * 256;
    float4 v[8];
    float s = 0.f;
    #pragma unroll
    for (int i = 0; i < 8; i++) {
        v[i] = xr[lane + 32 * i];
        s += v[i].x + v[i].y + v[i].z + v[i].w;
    }
    float mu = warp_sum(s) * (1.0f / 1024.0f);
    float vs = 0.f;
    #pragma unroll
    for (int i = 0; i < 8; i++) {
        v[i].x -= mu; v[i].y -= mu; v[i].z -= mu; v[i].w -= mu;
        vs += v[i].x*v[i].x + v[i].y*v[i].y + v[i].z*v[i].z + v[i].w*v[i].w;
    }
    float inv = rsqrtf(warp_sum(vs) * (1.0f / 1024.0f) + 1e-6f);
    // y = v*inv*G1 + B1
    float s2 = 0.f;
    #pragma unroll
    for (int i = 0; i < 8; i++) {
        float4 G = ((const float4*)g1)[lane + 32 * i];
        float4 B = ((const float4*)b1)[lane + 32 * i];
        v[i].x = v[i].x * inv * G.x + B.x;
        v[i].y = v[i].y * inv * G.y + B.y;
        v[i].z = v[i].z * inv * G.z + B.z;
        v[i].w = v[i].w * inv * G.w + B.w;
        s2 += v[i].x + v[i].y + v[i].z + v[i].w;
    }
    float mu2 = warp_sum(s2) * (1.0f / 1024.0f);
    float vs2 = 0.f;
    #pragma unroll
    for (int i = 0; i < 8; i++) {
        v[i].x -= mu2; v[i].y -= mu2; v[i].z -= mu2; v[i].w -= mu2;
        vs2 += v[i].x*v[i].x + v[i].y*v[i].y + v[i].z*v[i].z + v[i].w*v[i].w;
    }
    float inv2 = rsqrtf(warp_sum(vs2) * (1.0f / 1024.0f) + 1e-6f);
    __half2* yr = (__half2*)Y + (size_t)row * 512;
    #pragma unroll
    for (int i = 0; i < 8; i++) {
        float4 G = ((const float4*)g2)[lane + 32 * i];
        float4 B = ((const float4*)b2)[lane + 32 * i];
        yr[2 * (lane + 32 * i)]     = __floats2half2_rn(v[i].x * inv2 * G.x + B.x,
                                                        v[i].y * inv2 * G.y + B.y);
        yr[2 * (lane + 32 * i) + 1] = __floats2half2_rn(v[i].z * inv2 * G.z + B.z,
                                                        v[i].w * inv2 * G.w + B.w);
    }
}

__global__ __launch_bounds__(256) void ln_single_kernel(
    const float* __restrict__ X,
    const float* __restrict__ g, const float* __restrict__ b,
    __half* __restrict__ Y) {
    const int lane = threadIdx.x & 31, w = threadIdx.x >> 5;
    const int row = blockIdx.x * 8 + w;
    const float4* xr = (const float4*)X + (size_t)row * 256;
    float4 v[8];
    float s = 0.f;
    #pragma unroll
    for (int i = 0; i < 8; i++) {
        v[i] = xr[lane + 32 * i];
        s += v[i].x + v[i].y + v[i].z + v[i].w;
    }
    float mu = warp_sum(s) * (1.0f / 1024.0f);
    float vs = 0.f;
    #pragma unroll
    for (int i = 0; i < 8; i++) {
        v[i].x -= mu; v[i].y -= mu; v[i].z -= mu; v[i].w -= mu;
        vs += v[i].x*v[i].x + v[i].y*v[i].y + v[i].z*v[i].z + v[i].w*v[i].w;
    }
    float inv = rsqrtf(warp_sum(vs) * (1.0f / 1024.0f) + 1e-6f);
    __half2* yr = (__half2*)Y + (size_t)row * 512;
    #pragma unroll
    for (int i = 0; i < 8; i++) {
        float4 G = ((const float4*)g)[lane + 32 * i];
        float4 B = ((const float4*)b)[lane + 32 * i];
        yr[2 * (lane + 32 * i)]     = __floats2half2_rn(v[i].x * inv * G.x + B.x,
                                                        v[i].y * inv * G.y + B.y);
        yr[2 * (lane + 32 * i) + 1] = __floats2half2_rn(v[i].z * inv * G.z + B.z,
                                                        v[i].w * inv * G.w + B.w);
    }
}

// ---------------- FP16 cp.async GEMM: BK=64, 3 stages (proven R9) ------------
#define GSTG 32768

__global__ __launch_bounds__(256, 2) void gemm_f16_kernel(
    const __half* __restrict__ A, const __half* __restrict__ Wt,
    const float* __restrict__ bias, const float* __restrict__ res,
    float* __restrict__ C, __half* __restrict__ Ch,
    int M, int N, int K, int act)
{
    extern __shared__ __align__(128) char gsm[];
    const uint32_t sb = smem_u32(gsm);
    const int tid = threadIdx.x, lane = tid & 31, warp = tid >> 5;
    const int m0 = blockIdx.y * 128, n0 = blockIdx.x * 128;
    const int wm = (warp >> 2) * 64, wn = (warp & 3) * 32;

    const int sr = tid >> 3, scol = tid & 7;
    const uint32_t dstA0 = (uint32_t)(sr * 128 + ((scol ^ (sr & 7)) * 16));
    const __half* Abase = A  + (size_t)(m0 + sr) * K + scol * 8;
    const __half* Bbase = Wt + (size_t)(n0 + sr) * K + scol * 8;

    const int r8 = lane & 7, sel = lane >> 3;
    uint32_t a_row[4]; int a_key[4];
    #pragma unroll
    for (int mi = 0; mi < 4; mi++) {
        int r = wm + mi * 16 + (sel & 1) * 8 + r8;
        a_row[mi] = r * 128;
        a_key[mi] = r & 7;
    }
    const int a_hi = sel >> 1;
    uint32_t b_row[2]; int b_key[2];
    #pragma unroll
    for (int nj = 0; nj < 2; nj++) {
        int r = wn + (nj * 2 + (sel >> 1)) * 8 + r8;
        b_row[nj] = (uint32_t)(16384 + r * 128);
        b_key[nj] = r & 7;
    }
    const int b_hi = sel & 1;

    float acc[4][4][4] = {};

    auto issue = [&](int s, int kc) {
        const uint32_t st = sb + s * GSTG;
        const int ko = kc * 64;
        #pragma unroll
        for (int i = 0; i < 4; i++) {
            CP_ASYNC16(st + dstA0 + i * 4096, Abase + (size_t)i * 32 * K + ko);
            CP_ASYNC16(st + 16384 + dstA0 + i * 4096, Bbase + (size_t)i * 32 * K + ko);
        }
        CP_COMMIT();
    };

    const int NC = K >> 6;
    issue(0, 0);
    if (NC > 1) issue(1, 1);

    for (int kc = 0; kc < NC; kc++) {
        const int cur = kc % 3;
        if (kc + 1 < NC) CP_WAIT(1); else CP_WAIT(0);
        __syncthreads();
        if (kc + 2 < NC) issue((kc + 2) % 3, kc + 2);

        const uint32_t stb = sb + cur * GSTG;
        #pragma unroll
        for (int ks = 0; ks < 4; ks++) {
            unsigned af[4][4], bf[4][2];
            #pragma unroll
            for (int mi = 0; mi < 4; mi++) {
                uint32_t addr = stb + a_row[mi]
                              + (uint32_t)(((ks * 2 + a_hi) ^ a_key[mi]) * 16);
                asm volatile(
                    "ldmatrix.sync.aligned.m8n8.x4.shared.b16 {%0,%1,%2,%3}, [%4];"
                    : "=r"(af[mi][0]), "=r"(af[mi][1]), "=r"(af[mi][2]), "=r"(af[mi][3])
                    : "r"(addr));
            }
            #pragma unroll
            for (int nj = 0; nj < 2; nj++) {
                uint32_t addr = stb + b_row[nj]
                              + (uint32_t)(((ks * 2 + b_hi) ^ b_key[nj]) * 16);
                asm volatile(
                    "ldmatrix.sync.aligned.m8n8.x4.shared.b16 {%0,%1,%2,%3}, [%4];"
                    : "=r"(bf[nj*2][0]), "=r"(bf[nj*2][1]),
                      "=r"(bf[nj*2+1][0]), "=r"(bf[nj*2+1][1])
                    : "r"(addr));
            }
            #pragma unroll
            for (int mi = 0; mi < 4; mi++)
                #pragma unroll
                for (int ni = 0; ni < 4; ni++)
                    mma16(acc[mi][ni], af[mi], bf[ni][0], bf[ni][1]);
        }
    }

    const int g = lane >> 2, c4 = lane & 3;
    #pragma unroll
    for (int mi = 0; mi < 4; mi++) {
        #pragma unroll
        for (int ni = 0; ni < 4; ni++) {
            int gn = n0 + wn + ni * 8 + c4 * 2;
            float bv0 = bias[gn], bv1 = bias[gn + 1];
            #pragma unroll
            for (int half_ = 0; half_ < 2; half_++) {
                int gr = m0 + wm + mi * 16 + g + half_ * 8;
                float v0 = acc[mi][ni][half_ * 2 + 0] + bv0;
                float v1 = acc[mi][ni][half_ * 2 + 1] + bv1;
                if (act) {
                    v0 = 0.5f * v0 * (1.0f + erff(v0 * 0.70710678118654752f));
                    v1 = 0.5f * v1 * (1.0f + erff(v1 * 0.70710678118654752f));
                }
                size_t o = (size_t)gr * N + gn;
                if (res) { v0 += res[o]; v1 += res[o + 1]; }
                if (Ch) {
                    *(__half2*)(Ch + o) = __floats2half2_rn(v0, v1);
                } else {
                    C[o] = v0; C[o + 1] = v1;
                }
            }
        }
    }
}

// ---------------- FP16 flash attention: 128 q rows, 3-stage pipeline ---------
#define ATT_STG 16384            // K 8KB + V 8KB per stage; 3 stages = 48KB
#define QKV_LD  (3 * DMODEL)

__global__ __launch_bounds__(256) void attn_f16_kernel(
    const __half* __restrict__ QKV, __half* __restrict__ O) {
    __shared__ __align__(128) char smb[3 * ATT_STG];
    const uint32_t sb = smem_u32(smb);
    const int tid = threadIdx.x, lane = tid & 31, warp = tid >> 5;
    const int g = lane >> 2, c4 = lane & 3;
    const int bh = blockIdx.x, qt = blockIdx.y;
    const int b = bh >> 4, h = bh & 15;

    unsigned aQ[4][4];
    const int qr = qt * 128 + warp * 16 + g;
    {
        const __half2 sc = __floats2half2_rn(0.125f, 0.125f);
        const __half* q0 = QKV + (size_t)(b * SEQ + qr) * QKV_LD + h * HD;
        const __half* q8 = q0 + (size_t)8 * QKV_LD;
        #pragma unroll
        for (int j = 0; j < 4; j++) {
            __half2 t;
            t = __hmul2(*(const __half2*)(q0 + j * 16 + 2 * c4), sc);     aQ[j][0] = *(unsigned*)&t;
            t = __hmul2(*(const __half2*)(q8 + j * 16 + 2 * c4), sc);     aQ[j][1] = *(unsigned*)&t;
            t = __hmul2(*(const __half2*)(q0 + j * 16 + 8 + 2 * c4), sc); aQ[j][2] = *(unsigned*)&t;
            t = __hmul2(*(const __half2*)(q8 + j * 16 + 8 + 2 * c4), sc); aQ[j][3] = *(unsigned*)&t;
        }
    }

    const int sr = tid >> 2, scg = (tid & 3) * 2;
    const __half* ksrc0 = QKV + (size_t)(b * SEQ + sr) * QKV_LD + DMODEL + h * HD;
    const __half* vsrc0 = ksrc0 + DMODEL;

    auto issue = [&](int s, int kt) {
        const uint32_t st = sb + s * ATT_STG;
        const size_t roff = (size_t)(kt * 64) * QKV_LD;
        #pragma unroll
        for (int j = 0; j < 2; j++) {
            int c = scg + j;
            uint32_t d = (uint32_t)(sr * 128 + ((c ^ (sr & 7)) * 16));
            CP_ASYNC16(st + d, ksrc0 + roff + c * 8);
            CP_ASYNC16(st + 8192 + d, vsrc0 + roff + c * 8);
        }
        CP_COMMIT();
    };

    float m0 = -INFINITY, m1 = -INFINITY, l0 = 0.f, l1 = 0.f;
    float acc[8][4] = {};

    const int sel = lane >> 3, r8 = lane & 7;

    const int NT = SEQ / 64;
    issue(0, 0);
    issue(1, 1);
    for (int kt = 0; kt < NT; kt++) {
        const int cur = kt % 3;
        if (kt + 1 < NT) CP_WAIT(1); else CP_WAIT(0);
        __syncthreads();                 // readers of stage (kt+2)%3 done at kt-1
        if (kt + 2 < NT) issue((kt + 2) % 3, kt + 2);

        const uint32_t Kb = sb + cur * ATT_STG;
        const uint32_t Vb = Kb + 8192;

        float s[8][4] = {};
        #pragma unroll
        for (int ks = 0; ks < 4; ks++) {
            #pragma unroll
            for (int njp = 0; njp < 4; njp++) {
                int row = (njp * 2 + (sel >> 1)) * 8 + r8;
                int c = ks * 2 + (sel & 1);
                uint32_t addr = Kb + (uint32_t)(row * 128 + ((c ^ (row & 7)) * 16));
                unsigned bf0, bf1, bf2, bf3;
                asm volatile(
                    "ldmatrix.sync.aligned.m8n8.x4.shared.b16 {%0,%1,%2,%3}, [%4];"
                    : "=r"(bf0), "=r"(bf1), "=r"(bf2), "=r"(bf3) : "r"(addr));
                mma16(s[njp * 2],     aQ[ks], bf0, bf1);
                mma16(s[njp * 2 + 1], aQ[ks], bf2, bf3);
            }
        }

        float tm0 = -INFINITY, tm1 = -INFINITY;
        #pragma unroll
        for (int nt = 0; nt < 8; nt++) {
            tm0 = fmaxf(tm0, fmaxf(s[nt][0], s[nt][1]));
            tm1 = fmaxf(tm1, fmaxf(s[nt][2], s[nt][3]));
        }
        tm0 = fmaxf(tm0, __shfl_xor_sync(0xffffffffu, tm0, 1));
        tm0 = fmaxf(tm0, __shfl_xor_sync(0xffffffffu, tm0, 2));
        tm1 = fmaxf(tm1, __shfl_xor_sync(0xffffffffu, tm1, 1));
        tm1 = fmaxf(tm1, __shfl_xor_sync(0xffffffffu, tm1, 2));
        float mn0 = fmaxf(m0, tm0), mn1 = fmaxf(m1, tm1);
        float cf0 = __expf(m0 - mn0), cf1 = __expf(m1 - mn1);
        m0 = mn0; m1 = mn1;

        float rs0 = 0.f, rs1 = 0.f;
        #pragma unroll
        for (int nt = 0; nt < 8; nt++) {
            s[nt][0] = __expf(s[nt][0] - m0);
            s[nt][1] = __expf(s[nt][1] - m0);
            s[nt][2] = __expf(s[nt][2] - m1);
            s[nt][3] = __expf(s[nt][3] - m1);
            rs0 += s[nt][0] + s[nt][1];
            rs1 += s[nt][2] + s[nt][3];
        }
        rs0 += __shfl_xor_sync(0xffffffffu, rs0, 1);
        rs0 += __shfl_xor_sync(0xffffffffu, rs0, 2);
        rs1 += __shfl_xor_sync(0xffffffffu, rs1, 1);
        rs1 += __shfl_xor_sync(0xffffffffu, rs1, 2);
        l0 = l0 * cf0 + rs0; l1 = l1 * cf1 + rs1;
        #pragma unroll
        for (int nt = 0; nt < 8; nt++) {
            acc[nt][0] *= cf0; acc[nt][1] *= cf0;
            acc[nt][2] *= cf1; acc[nt][3] *= cf1;
        }

        unsigned aP[4][4];
        #pragma unroll
        for (int j = 0; j < 4; j++) {
            aP[j][0] = pack2(s[2*j][0],   s[2*j][1]);
            aP[j][1] = pack2(s[2*j][2],   s[2*j][3]);
            aP[j][2] = pack2(s[2*j+1][0], s[2*j+1][1]);
            aP[j][3] = pack2(s[2*j+1][2], s[2*j+1][3]);
        }

        #pragma unroll
        for (int j = 0; j < 4; j++) {
            #pragma unroll
            for (int njp = 0; njp < 4; njp++) {
                int row = 16 * j + (sel & 1) * 8 + r8;
                int c = njp * 2 + (sel >> 1);
                uint32_t addr = Vb + (uint32_t)(row * 128 + ((c ^ (row & 7)) * 16));
                unsigned bf0, bf1, bf2, bf3;
                asm volatile(
                    "ldmatrix.sync.aligned.m8n8.x4.trans.shared.b16 {%0,%1,%2,%3}, [%4];"
                    : "=r"(bf0), "=r"(bf1), "=r"(bf2), "=r"(bf3) : "r"(addr));
                mma16(acc[njp * 2],     aP[j], bf0, bf1);
                mma16(acc[njp * 2 + 1], aP[j], bf2, bf3);
            }
        }
    }

    const float inv0 = 1.0f / l0, inv1 = 1.0f / l1;
    __half* orow0 = O + (size_t)(b * SEQ + qr) * DMODEL + h * HD;
    __half* orow8 = orow0 + (size_t)8 * DMODEL;
    #pragma unroll
    for (int nt = 0; nt < 8; nt++) {
        int col = nt * 8 + 2 * c4;
        *(__half2*)(orow0 + col) = __floats2half2_rn(acc[nt][0] * inv0, acc[nt][1] * inv0);
        *(__half2*)(orow8 + col) = __floats2half2_rn(acc[nt][2] * inv1, acc[nt][3] * inv1);
    }
}

// ---------------- launch ----------------
extern "C" void kernel_launch(void* const* d_in, const int* in_sizes, int n_in,
                              void* d_out, int out_size) {
    const float* x     = (const float*)d_in[0];
    const float* ln1_g = (const float*)d_in[1];
    const float* ln1_b = (const float*)d_in[2];
    const float* ln2_g = (const float*)d_in[3];
    const float* ln2_b = (const float*)d_in[4];
    const float* wq    = (const float*)d_in[5];
    const float* bq    = (const float*)d_in[6];
    const float* wk    = (const float*)d_in[7];
    const float* bk    = (const float*)d_in[8];
    const float* wv    = (const float*)d_in[9];
    const float* bv    = (const float*)d_in[10];
    const float* wp    = (const float*)d_in[11];
    const float* bp    = (const float*)d_in[12];
    const float* ln3_g = (const float*)d_in[13];
    const float* ln3_b = (const float*)d_in[14];
    const float* w1    = (const float*)d_in[15];
    const float* b1    = (const float*)d_in[16];
    const float* w2    = (const float*)d_in[17];
    const float* b2    = (const float*)d_in[18];
    float* out = (float*)d_out;

    float *y1, *bqkv;
    __half *xnh, *qkvh, *ctxh, *ffh, *wqkvT, *wpT, *w1T, *w2T;
    cudaGetSymbolAddress((void**)&y1,    g_y1);
    cudaGetSymbolAddress((void**)&bqkv,  g_bqkv);
    cudaGetSymbolAddress((void**)&xnh,   g_xnh);
    cudaGetSymbolAddress((void**)&qkvh,  g_qkvh);
    cudaGetSymbolAddress((void**)&ctxh,  g_ctxh);
    cudaGetSymbolAddress((void**)&ffh,   g_ffh);
    cudaGetSymbolAddress((void**)&wqkvT, g_wqkvT);
    cudaGetSymbolAddress((void**)&wpT,   g_wpT);
    cudaGetSymbolAddress((void**)&w1T,   g_w1T);
    cudaGetSymbolAddress((void**)&w2T,   g_w2T);

    cudaFuncSetAttribute(gemm_f16_kernel,
                         cudaFuncAttributeMaxDynamicSharedMemorySize, 3 * GSTG);

    // 0. weight prep (one launch: transposes + bias concat)
    cvt_all_kernel<<<12292, dim3(32, 8)>>>(wq, wk, wv, wp, w1, w2, bq, bk, bv,
                                           wqkvT, wpT, w1T, w2T, bqkv);

    // 1. double pre-norm -> fp16 (warp-per-row)
    ln_double_kernel<<<MROWS / 8, 256>>>(x, ln1_g, ln1_b, ln2_g, ln2_b, xnh);

    // 2. fused QKV projection (fp16 out, N=3072)
    gemm_f16_kernel<<<dim3(3*DMODEL/128, MROWS/128), 256, 3*GSTG>>>(
        xnh, wqkvT, bqkv, nullptr, nullptr, qkvh, MROWS, 3*DMODEL, DMODEL, 0);

    // 3. fp16 flash attention -> fp16 ctx (128 q rows / CTA, 3-stage)
    attn_f16_kernel<<<dim3(BATCH * NHEAD, SEQ / 128), 256>>>(qkvh, ctxh);

    // 4. output projection + residual (fp32 out)
    dim3 gdd(DMODEL / 128, MROWS / 128);
    gemm_f16_kernel<<<gdd, 256, 3*GSTG>>>(ctxh, wpT, bp, x, y1, nullptr,
                                          MROWS, DMODEL, DMODEL, 0);

    // 5. ffn pre-norm -> fp16 (warp-per-row)
    ln_single_kernel<<<MROWS / 8, 256>>>(y1, ln3_g, ln3_b, xnh);

    // 6. FFN: w1 (+gelu, fp16 out), w2 (+residual, fp32 out -> d_out)
    gemm_f16_kernel<<<dim3(FFDIM / 128, MROWS / 128), 256, 3*GSTG>>>(
        xnh, w1T, b1, nullptr, nullptr, ffh, MROWS, FFDIM, DMODEL, 1);
    gemm_f16_kernel<<<gdd, 256, 3*GSTG>>>(ffh, w2T, b2, y1, out, nullptr,
                                          MROWS, DMODEL, FFDIM, 0);
}

// round 11
// speedup vs baseline: 2.8718x; 1.0103x over previous
#include <cuda_runtime.h>
#include <cuda_fp16.h>
#include <math.h>
#include <stdint.h>

// Shapes (fixed by the problem)
#define BATCH 8
#define SEQ   1024
#define DMODEL 1024
#define NHEAD 16
#define HD    64
#define FFDIM 4096
#define MROWS (BATCH*SEQ)   // 8192

// ---------------- scratch (device globals; no allocation allowed) ----------
__device__ float g_y1 [MROWS*DMODEL];

__device__ __half g_xnh [MROWS*DMODEL];
__device__ __half g_qkvh[MROWS*3*DMODEL];     // [token][3072]: q|k|v
__device__ __half g_ctxh[MROWS*DMODEL];
__device__ __half g_ffh [MROWS*FFDIM];

__device__ __half g_wqkvT[3*DMODEL*DMODEL];   // [3072][1024]
__device__ __half g_wpT[DMODEL*DMODEL];
__device__ __half g_w1T[DMODEL*FFDIM];
__device__ __half g_w2T[FFDIM*DMODEL];
__device__ float  g_bqkv[3*DMODEL];

// ---------------- common helpers ----------------
__device__ __forceinline__ void mma16(float acc[4], const unsigned a[4],
                                      unsigned b0, unsigned b1) {
    asm volatile(
        "mma.sync.aligned.m16n8k16.row.col.f32.f16.f16.f32 "
        "{%0,%1,%2,%3}, {%4,%5,%6,%7}, {%8,%9}, {%0,%1,%2,%3};\n"
        : "+f"(acc[0]), "+f"(acc[1]), "+f"(acc[2]), "+f"(acc[3])
        : "r"(a[0]), "r"(a[1]), "r"(a[2]), "r"(a[3]), "r"(b0), "r"(b1));
}

__device__ __forceinline__ uint32_t smem_u32(const void* p) {
    uint32_t a;
    asm("{ .reg .u64 t; cvta.to.shared.u64 t, %1; cvt.u32.u64 %0, t; }"
        : "=r"(a) : "l"(p));
    return a;
}

#define CP_ASYNC16(dst, src) \
    asm volatile("cp.async.cg.shared.global [%0], [%1], 16;" :: "r"(dst), "l"(src))
#define CP_COMMIT()   asm volatile("cp.async.commit_group;" ::: "memory")
#define CP_WAIT(n)    asm volatile("cp.async.wait_group %0;" :: "n"(n) : "memory")

__device__ __forceinline__ unsigned pack2(float a, float b) {
    __half2 h = __floats2half2_rn(a, b);
    return *(unsigned*)&h;
}

__device__ __forceinline__ float warp_sum(float v) {
    #pragma unroll
    for (int o = 16; o; o >>= 1) v += __shfl_xor_sync(0xffffffffu, v, o);
    return v;
}

// ---------------- merged weight convert+transpose + bias concat --------------
__global__ void cvt_all_kernel(const float* __restrict__ wq, const float* __restrict__ wk,
                               const float* __restrict__ wv, const float* __restrict__ wp,
                               const float* __restrict__ w1, const float* __restrict__ w2,
                               const float* __restrict__ bq, const float* __restrict__ bk,
                               const float* __restrict__ bv,
                               __half* __restrict__ wqkvT, __half* __restrict__ wpT,
                               __half* __restrict__ w1T,   __half* __restrict__ w2T,
                               float* __restrict__ bqkv) {
    int id = blockIdx.x;
    if (id >= 12288) {
        int i = (id - 12288) * 256 + threadIdx.y * 32 + threadIdx.x;
        if (i < DMODEL) {
            bqkv[i] = bq[i];
            bqkv[DMODEL + i] = bk[i];
            bqkv[2 * DMODEL + i] = bv[i];
        }
        return;
    }
    __shared__ float t[32][33];
    const float* W; __half* Wt; int K, N, local;
    if (id < 4096) {
        K = DMODEL; N = DMODEL; local = id & 1023;
        int sel = id >> 10;
        if (sel == 0)      { W = wq; Wt = wqkvT; }
        else if (sel == 1) { W = wk; Wt = wqkvT + DMODEL*DMODEL; }
        else if (sel == 2) { W = wv; Wt = wqkvT + 2*DMODEL*DMODEL; }
        else               { W = wp; Wt = wpT; }
    } else if (id < 8192) {
        K = DMODEL; N = FFDIM; local = id - 4096; W = w1; Wt = w1T;
    } else {
        K = FFDIM; N = DMODEL; local = id - 8192; W = w2; Wt = w2T;
    }
    int gx = K >> 5;
    int bk_ = (local % gx) * 32, bn = (local / gx) * 32;
    int tx = threadIdx.x, ty = threadIdx.y;   // (32, 8)
    #pragma unroll
    for (int i = 0; i < 4; i++)
        t[ty + i * 8][tx] = W[(size_t)(bk_ + ty + i * 8) * N + bn + tx];
    __syncthreads();
    #pragma unroll
    for (int i = 0; i < 4; i++)
        Wt[(size_t)(bn + ty + i * 8) * K + bk_ + tx] = __float2half(t[tx][ty + i * 8]);
}

// ---------------- LayerNorm kernels: warp-per-row, shuffle-only --------------
__global__ __launch_bounds__(256) void ln_double_kernel(
    const float* __restrict__ X,
    const float* __restrict__ g1, const float* __restrict__ b1,
    const float* __restrict__ g2, const float* __restrict__ b2,
    __half* __restrict__ Y) {
    const int lane = threadIdx.x & 31, w = threadIdx.x >> 5;
    const int row = blockIdx.x * 8 + w;
    const float4* xr = (const float4*)X + (size_t)row * 256;
    float4 v[8];
    float s = 0.f;
    #pragma unroll
    for (int i = 0; i < 8; i++) {
        v[i] = xr[lane + 32 * i];
        s += v[i].x + v[i].y + v[i].z + v[i].w;
    }
    float mu = warp_sum(s) * (1.0f / 1024.0f);
    float vs = 0.f;
    #pragma unroll
    for (int i = 0; i < 8; i++) {
        v[i].x -= mu; v[i].y -= mu; v[i].z -= mu; v[i].w -= mu;
        vs += v[i].x*v[i].x + v[i].y*v[i].y + v[i].z*v[i].z + v[i].w*v[i].w;
    }
    float inv = rsqrtf(warp_sum(vs) * (1.0f / 1024.0f) + 1e-6f);
    float s2 = 0.f;
    #pragma unroll
    for (int i = 0; i < 8; i++) {
        float4 G = ((const float4*)g1)[lane + 32 * i];
        float4 B = ((const float4*)b1)[lane + 32 * i];
        v[i].x = v[i].x * inv * G.x + B.x;
        v[i].y = v[i].y * inv * G.y + B.y;
        v[i].z = v[i].z * inv * G.z + B.z;
        v[i].w = v[i].w * inv * G.w + B.w;
        s2 += v[i].x + v[i].y + v[i].z + v[i].w;
    }
    float mu2 = warp_sum(s2) * (1.0f / 1024.0f);
    float vs2 = 0.f;
    #pragma unroll
    for (int i = 0; i < 8; i++) {
        v[i].x -= mu2; v[i].y -= mu2; v[i].z -= mu2; v[i].w -= mu2;
        vs2 += v[i].x*v[i].x + v[i].y*v[i].y + v[i].z*v[i].z + v[i].w*v[i].w;
    }
    float inv2 = rsqrtf(warp_sum(vs2) * (1.0f / 1024.0f) + 1e-6f);
    __half2* yr = (__half2*)Y + (size_t)row * 512;
    #pragma unroll
    for (int i = 0; i < 8; i++) {
        float4 G = ((const float4*)g2)[lane + 32 * i];
        float4 B = ((const float4*)b2)[lane + 32 * i];
        yr[2 * (lane + 32 * i)]     = __floats2half2_rn(v[i].x * inv2 * G.x + B.x,
                                                        v[i].y * inv2 * G.y + B.y);
        yr[2 * (lane + 32 * i) + 1] = __floats2half2_rn(v[i].z * inv2 * G.z + B.z,
                                                        v[i].w * inv2 * G.w + B.w);
    }
}

__global__ __launch_bounds__(256) void ln_single_kernel(
    const float* __restrict__ X,
    const float* __restrict__ g, const float* __restrict__ b,
    __half* __restrict__ Y) {
    const int lane = threadIdx.x & 31, w = threadIdx.x >> 5;
    const int row = blockIdx.x * 8 + w;
    const float4* xr = (const float4*)X + (size_t)row * 256;
    float4 v[8];
    float s = 0.f;
    #pragma unroll
    for (int i = 0; i < 8; i++) {
        v[i] = xr[lane + 32 * i];
        s += v[i].x + v[i].y + v[i].z + v[i].w;
    }
    float mu = warp_sum(s) * (1.0f / 1024.0f);
    float vs = 0.f;
    #pragma unroll
    for (int i = 0; i < 8; i++) {
        v[i].x -= mu; v[i].y -= mu; v[i].z -= mu; v[i].w -= mu;
        vs += v[i].x*v[i].x + v[i].y*v[i].y + v[i].z*v[i].z + v[i].w*v[i].w;
    }
    float inv = rsqrtf(warp_sum(vs) * (1.0f / 1024.0f) + 1e-6f);
    __half2* yr = (__half2*)Y + (size_t)row * 512;
    #pragma unroll
    for (int i = 0; i < 8; i++) {
        float4 G = ((const float4*)g)[lane + 32 * i];
        float4 B = ((const float4*)b)[lane + 32 * i];
        yr[2 * (lane + 32 * i)]     = __floats2half2_rn(v[i].x * inv * G.x + B.x,
                                                        v[i].y * inv * G.y + B.y);
        yr[2 * (lane + 32 * i) + 1] = __floats2half2_rn(v[i].z * inv * G.z + B.z,
                                                        v[i].w * inv * G.w + B.w);
    }
}

// ---------------- FP16 cp.async GEMM: BK=64, 3 stages (proven R9) ------------
#define GSTG 32768

__global__ __launch_bounds__(256, 2) void gemm_f16_kernel(
    const __half* __restrict__ A, const __half* __restrict__ Wt,
    const float* __restrict__ bias, const float* __restrict__ res,
    float* __restrict__ C, __half* __restrict__ Ch,
    int M, int N, int K, int act)
{
    extern __shared__ __align__(128) char gsm[];
    const uint32_t sb = smem_u32(gsm);
    const int tid = threadIdx.x, lane = tid & 31, warp = tid >> 5;
    const int m0 = blockIdx.y * 128, n0 = blockIdx.x * 128;
    const int wm = (warp >> 2) * 64, wn = (warp & 3) * 32;

    const int sr = tid >> 3, scol = tid & 7;
    const uint32_t dstA0 = (uint32_t)(sr * 128 + ((scol ^ (sr & 7)) * 16));
    const __half* Abase = A  + (size_t)(m0 + sr) * K + scol * 8;
    const __half* Bbase = Wt + (size_t)(n0 + sr) * K + scol * 8;

    const int r8 = lane & 7, sel = lane >> 3;
    uint32_t a_row[4]; int a_key[4];
    #pragma unroll
    for (int mi = 0; mi < 4; mi++) {
        int r = wm + mi * 16 + (sel & 1) * 8 + r8;
        a_row[mi] = r * 128;
        a_key[mi] = r & 7;
    }
    const int a_hi = sel >> 1;
    uint32_t b_row[2]; int b_key[2];
    #pragma unroll
    for (int nj = 0; nj < 2; nj++) {
        int r = wn + (nj * 2 + (sel >> 1)) * 8 + r8;
        b_row[nj] = (uint32_t)(16384 + r * 128);
        b_key[nj] = r & 7;
    }
    const int b_hi = sel & 1;

    float acc[4][4][4] = {};

    auto issue = [&](int s, int kc) {
        const uint32_t st = sb + s * GSTG;
        const int ko = kc * 64;
        #pragma unroll
        for (int i = 0; i < 4; i++) {
            CP_ASYNC16(st + dstA0 + i * 4096, Abase + (size_t)i * 32 * K + ko);
            CP_ASYNC16(st + 16384 + dstA0 + i * 4096, Bbase + (size_t)i * 32 * K + ko);
        }
        CP_COMMIT();
    };

    const int NC = K >> 6;
    issue(0, 0);
    if (NC > 1) issue(1, 1);

    for (int kc = 0; kc < NC; kc++) {
        const int cur = kc % 3;
        if (kc + 1 < NC) CP_WAIT(1); else CP_WAIT(0);
        __syncthreads();
        if (kc + 2 < NC) issue((kc + 2) % 3, kc + 2);

        const uint32_t stb = sb + cur * GSTG;
        #pragma unroll
        for (int ks = 0; ks < 4; ks++) {
            unsigned af[4][4], bf[4][2];
            #pragma unroll
            for (int mi = 0; mi < 4; mi++) {
                uint32_t addr = stb + a_row[mi]
                              + (uint32_t)(((ks * 2 + a_hi) ^ a_key[mi]) * 16);
                asm volatile(
                    "ldmatrix.sync.aligned.m8n8.x4.shared.b16 {%0,%1,%2,%3}, [%4];"
                    : "=r"(af[mi][0]), "=r"(af[mi][1]), "=r"(af[mi][2]), "=r"(af[mi][3])
                    : "r"(addr));
            }
            #pragma unroll
            for (int nj = 0; nj < 2; nj++) {
                uint32_t addr = stb + b_row[nj]
                              + (uint32_t)(((ks * 2 + b_hi) ^ b_key[nj]) * 16);
                asm volatile(
                    "ldmatrix.sync.aligned.m8n8.x4.shared.b16 {%0,%1,%2,%3}, [%4];"
                    : "=r"(bf[nj*2][0]), "=r"(bf[nj*2][1]),
                      "=r"(bf[nj*2+1][0]), "=r"(bf[nj*2+1][1])
                    : "r"(addr));
            }
            #pragma unroll
            for (int mi = 0; mi < 4; mi++)
                #pragma unroll
                for (int ni = 0; ni < 4; ni++)
                    mma16(acc[mi][ni], af[mi], bf[ni][0], bf[ni][1]);
        }
    }

    const int g = lane >> 2, c4 = lane & 3;
    #pragma unroll
    for (int mi = 0; mi < 4; mi++) {
        #pragma unroll
        for (int ni = 0; ni < 4; ni++) {
            int gn = n0 + wn + ni * 8 + c4 * 2;
            float bv0 = bias[gn], bv1 = bias[gn + 1];
            #pragma unroll
            for (int half_ = 0; half_ < 2; half_++) {
                int gr = m0 + wm + mi * 16 + g + half_ * 8;
                float v0 = acc[mi][ni][half_ * 2 + 0] + bv0;
                float v1 = acc[mi][ni][half_ * 2 + 1] + bv1;
                if (act) {
                    v0 = 0.5f * v0 * (1.0f + erff(v0 * 0.70710678118654752f));
                    v1 = 0.5f * v1 * (1.0f + erff(v1 * 0.70710678118654752f));
                }
                size_t o = (size_t)gr * N + gn;
                if (res) { v0 += res[o]; v1 += res[o + 1]; }
                if (Ch) {
                    *(__half2*)(Ch + o) = __floats2half2_rn(v0, v1);
                } else {
                    C[o] = v0; C[o + 1] = v1;
                }
            }
        }
    }
}

// ---------------- FP16 flash attention: 128 q rows, 3-stage, exp2 softmax ----
// Address strength-reduction: every smem row = 8k + r8, so the swizzle key is
// the thread-constant r8 for all ldmatrix addresses; precompute row/col parts.
#define ATT_STG 16384            // K 8KB + V 8KB per stage; 3 stages = 48KB
#define QKV_LD  (3 * DMODEL)

__global__ __launch_bounds__(256, 2) void attn_f16_kernel(
    const __half* __restrict__ QKV, __half* __restrict__ O) {
    __shared__ __align__(128) char smb[3 * ATT_STG];
    const uint32_t sb = smem_u32(smb);
    const int tid = threadIdx.x, lane = tid & 31, warp = tid >> 5;
    const int g = lane >> 2, c4 = lane & 3;
    const int bh = blockIdx.x, qt = blockIdx.y;
    const int b = bh >> 4, h = bh & 15;

    // Q scaled by 0.125 * log2(e) -> scores in log2 domain
    unsigned aQ[4][4];
    const int qr = qt * 128 + warp * 16 + g;
    {
        const float QS = 0.18033688011112042f;
        const __half2 sc = __floats2half2_rn(QS, QS);
        const __half* q0 = QKV + (size_t)(b * SEQ + qr) * QKV_LD + h * HD;
        const __half* q8 = q0 + (size_t)8 * QKV_LD;
        #pragma unroll
        for (int j = 0; j < 4; j++) {
            __half2 t;
            t = __hmul2(*(const __half2*)(q0 + j * 16 + 2 * c4), sc);     aQ[j][0] = *(unsigned*)&t;
            t = __hmul2(*(const __half2*)(q8 + j * 16 + 2 * c4), sc);     aQ[j][1] = *(unsigned*)&t;
            t = __hmul2(*(const __half2*)(q0 + j * 16 + 8 + 2 * c4), sc); aQ[j][2] = *(unsigned*)&t;
            t = __hmul2(*(const __half2*)(q8 + j * 16 + 8 + 2 * c4), sc); aQ[j][3] = *(unsigned*)&t;
        }
    }

    const int sr = tid >> 2, scg = (tid & 3) * 2;
    const __half* ksrc0 = QKV + (size_t)(b * SEQ + sr) * QKV_LD + DMODEL + h * HD;
    const __half* vsrc0 = ksrc0 + DMODEL;

    auto issue = [&](int s, int kt) {
        const uint32_t st = sb + s * ATT_STG;
        const size_t roff = (size_t)(kt * 64) * QKV_LD;
        #pragma unroll
        for (int j = 0; j < 2; j++) {
            int c = scg + j;
            uint32_t d = (uint32_t)(sr * 128 + ((c ^ (sr & 7)) * 16));
            CP_ASYNC16(st + d, ksrc0 + roff + c * 8);
            CP_ASYNC16(st + 8192 + d, vsrc0 + roff + c * 8);
        }
        CP_COMMIT();
    };

    // precomputed ldmatrix address components (swizzle key == r8 everywhere)
    const int sel = lane >> 3, r8 = lane & 7;
    const int lo = sel & 1, hi = sel >> 1;
    uint32_t krow[4], kcx[4], vrow[4], vcx[4];
    #pragma unroll
    for (int i = 0; i < 4; i++) {
        krow[i] = (uint32_t)((((i * 2 + hi) * 8) + r8) * 128);
        kcx[i]  = (uint32_t)((((i * 2 + lo) ^ r8)) * 16);
        vrow[i] = (uint32_t)(((16 * i + lo * 8) + r8) * 128);
        vcx[i]  = (uint32_t)((((i * 2 + hi) ^ r8)) * 16);
    }

    float m0 = -INFINITY, m1 = -INFINITY, l0 = 0.f, l1 = 0.f;
    float acc[8][4] = {};

    const int NT = SEQ / 64;
    issue(0, 0);
    issue(1, 1);
    for (int kt = 0; kt < NT; kt++) {
        const int cur = kt % 3;
        if (kt + 1 < NT) CP_WAIT(1); else CP_WAIT(0);
        __syncthreads();
        if (kt + 2 < NT) issue((kt + 2) % 3, kt + 2);

        const uint32_t Kb = sb + cur * ATT_STG;
        const uint32_t Vb = Kb + 8192;

        float s[8][4] = {};
        #pragma unroll
        for (int ks = 0; ks < 4; ks++) {
            #pragma unroll
            for (int njp = 0; njp < 4; njp++) {
                uint32_t addr = Kb + krow[njp] + kcx[ks];
                unsigned bf0, bf1, bf2, bf3;
                asm volatile(
                    "ldmatrix.sync.aligned.m8n8.x4.shared.b16 {%0,%1,%2,%3}, [%4];"
                    : "=r"(bf0), "=r"(bf1), "=r"(bf2), "=r"(bf3) : "r"(addr));
                mma16(s[njp * 2],     aQ[ks], bf0, bf1);
                mma16(s[njp * 2 + 1], aQ[ks], bf2, bf3);
            }
        }

        // online softmax in log2 domain (exp2 only, no mul)
        float tm0 = -INFINITY, tm1 = -INFINITY;
        #pragma unroll
        for (int nt = 0; nt < 8; nt++) {
            tm0 = fmaxf(tm0, fmaxf(s[nt][0], s[nt][1]));
            tm1 = fmaxf(tm1, fmaxf(s[nt][2], s[nt][3]));
        }
        tm0 = fmaxf(tm0, __shfl_xor_sync(0xffffffffu, tm0, 1));
        tm0 = fmaxf(tm0, __shfl_xor_sync(0xffffffffu, tm0, 2));
        tm1 = fmaxf(tm1, __shfl_xor_sync(0xffffffffu, tm1, 1));
        tm1 = fmaxf(tm1, __shfl_xor_sync(0xffffffffu, tm1, 2));
        float mn0 = fmaxf(m0, tm0), mn1 = fmaxf(m1, tm1);
        float cf0 = exp2f(m0 - mn0), cf1 = exp2f(m1 - mn1);
        m0 = mn0; m1 = mn1;

        float rs0 = 0.f, rs1 = 0.f;
        #pragma unroll
        for (int nt = 0; nt < 8; nt++) {
            s[nt][0] = exp2f(s[nt][0] - m0);
            s[nt][1] = exp2f(s[nt][1] - m0);
            s[nt][2] = exp2f(s[nt][2] - m1);
            s[nt][3] = exp2f(s[nt][3] - m1);
            rs0 += s[nt][0] + s[nt][1];
            rs1 += s[nt][2] + s[nt][3];
        }
        rs0 += __shfl_xor_sync(0xffffffffu, rs0, 1);
        rs0 += __shfl_xor_sync(0xffffffffu, rs0, 2);
        rs1 += __shfl_xor_sync(0xffffffffu, rs1, 1);
        rs1 += __shfl_xor_sync(0xffffffffu, rs1, 2);
        l0 = l0 * cf0 + rs0; l1 = l1 * cf1 + rs1;
        #pragma unroll
        for (int nt = 0; nt < 8; nt++) {
            acc[nt][0] *= cf0; acc[nt][1] *= cf0;
            acc[nt][2] *= cf1; acc[nt][3] *= cf1;
        }

        unsigned aP[4][4];
        #pragma unroll
        for (int j = 0; j < 4; j++) {
            aP[j][0] = pack2(s[2*j][0],   s[2*j][1]);
            aP[j][1] = pack2(s[2*j][2],   s[2*j][3]);
            aP[j][2] = pack2(s[2*j+1][0], s[2*j+1][1]);
            aP[j][3] = pack2(s[2*j+1][2], s[2*j+1][3]);
        }

        #pragma unroll
        for (int j = 0; j < 4; j++) {
            #pragma unroll
            for (int njp = 0; njp < 4; njp++) {
                uint32_t addr = Vb + vrow[j] + vcx[njp];
                unsigned bf0, bf1, bf2, bf3;
                asm volatile(
                    "ldmatrix.sync.aligned.m8n8.x4.trans.shared.b16 {%0,%1,%2,%3}, [%4];"
                    : "=r"(bf0), "=r"(bf1), "=r"(bf2), "=r"(bf3) : "r"(addr));
                mma16(acc[njp * 2],     aP[j], bf0, bf1);
                mma16(acc[njp * 2 + 1], aP[j], bf2, bf3);
            }
        }
    }

    const float inv0 = 1.0f / l0, inv1 = 1.0f / l1;
    __half* orow0 = O + (size_t)(b * SEQ + qr) * DMODEL + h * HD;
    __half* orow8 = orow0 + (size_t)8 * DMODEL;
    #pragma unroll
    for (int nt = 0; nt < 8; nt++) {
        int col = nt * 8 + 2 * c4;
        *(__half2*)(orow0 + col) = __floats2half2_rn(acc[nt][0] * inv0, acc[nt][1] * inv0);
        *(__half2*)(orow8 + col) = __floats2half2_rn(acc[nt][2] * inv1, acc[nt][3] * inv1);
    }
}

// ---------------- launch ----------------
extern "C" void kernel_launch(void* const* d_in, const int* in_sizes, int n_in,
                              void* d_out, int out_size) {
    const float* x     = (const float*)d_in[0];
    const float* ln1_g = (const float*)d_in[1];
    const float* ln1_b = (const float*)d_in[2];
    const float* ln2_g = (const float*)d_in[3];
    const float* ln2_b = (const float*)d_in[4];
    const float* wq    = (const float*)d_in[5];
    const float* bq    = (const float*)d_in[6];
    const float* wk    = (const float*)d_in[7];
    const float* bk    = (const float*)d_in[8];
    const float* wv    = (const float*)d_in[9];
    const float* bv    = (const float*)d_in[10];
    const float* wp    = (const float*)d_in[11];
    const float* bp    = (const float*)d_in[12];
    const float* ln3_g = (const float*)d_in[13];
    const float* ln3_b = (const float*)d_in[14];
    const float* w1    = (const float*)d_in[15];
    const float* b1    = (const float*)d_in[16];
    const float* w2    = (const float*)d_in[17];
    const float* b2    = (const float*)d_in[18];
    float* out = (float*)d_out;

    float *y1, *bqkv;
    __half *xnh, *qkvh, *ctxh, *ffh, *wqkvT, *wpT, *w1T, *w2T;
    cudaGetSymbolAddress((void**)&y1,    g_y1);
    cudaGetSymbolAddress((void**)&bqkv,  g_bqkv);
    cudaGetSymbolAddress((void**)&xnh,   g_xnh);
    cudaGetSymbolAddress((void**)&qkvh,  g_qkvh);
    cudaGetSymbolAddress((void**)&ctxh,  g_ctxh);
    cudaGetSymbolAddress((void**)&ffh,   g_ffh);
    cudaGetSymbolAddress((void**)&wqkvT, g_wqkvT);
    cudaGetSymbolAddress((void**)&wpT,   g_wpT);
    cudaGetSymbolAddress((void**)&w1T,   g_w1T);
    cudaGetSymbolAddress((void**)&w2T,   g_w2T);

    cudaFuncSetAttribute(gemm_f16_kernel,
                         cudaFuncAttributeMaxDynamicSharedMemorySize, 3 * GSTG);

    // 0. weight prep (one launch: transposes + bias concat)
    cvt_all_kernel<<<12292, dim3(32, 8)>>>(wq, wk, wv, wp, w1, w2, bq, bk, bv,
                                           wqkvT, wpT, w1T, w2T, bqkv);

    // 1. double pre-norm -> fp16 (warp-per-row)
    ln_double_kernel<<<MROWS / 8, 256>>>(x, ln1_g, ln1_b, ln2_g, ln2_b, xnh);

    // 2. fused QKV projection (fp16 out, N=3072)
    gemm_f16_kernel<<<dim3(3*DMODEL/128, MROWS/128), 256, 3*GSTG>>>(
        xnh, wqkvT, bqkv, nullptr, nullptr, qkvh, MROWS, 3*DMODEL, DMODEL, 0);

    // 3. fp16 flash attention -> fp16 ctx
    attn_f16_kernel<<<dim3(BATCH * NHEAD, SEQ / 128), 256>>>(qkvh, ctxh);

    // 4. output projection + residual (fp32 out)
    dim3 gdd(DMODEL / 128, MROWS / 128);
    gemm_f16_kernel<<<gdd, 256, 3*GSTG>>>(ctxh, wpT, bp, x, y1, nullptr,
                                          MROWS, DMODEL, DMODEL, 0);

    // 5. ffn pre-norm -> fp16 (warp-per-row)
    ln_single_kernel<<<MROWS / 8, 256>>>(y1, ln3_g, ln3_b, xnh);

    // 6. FFN: w1 (+gelu, fp16 out), w2 (+residual, fp32 out -> d_out)
    gemm_f16_kernel<<<dim3(FFDIM / 128, MROWS / 128), 256, 3*GSTG>>>(
        xnh, w1T, b1, nullptr, nullptr, ffh, MROWS, FFDIM, DMODEL, 1);
    gemm_f16_kernel<<<gdd, 256, 3*GSTG>>>(ffh, w2T, b2, y1, out, nullptr,
                                          MROWS, DMODEL, FFDIM, 0);
}

// round 14
// speedup vs baseline: 2.8868x; 1.0052x over previous
#include <cuda_runtime.h>
#include <cuda_fp16.h>
#include <math.h>
#include <stdint.h>

// Shapes (fixed by the problem)
#define BATCH 8
#define SEQ   1024
#define DMODEL 1024
#define NHEAD 16
#define HD    64
#define FFDIM 4096
#define MROWS (BATCH*SEQ)   // 8192

// ---------------- scratch (device globals; no allocation allowed) ----------
__device__ float g_y1 [MROWS*DMODEL];

__device__ __half g_xnh [MROWS*DMODEL];
__device__ __half g_qkvh[MROWS*3*DMODEL];     // [token][3072]: q|k|v
__device__ __half g_ctxh[MROWS*DMODEL];
__device__ __half g_ffh [MROWS*FFDIM];

__device__ __half g_wqkvT[3*DMODEL*DMODEL];   // [3072][1024]
__device__ __half g_wpT[DMODEL*DMODEL];
__device__ __half g_w1T[DMODEL*FFDIM];
__device__ __half g_w2T[FFDIM*DMODEL];
__device__ float  g_bqkv[3*DMODEL];

// ---------------- common helpers ----------------
__device__ __forceinline__ void mma16(float acc[4], const unsigned a[4],
                                      unsigned b0, unsigned b1) {
    asm volatile(
        "mma.sync.aligned.m16n8k16.row.col.f32.f16.f16.f32 "
        "{%0,%1,%2,%3}, {%4,%5,%6,%7}, {%8,%9}, {%0,%1,%2,%3};\n"
        : "+f"(acc[0]), "+f"(acc[1]), "+f"(acc[2]), "+f"(acc[3])
        : "r"(a[0]), "r"(a[1]), "r"(a[2]), "r"(a[3]), "r"(b0), "r"(b1));
}

__device__ __forceinline__ uint32_t smem_u32(const void* p) {
    uint32_t a;
    asm("{ .reg .u64 t; cvta.to.shared.u64 t, %1; cvt.u32.u64 %0, t; }"
        : "=r"(a) : "l"(p));
    return a;
}

#define CP_ASYNC16(dst, src) \
    asm volatile("cp.async.cg.shared.global [%0], [%1], 16;" :: "r"(dst), "l"(src))
#define CP_COMMIT()   asm volatile("cp.async.commit_group;" ::: "memory")
#define CP_WAIT(n)    asm volatile("cp.async.wait_group %0;" :: "n"(n) : "memory")

__device__ __forceinline__ unsigned pack2(float a, float b) {
    __half2 h = __floats2half2_rn(a, b);
    return *(unsigned*)&h;
}

__device__ __forceinline__ float warp_sum(float v) {
    #pragma unroll
    for (int o = 16; o; o >>= 1) v += __shfl_xor_sync(0xffffffffu, v, o);
    return v;
}

// ---------------- merged weight convert+transpose + bias concat --------------
__global__ void cvt_all_kernel(const float* __restrict__ wq, const float* __restrict__ wk,
                               const float* __restrict__ wv, const float* __restrict__ wp,
                               const float* __restrict__ w1, const float* __restrict__ w2,
                               const float* __restrict__ bq, const float* __restrict__ bk,
                               const float* __restrict__ bv,
                               __half* __restrict__ wqkvT, __half* __restrict__ wpT,
                               __half* __restrict__ w1T,   __half* __restrict__ w2T,
                               float* __restrict__ bqkv) {
    int id = blockIdx.x;
    if (id >= 12288) {
        int i = (id - 12288) * 256 + threadIdx.y * 32 + threadIdx.x;
        if (i < DMODEL) {
            bqkv[i] = bq[i];
            bqkv[DMODEL + i] = bk[i];
            bqkv[2 * DMODEL + i] = bv[i];
        }
        return;
    }
    __shared__ float t[32][33];
    const float* W; __half* Wt; int K, N, local;
    if (id < 4096) {
        K = DMODEL; N = DMODEL; local = id & 1023;
        int sel = id >> 10;
        if (sel == 0)      { W = wq; Wt = wqkvT; }
        else if (sel == 1) { W = wk; Wt = wqkvT + DMODEL*DMODEL; }
        else if (sel == 2) { W = wv; Wt = wqkvT + 2*DMODEL*DMODEL; }
        else               { W = wp; Wt = wpT; }
    } else if (id < 8192) {
        K = DMODEL; N = FFDIM; local = id - 4096; W = w1; Wt = w1T;
    } else {
        K = FFDIM; N = DMODEL; local = id - 8192; W = w2; Wt = w2T;
    }
    int gx = K >> 5;
    int bk_ = (local % gx) * 32, bn = (local / gx) * 32;
    int tx = threadIdx.x, ty = threadIdx.y;   // (32, 8)
    #pragma unroll
    for (int i = 0; i < 4; i++)
        t[ty + i * 8][tx] = W[(size_t)(bk_ + ty + i * 8) * N + bn + tx];
    __syncthreads();
    #pragma unroll
    for (int i = 0; i < 4; i++)
        Wt[(size_t)(bn + ty + i * 8) * K + bk_ + tx] = __float2half(t[tx][ty + i * 8]);
}

// ---------------- LayerNorm kernels: warp-per-row, shuffle-only --------------
__global__ __launch_bounds__(256) void ln_double_kernel(
    const float* __restrict__ X,
    const float* __restrict__ g1, const float* __restrict__ b1,
    const float* __restrict__ g2, const float* __restrict__ b2,
    __half* __restrict__ Y) {
    const int lane = threadIdx.x & 31, w = threadIdx.x >> 5;
    const int row = blockIdx.x * 8 + w;
    const float4* xr = (const float4*)X + (size_t)row * 256;
    float4 v[8];
    float s = 0.f;
    #pragma unroll
    for (int i = 0; i < 8; i++) {
        v[i] = xr[lane + 32 * i];
        s += v[i].x + v[i].y + v[i].z + v[i].w;
    }
    float mu = warp_sum(s) * (1.0f / 1024.0f);
    float vs = 0.f;
    #pragma unroll
    for (int i = 0; i < 8; i++) {
        v[i].x -= mu; v[i].y -= mu; v[i].z -= mu; v[i].w -= mu;
        vs += v[i].x*v[i].x + v[i].y*v[i].y + v[i].z*v[i].z + v[i].w*v[i].w;
    }
    float inv = rsqrtf(warp_sum(vs) * (1.0f / 1024.0f) + 1e-6f);
    float s2 = 0.f;
    #pragma unroll
    for (int i = 0; i < 8; i++) {
        float4 G = ((const float4*)g1)[lane + 32 * i];
        float4 B = ((const float4*)b1)[lane + 32 * i];
        v[i].x = v[i].x * inv * G.x + B.x;
        v[i].y = v[i].y * inv * G.y + B.y;
        v[i].z = v[i].z * inv * G.z + B.z;
        v[i].w = v[i].w * inv * G.w + B.w;
        s2 += v[i].x + v[i].y + v[i].z + v[i].w;
    }
    float mu2 = warp_sum(s2) * (1.0f / 1024.0f);
    float vs2 = 0.f;
    #pragma unroll
    for (int i = 0; i < 8; i++) {
        v[i].x -= mu2; v[i].y -= mu2; v[i].z -= mu2; v[i].w -= mu2;
        vs2 += v[i].x*v[i].x + v[i].y*v[i].y + v[i].z*v[i].z + v[i].w*v[i].w;
    }
    float inv2 = rsqrtf(warp_sum(vs2) * (1.0f / 1024.0f) + 1e-6f);
    __half2* yr = (__half2*)Y + (size_t)row * 512;
    #pragma unroll
    for (int i = 0; i < 8; i++) {
        float4 G = ((const float4*)g2)[lane + 32 * i];
        float4 B = ((const float4*)b2)[lane + 32 * i];
        yr[2 * (lane + 32 * i)]     = __floats2half2_rn(v[i].x * inv2 * G.x + B.x,
                                                        v[i].y * inv2 * G.y + B.y);
        yr[2 * (lane + 32 * i) + 1] = __floats2half2_rn(v[i].z * inv2 * G.z + B.z,
                                                        v[i].w * inv2 * G.w + B.w);
    }
}

__global__ __launch_bounds__(256) void ln_single_kernel(
    const float* __restrict__ X,
    const float* __restrict__ g, const float* __restrict__ b,
    __half* __restrict__ Y) {
    const int lane = threadIdx.x & 31, w = threadIdx.x >> 5;
    const int row = blockIdx.x * 8 + w;
    const float4* xr = (const float4*)X + (size_t)row * 256;
    float4 v[8];
    float s = 0.f;
    #pragma unroll
    for (int i = 0; i < 8; i++) {
        v[i] = xr[lane + 32 * i];
        s += v[i].x + v[i].y + v[i].z + v[i].w;
    }
    float mu = warp_sum(s) * (1.0f / 1024.0f);
    float vs = 0.f;
    #pragma unroll
    for (int i = 0; i < 8; i++) {
        v[i].x -= mu; v[i].y -= mu; v[i].z -= mu; v[i].w -= mu;
        vs += v[i].x*v[i].x + v[i].y*v[i].y + v[i].z*v[i].z + v[i].w*v[i].w;
    }
    float inv = rsqrtf(warp_sum(vs) * (1.0f / 1024.0f) + 1e-6f);
    __half2* yr = (__half2*)Y + (size_t)row * 512;
    #pragma unroll
    for (int i = 0; i < 8; i++) {
        float4 G = ((const float4*)g)[lane + 32 * i];
        float4 B = ((const float4*)b)[lane + 32 * i];
        yr[2 * (lane + 32 * i)]     = __floats2half2_rn(v[i].x * inv * G.x + B.x,
                                                        v[i].y * inv * G.y + B.y);
        yr[2 * (lane + 32 * i) + 1] = __floats2half2_rn(v[i].z * inv * G.z + B.z,
                                                        v[i].w * inv * G.w + B.w);
    }
}

// ---------------- FP16 cp.async GEMM: BK=64, 3 stages (proven R9) ------------
#define GSTG 32768

__global__ __launch_bounds__(256, 2) void gemm_f16_kernel(
    const __half* __restrict__ A, const __half* __restrict__ Wt,
    const float* __restrict__ bias, const float* __restrict__ res,
    float* __restrict__ C, __half* __restrict__ Ch,
    int M, int N, int K, int act)
{
    extern __shared__ __align__(128) char gsm[];
    const uint32_t sb = smem_u32(gsm);
    const int tid = threadIdx.x, lane = tid & 31, warp = tid >> 5;
    const int m0 = blockIdx.y * 128, n0 = blockIdx.x * 128;
    const int wm = (warp >> 2) * 64, wn = (warp & 3) * 32;

    const int sr = tid >> 3, scol = tid & 7;
    const uint32_t dstA0 = (uint32_t)(sr * 128 + ((scol ^ (sr & 7)) * 16));
    const __half* Abase = A  + (size_t)(m0 + sr) * K + scol * 8;
    const __half* Bbase = Wt + (size_t)(n0 + sr) * K + scol * 8;

    const int r8 = lane & 7, sel = lane >> 3;
    uint32_t a_row[4]; int a_key[4];
    #pragma unroll
    for (int mi = 0; mi < 4; mi++) {
        int r = wm + mi * 16 + (sel & 1) * 8 + r8;
        a_row[mi] = r * 128;
        a_key[mi] = r & 7;
    }
    const int a_hi = sel >> 1;
    uint32_t b_row[2]; int b_key[2];
    #pragma unroll
    for (int nj = 0; nj < 2; nj++) {
        int r = wn + (nj * 2 + (sel >> 1)) * 8 + r8;
        b_row[nj] = (uint32_t)(16384 + r * 128);
        b_key[nj] = r & 7;
    }
    const int b_hi = sel & 1;

    float acc[4][4][4] = {};

    auto issue = [&](int s, int kc) {
        const uint32_t st = sb + s * GSTG;
        const int ko = kc * 64;
        #pragma unroll
        for (int i = 0; i < 4; i++) {
            CP_ASYNC16(st + dstA0 + i * 4096, Abase + (size_t)i * 32 * K + ko);
            CP_ASYNC16(st + 16384 + dstA0 + i * 4096, Bbase + (size_t)i * 32 * K + ko);
        }
        CP_COMMIT();
    };

    const int NC = K >> 6;
    issue(0, 0);
    if (NC > 1) issue(1, 1);

    for (int kc = 0; kc < NC; kc++) {
        const int cur = kc % 3;
        if (kc + 1 < NC) CP_WAIT(1); else CP_WAIT(0);
        __syncthreads();
        if (kc + 2 < NC) issue((kc + 2) % 3, kc + 2);

        const uint32_t stb = sb + cur * GSTG;
        #pragma unroll
        for (int ks = 0; ks < 4; ks++) {
            unsigned af[4][4], bf[4][2];
            #pragma unroll
            for (int mi = 0; mi < 4; mi++) {
                uint32_t addr = stb + a_row[mi]
                              + (uint32_t)(((ks * 2 + a_hi) ^ a_key[mi]) * 16);
                asm volatile(
                    "ldmatrix.sync.aligned.m8n8.x4.shared.b16 {%0,%1,%2,%3}, [%4];"
                    : "=r"(af[mi][0]), "=r"(af[mi][1]), "=r"(af[mi][2]), "=r"(af[mi][3])
                    : "r"(addr));
            }
            #pragma unroll
            for (int nj = 0; nj < 2; nj++) {
                uint32_t addr = stb + b_row[nj]
                              + (uint32_t)(((ks * 2 + b_hi) ^ b_key[nj]) * 16);
                asm volatile(
                    "ldmatrix.sync.aligned.m8n8.x4.shared.b16 {%0,%1,%2,%3}, [%4];"
                    : "=r"(bf[nj*2][0]), "=r"(bf[nj*2][1]),
                      "=r"(bf[nj*2+1][0]), "=r"(bf[nj*2+1][1])
                    : "r"(addr));
            }
            #pragma unroll
            for (int mi = 0; mi < 4; mi++)
                #pragma unroll
                for (int ni = 0; ni < 4; ni++)
                    mma16(acc[mi][ni], af[mi], bf[ni][0], bf[ni][1]);
        }
    }

    const int g = lane >> 2, c4 = lane & 3;
    #pragma unroll
    for (int mi = 0; mi < 4; mi++) {
        #pragma unroll
        for (int ni = 0; ni < 4; ni++) {
            int gn = n0 + wn + ni * 8 + c4 * 2;
            float bv0 = bias[gn], bv1 = bias[gn + 1];
            #pragma unroll
            for (int half_ = 0; half_ < 2; half_++) {
                int gr = m0 + wm + mi * 16 + g + half_ * 8;
                float v0 = acc[mi][ni][half_ * 2 + 0] + bv0;
                float v1 = acc[mi][ni][half_ * 2 + 1] + bv1;
                if (act) {
                    v0 = 0.5f * v0 * (1.0f + erff(v0 * 0.70710678118654752f));
                    v1 = 0.5f * v1 * (1.0f + erff(v1 * 0.70710678118654752f));
                }
                size_t o = (size_t)gr * N + gn;
                if (res) { v0 += res[o]; v1 += res[o + 1]; }
                if (Ch) {
                    *(__half2*)(Ch + o) = __floats2half2_rn(v0, v1);
                } else {
                    C[o] = v0; C[o + 1] = v1;
                }
            }
        }
    }
}

// ---------------- FP16 flash attention: fp32 exp2 softmax + ones-MMA row sum -
#define ATT_STG 16384            // K 8KB + V 8KB per stage; 3 stages = 48KB
#define QKV_LD  (3 * DMODEL)
#define H2_ONES 0x3C003C00u

__global__ __launch_bounds__(256, 2) void attn_f16_kernel(
    const __half* __restrict__ QKV, __half* __restrict__ O) {
    __shared__ __align__(128) char smb[3 * ATT_STG];
    const uint32_t sb = smem_u32(smb);
    const int tid = threadIdx.x, lane = tid & 31, warp = tid >> 5;
    const int g = lane >> 2, c4 = lane & 3;
    const int bh = blockIdx.x, qt = blockIdx.y;
    const int b = bh >> 4, h = bh & 15;

    // Q scaled by 0.125 * log2(e) -> scores in log2 domain
    unsigned aQ[4][4];
    const int qr = qt * 128 + warp * 16 + g;
    {
        const float QS = 0.18033688011112042f;
        const __half2 sc = __floats2half2_rn(QS, QS);
        const __half* q0 = QKV + (size_t)(b * SEQ + qr) * QKV_LD + h * HD;
        const __half* q8 = q0 + (size_t)8 * QKV_LD;
        #pragma unroll
        for (int j = 0; j < 4; j++) {
            __half2 t;
            t = __hmul2(*(const __half2*)(q0 + j * 16 + 2 * c4), sc);     aQ[j][0] = *(unsigned*)&t;
            t = __hmul2(*(const __half2*)(q8 + j * 16 + 2 * c4), sc);     aQ[j][1] = *(unsigned*)&t;
            t = __hmul2(*(const __half2*)(q0 + j * 16 + 8 + 2 * c4), sc); aQ[j][2] = *(unsigned*)&t;
            t = __hmul2(*(const __half2*)(q8 + j * 16 + 8 + 2 * c4), sc); aQ[j][3] = *(unsigned*)&t;
        }
    }

    const int sr = tid >> 2, scg = (tid & 3) * 2;
    const __half* ksrc0 = QKV + (size_t)(b * SEQ + sr) * QKV_LD + DMODEL + h * HD;
    const __half* vsrc0 = ksrc0 + DMODEL;

    auto issue = [&](int s, int kt) {
        const uint32_t st = sb + s * ATT_STG;
        const size_t roff = (size_t)(kt * 64) * QKV_LD;
        #pragma unroll
        for (int j = 0; j < 2; j++) {
            int c = scg + j;
            uint32_t d = (uint32_t)(sr * 128 + ((c ^ (sr & 7)) * 16));
            CP_ASYNC16(st + d, ksrc0 + roff + c * 8);
            CP_ASYNC16(st + 8192 + d, vsrc0 + roff + c * 8);
        }
        CP_COMMIT();
    };

    // precomputed ldmatrix address components (swizzle key == r8 everywhere)
    const int sel = lane >> 3, r8 = lane & 7;
    const int lo = sel & 1, hi = sel >> 1;
    uint32_t krow[4], kcx[4], vrow[4], vcx[4];
    #pragma unroll
    for (int i = 0; i < 4; i++) {
        krow[i] = (uint32_t)((((i * 2 + hi) * 8) + r8) * 128);
        kcx[i]  = (uint32_t)((((i * 2 + lo) ^ r8)) * 16);
        vrow[i] = (uint32_t)(((16 * i + lo * 8) + r8) * 128);
        vcx[i]  = (uint32_t)((((i * 2 + hi) ^ r8)) * 16);
    }

    float m0 = -INFINITY, m1 = -INFINITY;
    float acc[8][4] = {};
    float accL[4] = {};          // ones-MMA row-sum accumulator (l in [0],[2])

    const int NT = SEQ / 64;
    issue(0, 0);
    issue(1, 1);
    for (int kt = 0; kt < NT; kt++) {
        const int cur = kt % 3;
        if (kt + 1 < NT) CP_WAIT(1); else CP_WAIT(0);
        __syncthreads();
        if (kt + 2 < NT) issue((kt + 2) % 3, kt + 2);

        const uint32_t Kb = sb + cur * ATT_STG;
        const uint32_t Vb = Kb + 8192;

        float s[8][4] = {};
        #pragma unroll
        for (int ks = 0; ks < 4; ks++) {
            #pragma unroll
            for (int njp = 0; njp < 4; njp++) {
                uint32_t addr = Kb + krow[njp] + kcx[ks];
                unsigned bf0, bf1, bf2, bf3;
                asm volatile(
                    "ldmatrix.sync.aligned.m8n8.x4.shared.b16 {%0,%1,%2,%3}, [%4];"
                    : "=r"(bf0), "=r"(bf1), "=r"(bf2), "=r"(bf3) : "r"(addr));
                mma16(s[njp * 2],     aQ[ks], bf0, bf1);
                mma16(s[njp * 2 + 1], aQ[ks], bf2, bf3);
            }
        }

        // online softmax in log2 domain (fp32 exp2f, proven R11)
        float tm0 = -INFINITY, tm1 = -INFINITY;
        #pragma unroll
        for (int nt = 0; nt < 8; nt++) {
            tm0 = fmaxf(tm0, fmaxf(s[nt][0], s[nt][1]));
            tm1 = fmaxf(tm1, fmaxf(s[nt][2], s[nt][3]));
        }
        tm0 = fmaxf(tm0, __shfl_xor_sync(0xffffffffu, tm0, 1));
        tm0 = fmaxf(tm0, __shfl_xor_sync(0xffffffffu, tm0, 2));
        tm1 = fmaxf(tm1, __shfl_xor_sync(0xffffffffu, tm1, 1));
        tm1 = fmaxf(tm1, __shfl_xor_sync(0xffffffffu, tm1, 2));
        float mn0 = fmaxf(m0, tm0), mn1 = fmaxf(m1, tm1);
        float cf0 = exp2f(m0 - mn0), cf1 = exp2f(m1 - mn1);
        m0 = mn0; m1 = mn1;

        #pragma unroll
        for (int nt = 0; nt < 8; nt++) {
            s[nt][0] = exp2f(s[nt][0] - m0);
            s[nt][1] = exp2f(s[nt][1] - m0);
            s[nt][2] = exp2f(s[nt][2] - m1);
            s[nt][3] = exp2f(s[nt][3] - m1);
        }

        // rescale acc + accL by correction factors
        #pragma unroll
        for (int nt = 0; nt < 8; nt++) {
            acc[nt][0] *= cf0; acc[nt][1] *= cf0;
            acc[nt][2] *= cf1; acc[nt][3] *= cf1;
        }
        accL[0] *= cf0; accL[1] *= cf0;
        accL[2] *= cf1; accL[3] *= cf1;

        // P fragments in registers (A of m16n8k16, k = keys)
        unsigned aP[4][4];
        #pragma unroll
        for (int j = 0; j < 4; j++) {
            aP[j][0] = pack2(s[2*j][0],   s[2*j][1]);
            aP[j][1] = pack2(s[2*j][2],   s[2*j][3]);
            aP[j][2] = pack2(s[2*j+1][0], s[2*j+1][1]);
            aP[j][3] = pack2(s[2*j+1][2], s[2*j+1][3]);
        }

        // acc += P V ; accL += P @ ones (row sums via tensor pipe)
        #pragma unroll
        for (int j = 0; j < 4; j++) {
            mma16(accL, aP[j], H2_ONES, H2_ONES);
            #pragma unroll
            for (int njp = 0; njp < 4; njp++) {
                uint32_t addr = Vb + vrow[j] + vcx[njp];
                unsigned bf0, bf1, bf2, bf3;
                asm volatile(
                    "ldmatrix.sync.aligned.m8n8.x4.trans.shared.b16 {%0,%1,%2,%3}, [%4];"
                    : "=r"(bf0), "=r"(bf1), "=r"(bf2), "=r"(bf3) : "r"(addr));
                mma16(acc[njp * 2],     aP[j], bf0, bf1);
                mma16(acc[njp * 2 + 1], aP[j], bf2, bf3);
            }
        }
    }

    const float inv0 = 1.0f / accL[0], inv1 = 1.0f / accL[2];
    __half* orow0 = O + (size_t)(b * SEQ + qr) * DMODEL + h * HD;
    __half* orow8 = orow0 + (size_t)8 * DMODEL;
    #pragma unroll
    for (int nt = 0; nt < 8; nt++) {
        int col = nt * 8 + 2 * c4;
        *(__half2*)(orow0 + col) = __floats2half2_rn(acc[nt][0] * inv0, acc[nt][1] * inv0);
        *(__half2*)(orow8 + col) = __floats2half2_rn(acc[nt][2] * inv1, acc[nt][3] * inv1);
    }
}

// ---------------- launch ----------------
extern "C" void kernel_launch(void* const* d_in, const int* in_sizes, int n_in,
                              void* d_out, int out_size) {
    const float* x     = (const float*)d_in[0];
    const float* ln1_g = (const float*)d_in[1];
    const float* ln1_b = (const float*)d_in[2];
    const float* ln2_g = (const float*)d_in[3];
    const float* ln2_b = (const float*)d_in[4];
    const float* wq    = (const float*)d_in[5];
    const float* bq    = (const float*)d_in[6];
    const float* wk    = (const float*)d_in[7];
    const float* bk    = (const float*)d_in[8];
    const float* wv    = (const float*)d_in[9];
    const float* bv    = (const float*)d_in[10];
    const float* wp    = (const float*)d_in[11];
    const float* bp    = (const float*)d_in[12];
    const float* ln3_g = (const float*)d_in[13];
    const float* ln3_b = (const float*)d_in[14];
    const float* w1    = (const float*)d_in[15];
    const float* b1    = (const float*)d_in[16];
    const float* w2    = (const float*)d_in[17];
    const float* b2    = (const float*)d_in[18];
    float* out = (float*)d_out;

    float *y1, *bqkv;
    __half *xnh, *qkvh, *ctxh, *ffh, *wqkvT, *wpT, *w1T, *w2T;
    cudaGetSymbolAddress((void**)&y1,    g_y1);
    cudaGetSymbolAddress((void**)&bqkv,  g_bqkv);
    cudaGetSymbolAddress((void**)&xnh,   g_xnh);
    cudaGetSymbolAddress((void**)&qkvh,  g_qkvh);
    cudaGetSymbolAddress((void**)&ctxh,  g_ctxh);
    cudaGetSymbolAddress((void**)&ffh,   g_ffh);
    cudaGetSymbolAddress((void**)&wqkvT, g_wqkvT);
    cudaGetSymbolAddress((void**)&wpT,   g_wpT);
    cudaGetSymbolAddress((void**)&w1T,   g_w1T);
    cudaGetSymbolAddress((void**)&w2T,   g_w2T);

    cudaFuncSetAttribute(gemm_f16_kernel,
                         cudaFuncAttributeMaxDynamicSharedMemorySize, 3 * GSTG);

    // 0. weight prep (one launch: transposes + bias concat)
    cvt_all_kernel<<<12292, dim3(32, 8)>>>(wq, wk, wv, wp, w1, w2, bq, bk, bv,
                                           wqkvT, wpT, w1T, w2T, bqkv);

    // 1. double pre-norm -> fp16 (warp-per-row)
    ln_double_kernel<<<MROWS / 8, 256>>>(x, ln1_g, ln1_b, ln2_g, ln2_b, xnh);

    // 2. fused QKV projection (fp16 out, N=3072)
    gemm_f16_kernel<<<dim3(3*DMODEL/128, MROWS/128), 256, 3*GSTG>>>(
        xnh, wqkvT, bqkv, nullptr, nullptr, qkvh, MROWS, 3*DMODEL, DMODEL, 0);

    // 3. fp16 flash attention -> fp16 ctx
    attn_f16_kernel<<<dim3(BATCH * NHEAD, SEQ / 128), 256>>>(qkvh, ctxh);

    // 4. output projection + residual (fp32 out)
    dim3 gdd(DMODEL / 128, MROWS / 128);
    gemm_f16_kernel<<<gdd, 256, 3*GSTG>>>(ctxh, wpT, bp, x, y1, nullptr,
                                          MROWS, DMODEL, DMODEL, 0);

    // 5. ffn pre-norm -> fp16 (warp-per-row)
    ln_single_kernel<<<MROWS / 8, 256>>>(y1, ln3_g, ln3_b, xnh);

    // 6. FFN: w1 (+gelu, fp16 out), w2 (+residual, fp32 out -> d_out)
    gemm_f16_kernel<<<dim3(FFDIM / 128, MROWS / 128), 256, 3*GSTG>>>(
        xnh, w1T, b1, nullptr, nullptr, ffh, MROWS, FFDIM, DMODEL, 1);
    gemm_f16_kernel<<<gdd, 256, 3*GSTG>>>(ffh, w2T, b2, y1, out, nullptr,
                                          MROWS, DMODEL, FFDIM, 0);
}